// round 5
// baseline (speedup 1.0000x reference)
#include <cuda_runtime.h>
#include <cuda_bf16.h>
#include <cstdint>

// ---------------------------------------------------------------------------
// ConvMultiheadAttention: B=8, S=1024, D=512, H=8, hd=64, KERNEL=3
// out  = [8,1024,512]  ; ave = [8,1024,1024]
// ---------------------------------------------------------------------------

#define BB 8
#define SS 1024
#define DD 512
#define HH 8
#define HD 64

typedef unsigned long long ull;

// ----- f32x2 helpers --------------------------------------------------------
__device__ __forceinline__ ull f2fma(ull a, ull b, ull c) {
    ull d; asm("fma.rn.f32x2 %0, %1, %2, %3;" : "=l"(d) : "l"(a), "l"(b), "l"(c)); return d;
}
__device__ __forceinline__ ull f2dup(float x) {
    ull d; asm("mov.b64 %0, {%1, %1};" : "=l"(d) : "f"(x)); return d;
}
__device__ __forceinline__ ull f2add(ull a, ull b) {
    ull d; asm("add.rn.f32x2 %0, %1, %2;" : "=l"(d) : "l"(a), "l"(b)); return d;
}
__device__ __forceinline__ float2 f2unpk(ull a) {
    float2 r; asm("mov.b64 {%0, %1}, %2;" : "=f"(r.x), "=f"(r.y) : "l"(a)); return r;
}

// ----- tf32 helpers ---------------------------------------------------------
__device__ __forceinline__ float to_tf32(float x) {
    float r; asm("cvt.rna.tf32.f32 %0, %1;" : "=f"(r) : "f"(x)); return r;
}
__device__ __forceinline__ void mma_tf32(float4& d, const uint32_t a[4],
                                         const uint32_t b[2]) {
    asm("mma.sync.aligned.m16n8k8.row.col.f32.tf32.tf32.f32 "
        "{%0,%1,%2,%3}, {%4,%5,%6,%7}, {%8,%9}, {%0,%1,%2,%3};"
        : "+f"(d.x), "+f"(d.y), "+f"(d.z), "+f"(d.w)
        : "r"(a[0]), "r"(a[1]), "r"(a[2]), "r"(a[3]), "r"(b[0]), "r"(b[1]));
}
__device__ __forceinline__ void mma8(float4& d, float a0, float a1, float a2,
                                     float a3, float b0, float b1) {
    asm("mma.sync.aligned.m16n8k8.row.col.f32.tf32.tf32.f32 "
        "{%0,%1,%2,%3}, {%4,%5,%6,%7}, {%8,%9}, {%0,%1,%2,%3};"
        : "+f"(d.x), "+f"(d.y), "+f"(d.z), "+f"(d.w)
        : "r"(__float_as_uint(a0)), "r"(__float_as_uint(a1)),
          "r"(__float_as_uint(a2)), "r"(__float_as_uint(a3)),
          "r"(__float_as_uint(b0)), "r"(__float_as_uint(b1)));
}

// ----- scratch (static device globals) --------------------------------------
__device__ float g_xt[3][BB][DD][SS];    // transposed inputs  [B,D,S]
__device__ float g_qkv[3][BB][DD][SS];   // conv outputs Q,K,V [B,D,S]
__device__ float g_vt[BB][SS][DD];       // V transposed to [B,S,D]
__device__ float g_kth[BB * HH][SS][HD]; // K hi, [t][perm(d)] per (b,h)
__device__ float g_ktl[BB * HH][SS][HD]; // K lo
__device__ float g_p[(size_t)BB * HH * SS * SS]; // attention probs
__device__ float g_o1[BB][SS][DD];       // pre-projection output

// ---------------------------------------------------------------------------
// Kernel 1: transpose [B,S,D] -> [B,D,S] for q, k, v
// ---------------------------------------------------------------------------
__global__ void transpose_kernel(const float* __restrict__ q,
                                 const float* __restrict__ k,
                                 const float* __restrict__ v) {
    __shared__ float tile[32][33];
    int zz = blockIdx.z;
    int tn = zz / BB, b = zz % BB;
    const float* src = (tn == 0) ? q : (tn == 1) ? k : v;
    float* dst = &g_xt[tn][b][0][0];
    int s0 = blockIdx.x * 32, d0 = blockIdx.y * 32;
    int tx = threadIdx.x, ty = threadIdx.y;
    #pragma unroll
    for (int i = ty; i < 32; i += 8)
        tile[i][tx] = src[((size_t)b * SS + s0 + i) * DD + d0 + tx];
    __syncthreads();
    #pragma unroll
    for (int i = ty; i < 32; i += 8)
        dst[(size_t)(d0 + i) * SS + s0 + tx] = tile[tx][i];
}

// ---------------------------------------------------------------------------
// Kernel 2: conv1d projections via mma.sync tf32 (split-precision, 3 terms).
// ---------------------------------------------------------------------------
#define CAH 20
#define CBH 136
#define CV_AH 0
#define CV_AL 2560
#define CV_BH 5120
#define CV_BL 7296
#define CV_BUF_FLOATS 9472
#define CV_SMEM (2 * CV_BUF_FLOATS * (int)sizeof(float))

__global__ __launch_bounds__(256, 1)
void conv_mma(const float* __restrict__ Wq, const float* __restrict__ bq,
              const float* __restrict__ Wk, const float* __restrict__ bk,
              const float* __restrict__ Wv, const float* __restrict__ bv) {
    extern __shared__ float sm[];
    __shared__ float s_bias[128];

    const int zz = blockIdx.z, tn = zz / BB, b = zz % BB;
    const float* W    = (tn == 0) ? Wq : (tn == 1) ? Wk : Wv;
    const float* bias = (tn == 0) ? bq : (tn == 1) ? bk : bv;
    const int KER  = (tn == 2) ? 1 : 3;
    const int Kdim = DD * KER;
    const float* xsrc = &g_xt[tn][b][0][0];
    float* out = &g_qkv[tn][b][0][0];
    const int m0 = blockIdx.x * 128, n0 = blockIdx.y * 128;
    const int tid = threadIdx.x, wid = tid >> 5, lane = tid & 31;
    const int g = lane >> 2, tg = lane & 3;
    const int wm = (wid >> 2) * 64, wn = (wid & 3) * 32;

    if (tid < 128) s_bias[tid] = bias[m0 + tid];

    float4 dacc[4][4];
    #pragma unroll
    for (int mi = 0; mi < 4; mi++)
        #pragma unroll
        for (int ni = 0; ni < 4; ni++) dacc[mi][ni] = make_float4(0.f, 0.f, 0.f, 0.f);

    const int la_row = tid >> 2, la_k = (tid & 3) * 4;
    const int lb_k = tid >> 4, lb_s = tid & 15;

    const int NC = Kdim / 16;
    float4 a_reg[2];
    float  b_reg[8];

    #pragma unroll
    for (int rr = 0; rr < 2; rr++)
        a_reg[rr] = *(const float4*)&W[(size_t)(m0 + rr * 64 + la_row) * Kdim + la_k];
    {
        int kk = lb_k;
        int ci, kof;
        if (KER == 3) { ci = kk / 3; kof = kk - ci * 3 - 1; }
        else          { ci = kk;     kof = 0; }
        const float* xr = xsrc + (size_t)ci * SS;
        #pragma unroll
        for (int j = 0; j < 8; j++) {
            int s = n0 + lb_s + 16 * j + kof;
            b_reg[j] = (s >= 0 && s < SS) ? xr[s] : 0.0f;
        }
    }
    {
        float* Ah = sm + CV_AH; float* Al = sm + CV_AL;
        float* Bh = sm + CV_BH; float* Bl = sm + CV_BL;
        #pragma unroll
        for (int rr = 0; rr < 2; rr++) {
            int row = rr * 64 + la_row;
            float h0 = to_tf32(a_reg[rr].x), h1 = to_tf32(a_reg[rr].y);
            float h2 = to_tf32(a_reg[rr].z), h3 = to_tf32(a_reg[rr].w);
            *(float4*)&Ah[row * CAH + la_k] = make_float4(h0, h1, h2, h3);
            *(float4*)&Al[row * CAH + la_k] =
                make_float4(to_tf32(a_reg[rr].x - h0), to_tf32(a_reg[rr].y - h1),
                            to_tf32(a_reg[rr].z - h2), to_tf32(a_reg[rr].w - h3));
        }
        #pragma unroll
        for (int j = 0; j < 8; j++) {
            float h = to_tf32(b_reg[j]);
            Bh[lb_k * CBH + lb_s + 16 * j] = h;
            Bl[lb_k * CBH + lb_s + 16 * j] = to_tf32(b_reg[j] - h);
        }
    }
    __syncthreads();

    for (int c = 0; c < NC; c++) {
        const int bf = c & 1;
        const bool have = (c + 1) < NC;

        if (have) {
            #pragma unroll
            for (int rr = 0; rr < 2; rr++)
                a_reg[rr] = *(const float4*)&W[(size_t)(m0 + rr * 64 + la_row) * Kdim
                                               + (c + 1) * 16 + la_k];
            int kk = (c + 1) * 16 + lb_k;
            int ci, kof;
            if (KER == 3) { ci = kk / 3; kof = kk - ci * 3 - 1; }
            else          { ci = kk;     kof = 0; }
            const float* xr = xsrc + (size_t)ci * SS;
            #pragma unroll
            for (int j = 0; j < 8; j++) {
                int s = n0 + lb_s + 16 * j + kof;
                b_reg[j] = (s >= 0 && s < SS) ? xr[s] : 0.0f;
            }
        }

        const float* Ah = sm + bf * CV_BUF_FLOATS + CV_AH;
        const float* Al = sm + bf * CV_BUF_FLOATS + CV_AL;
        const float* Bh = sm + bf * CV_BUF_FLOATS + CV_BH;
        const float* Bl = sm + bf * CV_BUF_FLOATS + CV_BL;

        #pragma unroll
        for (int ks = 0; ks < 16; ks += 8) {
            uint32_t ah[4][4], al[4][4], bh[4][2], bl[4][2];
            #pragma unroll
            for (int mi = 0; mi < 4; mi++) {
                int r0 = (wm + mi * 16 + g) * CAH + ks + tg;
                int r1 = r0 + 8 * CAH;
                ah[mi][0] = __float_as_uint(Ah[r0]);
                ah[mi][1] = __float_as_uint(Ah[r1]);
                ah[mi][2] = __float_as_uint(Ah[r0 + 4]);
                ah[mi][3] = __float_as_uint(Ah[r1 + 4]);
                al[mi][0] = __float_as_uint(Al[r0]);
                al[mi][1] = __float_as_uint(Al[r1]);
                al[mi][2] = __float_as_uint(Al[r0 + 4]);
                al[mi][3] = __float_as_uint(Al[r1 + 4]);
            }
            #pragma unroll
            for (int ni = 0; ni < 4; ni++) {
                int c0 = (ks + tg) * CBH + wn + ni * 8 + g;
                int c1 = c0 + 4 * CBH;
                bh[ni][0] = __float_as_uint(Bh[c0]);
                bh[ni][1] = __float_as_uint(Bh[c1]);
                bl[ni][0] = __float_as_uint(Bl[c0]);
                bl[ni][1] = __float_as_uint(Bl[c1]);
            }
            #pragma unroll
            for (int mi = 0; mi < 4; mi++)
                #pragma unroll
                for (int ni = 0; ni < 4; ni++) {
                    mma_tf32(dacc[mi][ni], ah[mi], bh[ni]);
                    mma_tf32(dacc[mi][ni], ah[mi], bl[ni]);
                    mma_tf32(dacc[mi][ni], al[mi], bh[ni]);
                }
        }

        if (have) {
            float* Ah2 = sm + (bf ^ 1) * CV_BUF_FLOATS + CV_AH;
            float* Al2 = sm + (bf ^ 1) * CV_BUF_FLOATS + CV_AL;
            float* Bh2 = sm + (bf ^ 1) * CV_BUF_FLOATS + CV_BH;
            float* Bl2 = sm + (bf ^ 1) * CV_BUF_FLOATS + CV_BL;
            #pragma unroll
            for (int rr = 0; rr < 2; rr++) {
                int row = rr * 64 + la_row;
                float h0 = to_tf32(a_reg[rr].x), h1 = to_tf32(a_reg[rr].y);
                float h2 = to_tf32(a_reg[rr].z), h3 = to_tf32(a_reg[rr].w);
                *(float4*)&Ah2[row * CAH + la_k] = make_float4(h0, h1, h2, h3);
                *(float4*)&Al2[row * CAH + la_k] =
                    make_float4(to_tf32(a_reg[rr].x - h0), to_tf32(a_reg[rr].y - h1),
                                to_tf32(a_reg[rr].z - h2), to_tf32(a_reg[rr].w - h3));
            }
            #pragma unroll
            for (int j = 0; j < 8; j++) {
                float h = to_tf32(b_reg[j]);
                Bh2[lb_k * CBH + lb_s + 16 * j] = h;
                Bl2[lb_k * CBH + lb_s + 16 * j] = to_tf32(b_reg[j] - h);
            }
        }
        __syncthreads();
    }

    #pragma unroll
    for (int mi = 0; mi < 4; mi++) {
        int lr0 = wm + mi * 16 + g;
        float b0 = s_bias[lr0], b1 = s_bias[lr0 + 8];
        #pragma unroll
        for (int ni = 0; ni < 4; ni++) {
            int col = n0 + wn + ni * 8 + 2 * tg;
            float4 d = dacc[mi][ni];
            *(float2*)&out[(size_t)(m0 + lr0) * SS + col]     = make_float2(d.x + b0, d.y + b0);
            *(float2*)&out[(size_t)(m0 + lr0 + 8) * SS + col] = make_float2(d.z + b1, d.w + b1);
        }
    }
}

// ---------------------------------------------------------------------------
// Kernel 3: transpose V conv output [B,D,S] -> [B,S,D]
// ---------------------------------------------------------------------------
__global__ void vt_kernel() {
    __shared__ float tile[32][33];
    int b = blockIdx.z;
    const float* src = &g_qkv[2][b][0][0];
    float* dst = &g_vt[b][0][0];
    int s0 = blockIdx.x * 32, d0 = blockIdx.y * 32;
    int tx = threadIdx.x, ty = threadIdx.y;
    #pragma unroll
    for (int i = ty; i < 32; i += 8)
        tile[i][tx] = src[(size_t)(d0 + i) * SS + s0 + tx];
    __syncthreads();
    #pragma unroll
    for (int i = ty; i < 32; i += 8)
        dst[(size_t)(s0 + i) * DD + d0 + tx] = tile[tx][i];
}

// ---------------------------------------------------------------------------
// Kernel 3b: K prep — transpose K conv output [B,D,S] -> per (b,h) [t][64],
// with d permuted so mma fragment pairs (k, k+4) are adjacent, split hi/lo.
// perm(d) = (d>>3)*8 + (d&3)*2 + ((d>>2)&1)
// ---------------------------------------------------------------------------
__global__ void ktprep_kernel() {
    __shared__ float tile[32][33];
    int b = blockIdx.z;
    const float* src = &g_qkv[1][b][0][0];
    int s0 = blockIdx.x * 32, d0 = blockIdx.y * 32;
    int tx = threadIdx.x, ty = threadIdx.y;
    #pragma unroll
    for (int i = ty; i < 32; i += 8)
        tile[i][tx] = src[(size_t)(d0 + i) * SS + s0 + tx];
    __syncthreads();
    int d = d0 + tx;
    int h = d >> 6, dh = d & 63;
    int cp = (dh >> 3) * 8 + (dh & 3) * 2 + ((dh >> 2) & 1);
    int bh = b * HH + h;
    #pragma unroll
    for (int i = ty; i < 32; i += 8) {
        float v = tile[tx][i];
        float hi = to_tf32(v);
        g_kth[bh][s0 + i][cp] = hi;
        g_ktl[bh][s0 + i][cp] = to_tf32(v - hi);
    }
}

// ---------------------------------------------------------------------------
// Kernel 4: scores + softmax via mma.sync tf32, registers-resident scores.
// CTA = (b, h, 16 rows). 8 warps, each owns a 16-col strip of each 128-col
// K chunk. 3-term split (QhKh + QlKh + QhKl), 1/64 folded into Q.
// smem: Qh/Ql [16][64] swizzled + Kh/Kl [128][64] swizzled + red[256].
// ---------------------------------------------------------------------------
#define SC2_SMEM ((2048 + 16384 + 256) * (int)sizeof(float))

__global__ __launch_bounds__(256, 2) void scores_mma() {
    extern __shared__ float sm[];
    float* Qh = sm;              // 16*64
    float* Ql = sm + 1024;       // 16*64
    float* Kh = sm + 2048;       // 128*64
    float* Kl = sm + 10240;      // 128*64
    float* red = sm + 18432;     // 2*128

    const int b = blockIdx.z, h = blockIdx.y, s0 = blockIdx.x * 16;
    const int bh = b * HH + h;
    const int tid = threadIdx.x, w = tid >> 5, lane = tid & 31;
    const int g = lane >> 2, tg = lane & 3;

    // ---- Q prep: load [64 d][16 r], scale by 1/64, split, permute+swizzle ----
    {
        const float* Qg = &g_qkv[0][b][h * HD][0];
        int d = tid >> 2, r0 = (tid & 3) * 4;
        float4 v4 = *(const float4*)&Qg[(size_t)d * SS + s0 + r0];
        int p = (d >> 3) * 8 + (d & 3) * 2 + ((d >> 2) & 1);
        int i16 = p >> 2, pl = p & 3;
        float vv[4] = {v4.x, v4.y, v4.z, v4.w};
        #pragma unroll
        for (int rr = 0; rr < 4; rr++) {
            int r = r0 + rr;
            float q = vv[rr] * 0.015625f;
            float hi = to_tf32(q);
            int f = ((i16 ^ (r & 7)) << 2) + pl;
            Qh[r * 64 + f] = hi;
            Ql[r * 64 + f] = to_tf32(q - hi);
        }
    }

    float4 sA[16];   // scores: [chunk tc][tile ni] -> sA[tc*2+ni]

    const int fill_t = tid >> 2;          // 0..63 (+64 second pass)
    const int fill_j = (tid & 3) * 4;     // float4 index 0..15 base

    for (int tc = 0; tc < 8; tc++) {
        __syncthreads();
        // ---- fill K chunk [128 t][64] hi/lo with 16B swizzle ----
        #pragma unroll
        for (int pass = 0; pass < 2; pass++) {
            int tl = pass * 64 + fill_t;
            int tglob = tc * 128 + tl;
            const float4* srcH = (const float4*)&g_kth[bh][tglob][0];
            const float4* srcL = (const float4*)&g_ktl[bh][tglob][0];
            float4* dstH = (float4*)&Kh[tl * 64];
            float4* dstL = (float4*)&Kl[tl * 64];
            int sw = tl & 7;
            #pragma unroll
            for (int j = 0; j < 4; j++) {
                int jj = fill_j + j;
                dstH[jj ^ sw] = srcH[jj];
                dstL[jj ^ sw] = srcL[jj];
            }
        }
        __syncthreads();

        float4 acc0 = make_float4(0.f, 0.f, 0.f, 0.f);
        float4 acc1 = make_float4(0.f, 0.f, 0.f, 0.f);
        const int t0 = w * 16 + g;        // tile ni adds +8 (t&7 unchanged)
        #pragma unroll
        for (int ks = 0; ks < 8; ks++) {
            int i16 = ks * 2 + (tg >> 1);
            int fA = ((i16 ^ g) << 2) + ((tg & 1) << 1);
            float2 qhg  = *(float2*)&Qh[g * 64 + fA];
            float2 qhg8 = *(float2*)&Qh[(g + 8) * 64 + fA];
            float2 qlg  = *(float2*)&Ql[g * 64 + fA];
            float2 qlg8 = *(float2*)&Ql[(g + 8) * 64 + fA];
            // fB: same swizzle since t&7 == g
            float2 kh0 = *(float2*)&Kh[t0 * 64 + fA];
            float2 kl0 = *(float2*)&Kl[t0 * 64 + fA];
            float2 kh1 = *(float2*)&Kh[(t0 + 8) * 64 + fA];
            float2 kl1 = *(float2*)&Kl[(t0 + 8) * 64 + fA];
            mma8(acc0, qhg.x, qhg8.x, qhg.y, qhg8.y, kh0.x, kh0.y);
            mma8(acc0, qlg.x, qlg8.x, qlg.y, qlg8.y, kh0.x, kh0.y);
            mma8(acc0, qhg.x, qhg8.x, qhg.y, qhg8.y, kl0.x, kl0.y);
            mma8(acc1, qhg.x, qhg8.x, qhg.y, qhg8.y, kh1.x, kh1.y);
            mma8(acc1, qlg.x, qlg8.x, qlg.y, qlg8.y, kh1.x, kh1.y);
            mma8(acc1, qhg.x, qhg8.x, qhg.y, qhg8.y, kl1.x, kl1.y);
        }
        sA[tc * 2 + 0] = acc0;
        sA[tc * 2 + 1] = acc1;
    }

    // ---- softmax over register-resident scores ----
    float mx0 = -1e30f, mx8 = -1e30f;
    #pragma unroll
    for (int i = 0; i < 16; i++) {
        mx0 = fmaxf(mx0, fmaxf(sA[i].x, sA[i].y));
        mx8 = fmaxf(mx8, fmaxf(sA[i].z, sA[i].w));
    }
    #pragma unroll
    for (int o = 1; o < 4; o <<= 1) {
        mx0 = fmaxf(mx0, __shfl_xor_sync(0xffffffffu, mx0, o));
        mx8 = fmaxf(mx8, __shfl_xor_sync(0xffffffffu, mx8, o));
    }
    __syncthreads();          // red reuse safety across chunks loop
    if (tg == 0) { red[w * 16 + g] = mx0; red[w * 16 + g + 8] = mx8; }
    __syncthreads();
    mx0 = -1e30f; mx8 = -1e30f;
    #pragma unroll
    for (int ww = 0; ww < 8; ww++) {
        mx0 = fmaxf(mx0, red[ww * 16 + g]);
        mx8 = fmaxf(mx8, red[ww * 16 + g + 8]);
    }

    float sum0 = 0.f, sum8 = 0.f;
    #pragma unroll
    for (int i = 0; i < 16; i++) {
        sA[i].x = __expf(sA[i].x - mx0);
        sA[i].y = __expf(sA[i].y - mx0);
        sA[i].z = __expf(sA[i].z - mx8);
        sA[i].w = __expf(sA[i].w - mx8);
        sum0 += sA[i].x + sA[i].y;
        sum8 += sA[i].z + sA[i].w;
    }
    #pragma unroll
    for (int o = 1; o < 4; o <<= 1) {
        sum0 += __shfl_xor_sync(0xffffffffu, sum0, o);
        sum8 += __shfl_xor_sync(0xffffffffu, sum8, o);
    }
    if (tg == 0) { red[128 + w * 16 + g] = sum0; red[128 + w * 16 + g + 8] = sum8; }
    __syncthreads();
    sum0 = 0.f; sum8 = 0.f;
    #pragma unroll
    for (int ww = 0; ww < 8; ww++) {
        sum0 += red[128 + ww * 16 + g];
        sum8 += red[128 + ww * 16 + g + 8];
    }
    float inv0 = 1.0f / sum0, inv8 = 1.0f / sum8;

    // ---- write P ----
    float* Pg = &g_p[((size_t)bh << 20)];
    const size_t row0 = (size_t)(s0 + g) * SS;
    const size_t row8 = (size_t)(s0 + g + 8) * SS;
    #pragma unroll
    for (int tc = 0; tc < 8; tc++)
        #pragma unroll
        for (int ni = 0; ni < 2; ni++) {
            float4 v = sA[tc * 2 + ni];
            int col = tc * 128 + w * 16 + ni * 8 + 2 * tg;
            *(float2*)&Pg[row0 + col] = make_float2(v.x * inv0, v.y * inv0);
            *(float2*)&Pg[row8 + col] = make_float2(v.z * inv8, v.w * inv8);
        }
}

// ---------------------------------------------------------------------------
// Kernel 5: ave_att = mean over heads of P
// ---------------------------------------------------------------------------
__global__ void ave_kernel(float* __restrict__ ave) {
    size_t idx = (size_t)blockIdx.x * 256 + threadIdx.x;
    size_t e = idx * 4;
    size_t b = e >> 20, st = e & 1048575;
    float4 a = make_float4(0.f, 0.f, 0.f, 0.f);
    #pragma unroll
    for (int h = 0; h < HH; h++) {
        const float4 p = *(const float4*)&g_p[((b * HH + h) << 20) + st];
        a.x += p.x; a.y += p.y; a.z += p.z; a.w += p.w;
    }
    a.x *= 0.125f; a.y *= 0.125f; a.z *= 0.125f; a.w *= 0.125f;
    *(float4*)&ave[e] = a;
}

// ---------------------------------------------------------------------------
// Kernel 6: PV GEMM per (b,h) with transposed V, f32x2 pairs along d.
// ---------------------------------------------------------------------------
__global__ __launch_bounds__(256) void pv_kernel() {
    __shared__ float Ps[128 * 36];
    __shared__ float Vs[32 * 64];
    const int b = blockIdx.z, h = blockIdx.y, s0 = blockIdx.x * 128;
    const float* Pg = &g_p[((size_t)(b * HH + h)) << 20];
    const int tid = threadIdx.x;
    const int tx = tid & 7, ty = tid >> 3;
    const int d_l = tx * 8, r_l = ty * 4;

    ull acc[4][4];
    #pragma unroll
    for (int i = 0; i < 4; i++)
        #pragma unroll
        for (int p = 0; p < 4; p++) acc[i][p] = 0ULL;

    const int pr = tid >> 1, pt = (tid & 1) * 16;
    for (int t0 = 0; t0 < SS; t0 += 32) {
        __syncthreads();
        #pragma unroll
        for (int j = 0; j < 4; j++)
            *(float4*)&Ps[pr * 36 + pt + j * 4] =
                *(const float4*)&Pg[(size_t)(s0 + pr) * SS + t0 + pt + j * 4];
        #pragma unroll
        for (int j = 0; j < 2; j++) {
            int idx = j * 256 + tid;
            int t = idx >> 4, d4 = (idx & 15) * 4;
            *(float4*)&Vs[t * 64 + d4] = *(const float4*)&g_vt[b][t0 + t][h * HD + d4];
        }
        __syncthreads();

        #pragma unroll
        for (int t = 0; t < 32; t++) {
            ull vb[4];
            #pragma unroll
            for (int p = 0; p < 4; p++) vb[p] = *(ull*)&Vs[t * 64 + d_l + 2 * p];
            #pragma unroll
            for (int i = 0; i < 4; i++) {
                ull ad = f2dup(Ps[(r_l + i) * 36 + t]);
                #pragma unroll
                for (int p = 0; p < 4; p++) acc[i][p] = f2fma(ad, vb[p], acc[i][p]);
            }
        }
    }

    #pragma unroll
    for (int i = 0; i < 4; i++)
        #pragma unroll
        for (int p = 0; p < 4; p++)
            *(ull*)&g_o1[b][s0 + r_l + i][h * HD + d_l + 2 * p] = acc[i][p];
}

// ---------------------------------------------------------------------------
// Kernel 7: output projection: out = O1 @ Wo^T + bo  (double-buffered f32x2)
// ---------------------------------------------------------------------------
__global__ __launch_bounds__(256) void proj_kernel(const float* __restrict__ Wo,
                                                   const float* __restrict__ bo,
                                                   float* __restrict__ out) {
    __shared__ float As[2][8][128];
    __shared__ float Bs[2][8][128];
    const int m0 = blockIdx.x * 128, n0 = blockIdx.y * 128;
    const float* A = &g_o1[0][0][0];
    const int tid = threadIdx.x, tx = tid & 15, ty = tid >> 4;
    const int li = tid >> 1, lj = (tid & 1) * 4;

    ull acc[8][4];
    #pragma unroll
    for (int i = 0; i < 8; i++)
        #pragma unroll
        for (int p = 0; p < 4; p++) acc[i][p] = 0ULL;

    float4 avr, bvr;
    {
        avr = *(const float4*)&A[(size_t)(m0 + li) * DD + lj];
        bvr = *(const float4*)&Wo[(size_t)(n0 + li) * DD + lj];
        As[0][lj + 0][li] = avr.x; As[0][lj + 1][li] = avr.y;
        As[0][lj + 2][li] = avr.z; As[0][lj + 3][li] = avr.w;
        Bs[0][lj + 0][li] = bvr.x; Bs[0][lj + 1][li] = bvr.y;
        Bs[0][lj + 2][li] = bvr.z; Bs[0][lj + 3][li] = bvr.w;
    }
    __syncthreads();

    int cur = 0;
    for (int k0 = 0; k0 < DD; k0 += 8) {
        bool hn = (k0 + 8) < DD;
        if (hn) {
            avr = *(const float4*)&A[(size_t)(m0 + li) * DD + k0 + 8 + lj];
            bvr = *(const float4*)&Wo[(size_t)(n0 + li) * DD + k0 + 8 + lj];
        }

        #pragma unroll
        for (int j = 0; j < 8; j++) {
            float4 a0 = *(float4*)&As[cur][j][ty * 8];
            float4 a1 = *(float4*)&As[cur][j][ty * 8 + 4];
            ull b2[4];
            #pragma unroll
            for (int p = 0; p < 4; p++) b2[p] = *(ull*)&Bs[cur][j][tx * 8 + 2 * p];
            float avv[8] = {a0.x, a0.y, a0.z, a0.w, a1.x, a1.y, a1.z, a1.w};
            #pragma unroll
            for (int i = 0; i < 8; i++) {
                ull ad = f2dup(avv[i]);
                #pragma unroll
                for (int p = 0; p < 4; p++) acc[i][p] = f2fma(ad, b2[p], acc[i][p]);
            }
        }

        if (hn) {
            int nb = cur ^ 1;
            As[nb][lj + 0][li] = avr.x; As[nb][lj + 1][li] = avr.y;
            As[nb][lj + 2][li] = avr.z; As[nb][lj + 3][li] = avr.w;
            Bs[nb][lj + 0][li] = bvr.x; Bs[nb][lj + 1][li] = bvr.y;
            Bs[nb][lj + 2][li] = bvr.z; Bs[nb][lj + 3][li] = bvr.w;
        }
        __syncthreads();
        cur ^= 1;
    }

    #pragma unroll
    for (int i = 0; i < 8; i++) {
        int m = m0 + ty * 8 + i;
        #pragma unroll
        for (int p = 0; p < 4; p++) {
            ull bb = *(const ull*)&bo[n0 + tx * 8 + 2 * p];
            ull r = f2add(acc[i][p], bb);
            *(ull*)&out[(size_t)m * DD + n0 + tx * 8 + 2 * p] = r;
        }
    }
}

// ---------------------------------------------------------------------------
extern "C" void kernel_launch(void* const* d_in, const int* in_sizes, int n_in,
                              void* d_out, int out_size) {
    const float* query = (const float*)d_in[0];
    const float* key_t = (const float*)d_in[1];
    const float* value = (const float*)d_in[2];
    const float* Wq    = (const float*)d_in[3];
    const float* bq    = (const float*)d_in[4];
    const float* Wk    = (const float*)d_in[5];
    const float* bk    = (const float*)d_in[6];
    const float* Wv    = (const float*)d_in[7];
    const float* bv    = (const float*)d_in[8];
    const float* Wo    = (const float*)d_in[9];
    const float* bo    = (const float*)d_in[10];

    float* out = (float*)d_out;
    float* ave = out + (size_t)BB * SS * DD;

    cudaFuncSetAttribute(conv_mma, cudaFuncAttributeMaxDynamicSharedMemorySize, CV_SMEM);
    cudaFuncSetAttribute(scores_mma, cudaFuncAttributeMaxDynamicSharedMemorySize, SC2_SMEM);

    transpose_kernel<<<dim3(SS / 32, DD / 32, 3 * BB), dim3(32, 8)>>>(query, key_t, value);
    conv_mma<<<dim3(DD / 128, SS / 128, 3 * BB), 256, CV_SMEM>>>(Wq, bq, Wk, bk, Wv, bv);
    vt_kernel<<<dim3(SS / 32, DD / 32, BB), dim3(32, 8)>>>();
    ktprep_kernel<<<dim3(SS / 32, DD / 32, BB), dim3(32, 8)>>>();
    scores_mma<<<dim3(SS / 16, HH, BB), 256, SC2_SMEM>>>();
    pv_kernel<<<dim3(SS / 128, HH, BB), 256>>>();
    ave_kernel<<<(BB * SS * SS / 4) / 256, 256>>>(ave);
    proj_kernel<<<dim3((BB * SS) / 128, DD / 128), 256>>>(Wo, bo, out);
}

// round 6
// speedup vs baseline: 1.1548x; 1.1548x over previous
#include <cuda_runtime.h>
#include <cuda_bf16.h>
#include <cstdint>

// ---------------------------------------------------------------------------
// ConvMultiheadAttention: B=8, S=1024, D=512, H=8, hd=64, KERNEL=3
// out  = [8,1024,512]  ; ave = [8,1024,1024]
// ---------------------------------------------------------------------------

#define BB 8
#define SS 1024
#define DD 512
#define HH 8
#define HD 64

typedef unsigned long long ull;

// ----- f32x2 helpers --------------------------------------------------------
__device__ __forceinline__ ull f2fma(ull a, ull b, ull c) {
    ull d; asm("fma.rn.f32x2 %0, %1, %2, %3;" : "=l"(d) : "l"(a), "l"(b), "l"(c)); return d;
}
__device__ __forceinline__ ull f2dup(float x) {
    ull d; asm("mov.b64 %0, {%1, %1};" : "=l"(d) : "f"(x)); return d;
}
__device__ __forceinline__ ull f2add(ull a, ull b) {
    ull d; asm("add.rn.f32x2 %0, %1, %2;" : "=l"(d) : "l"(a), "l"(b)); return d;
}
__device__ __forceinline__ float2 f2unpk(ull a) {
    float2 r; asm("mov.b64 {%0, %1}, %2;" : "=f"(r.x), "=f"(r.y) : "l"(a)); return r;
}

// ----- tf32 helpers ---------------------------------------------------------
__device__ __forceinline__ float to_tf32(float x) {
    float r; asm("cvt.rna.tf32.f32 %0, %1;" : "=f"(r) : "f"(x)); return r;
}
__device__ __forceinline__ void mma_tf32(float4& d, const uint32_t a[4],
                                         const uint32_t b[2]) {
    asm("mma.sync.aligned.m16n8k8.row.col.f32.tf32.tf32.f32 "
        "{%0,%1,%2,%3}, {%4,%5,%6,%7}, {%8,%9}, {%0,%1,%2,%3};"
        : "+f"(d.x), "+f"(d.y), "+f"(d.z), "+f"(d.w)
        : "r"(a[0]), "r"(a[1]), "r"(a[2]), "r"(a[3]), "r"(b[0]), "r"(b[1]));
}

// ----- scratch (static device globals) --------------------------------------
__device__ float g_xt[3][BB][DD][SS];    // transposed inputs  [B,D,S]
__device__ float g_qkv[3][BB][DD][SS];   // conv outputs Q,K,V [B,D,S]
__device__ float g_vt[BB][SS][DD];       // V transposed to [B,S,D]
__device__ float g_p[(size_t)BB * HH * SS * SS]; // attention probs
__device__ float g_o1[BB][SS][DD];       // pre-projection output

// ---------------------------------------------------------------------------
// Kernel 1: transpose [B,S,D] -> [B,D,S] for q, k, v
// ---------------------------------------------------------------------------
__global__ void transpose_kernel(const float* __restrict__ q,
                                 const float* __restrict__ k,
                                 const float* __restrict__ v) {
    __shared__ float tile[32][33];
    int zz = blockIdx.z;
    int tn = zz / BB, b = zz % BB;
    const float* src = (tn == 0) ? q : (tn == 1) ? k : v;
    float* dst = &g_xt[tn][b][0][0];
    int s0 = blockIdx.x * 32, d0 = blockIdx.y * 32;
    int tx = threadIdx.x, ty = threadIdx.y;
    #pragma unroll
    for (int i = ty; i < 32; i += 8)
        tile[i][tx] = src[((size_t)b * SS + s0 + i) * DD + d0 + tx];
    __syncthreads();
    #pragma unroll
    for (int i = ty; i < 32; i += 8)
        dst[(size_t)(d0 + i) * SS + s0 + tx] = tile[tx][i];
}

// ---------------------------------------------------------------------------
// Kernel 2: conv1d projections via mma.sync tf32 (split-precision, 3 terms).
// ---------------------------------------------------------------------------
#define CAH 20
#define CBH 136
#define CV_AH 0
#define CV_AL 2560
#define CV_BH 5120
#define CV_BL 7296
#define CV_BUF_FLOATS 9472
#define CV_SMEM (2 * CV_BUF_FLOATS * (int)sizeof(float))

__global__ __launch_bounds__(256, 1)
void conv_mma(const float* __restrict__ Wq, const float* __restrict__ bq,
              const float* __restrict__ Wk, const float* __restrict__ bk,
              const float* __restrict__ Wv, const float* __restrict__ bv) {
    extern __shared__ float sm[];
    __shared__ float s_bias[128];

    const int zz = blockIdx.z, tn = zz / BB, b = zz % BB;
    const float* W    = (tn == 0) ? Wq : (tn == 1) ? Wk : Wv;
    const float* bias = (tn == 0) ? bq : (tn == 1) ? bk : bv;
    const int KER  = (tn == 2) ? 1 : 3;
    const int Kdim = DD * KER;
    const float* xsrc = &g_xt[tn][b][0][0];
    float* out = &g_qkv[tn][b][0][0];
    const int m0 = blockIdx.x * 128, n0 = blockIdx.y * 128;
    const int tid = threadIdx.x, wid = tid >> 5, lane = tid & 31;
    const int g = lane >> 2, tg = lane & 3;
    const int wm = (wid >> 2) * 64, wn = (wid & 3) * 32;

    if (tid < 128) s_bias[tid] = bias[m0 + tid];

    float4 dacc[4][4];
    #pragma unroll
    for (int mi = 0; mi < 4; mi++)
        #pragma unroll
        for (int ni = 0; ni < 4; ni++) dacc[mi][ni] = make_float4(0.f, 0.f, 0.f, 0.f);

    const int la_row = tid >> 2, la_k = (tid & 3) * 4;
    const int lb_k = tid >> 4, lb_s = tid & 15;

    const int NC = Kdim / 16;
    float4 a_reg[2];
    float  b_reg[8];

    #pragma unroll
    for (int rr = 0; rr < 2; rr++)
        a_reg[rr] = *(const float4*)&W[(size_t)(m0 + rr * 64 + la_row) * Kdim + la_k];
    {
        int kk = lb_k;
        int ci, kof;
        if (KER == 3) { ci = kk / 3; kof = kk - ci * 3 - 1; }
        else          { ci = kk;     kof = 0; }
        const float* xr = xsrc + (size_t)ci * SS;
        #pragma unroll
        for (int j = 0; j < 8; j++) {
            int s = n0 + lb_s + 16 * j + kof;
            b_reg[j] = (s >= 0 && s < SS) ? xr[s] : 0.0f;
        }
    }
    {
        float* Ah = sm + CV_AH; float* Al = sm + CV_AL;
        float* Bh = sm + CV_BH; float* Bl = sm + CV_BL;
        #pragma unroll
        for (int rr = 0; rr < 2; rr++) {
            int row = rr * 64 + la_row;
            float h0 = to_tf32(a_reg[rr].x), h1 = to_tf32(a_reg[rr].y);
            float h2 = to_tf32(a_reg[rr].z), h3 = to_tf32(a_reg[rr].w);
            *(float4*)&Ah[row * CAH + la_k] = make_float4(h0, h1, h2, h3);
            *(float4*)&Al[row * CAH + la_k] =
                make_float4(to_tf32(a_reg[rr].x - h0), to_tf32(a_reg[rr].y - h1),
                            to_tf32(a_reg[rr].z - h2), to_tf32(a_reg[rr].w - h3));
        }
        #pragma unroll
        for (int j = 0; j < 8; j++) {
            float h = to_tf32(b_reg[j]);
            Bh[lb_k * CBH + lb_s + 16 * j] = h;
            Bl[lb_k * CBH + lb_s + 16 * j] = to_tf32(b_reg[j] - h);
        }
    }
    __syncthreads();

    for (int c = 0; c < NC; c++) {
        const int bf = c & 1;
        const bool have = (c + 1) < NC;

        if (have) {
            #pragma unroll
            for (int rr = 0; rr < 2; rr++)
                a_reg[rr] = *(const float4*)&W[(size_t)(m0 + rr * 64 + la_row) * Kdim
                                               + (c + 1) * 16 + la_k];
            int kk = (c + 1) * 16 + lb_k;
            int ci, kof;
            if (KER == 3) { ci = kk / 3; kof = kk - ci * 3 - 1; }
            else          { ci = kk;     kof = 0; }
            const float* xr = xsrc + (size_t)ci * SS;
            #pragma unroll
            for (int j = 0; j < 8; j++) {
                int s = n0 + lb_s + 16 * j + kof;
                b_reg[j] = (s >= 0 && s < SS) ? xr[s] : 0.0f;
            }
        }

        const float* Ah = sm + bf * CV_BUF_FLOATS + CV_AH;
        const float* Al = sm + bf * CV_BUF_FLOATS + CV_AL;
        const float* Bh = sm + bf * CV_BUF_FLOATS + CV_BH;
        const float* Bl = sm + bf * CV_BUF_FLOATS + CV_BL;

        #pragma unroll
        for (int ks = 0; ks < 16; ks += 8) {
            uint32_t ah[4][4], al[4][4], bh[4][2], bl[4][2];
            #pragma unroll
            for (int mi = 0; mi < 4; mi++) {
                int r0 = (wm + mi * 16 + g) * CAH + ks + tg;
                int r1 = r0 + 8 * CAH;
                ah[mi][0] = __float_as_uint(Ah[r0]);
                ah[mi][1] = __float_as_uint(Ah[r1]);
                ah[mi][2] = __float_as_uint(Ah[r0 + 4]);
                ah[mi][3] = __float_as_uint(Ah[r1 + 4]);
                al[mi][0] = __float_as_uint(Al[r0]);
                al[mi][1] = __float_as_uint(Al[r1]);
                al[mi][2] = __float_as_uint(Al[r0 + 4]);
                al[mi][3] = __float_as_uint(Al[r1 + 4]);
            }
            #pragma unroll
            for (int ni = 0; ni < 4; ni++) {
                int c0 = (ks + tg) * CBH + wn + ni * 8 + g;
                int c1 = c0 + 4 * CBH;
                bh[ni][0] = __float_as_uint(Bh[c0]);
                bh[ni][1] = __float_as_uint(Bh[c1]);
                bl[ni][0] = __float_as_uint(Bl[c0]);
                bl[ni][1] = __float_as_uint(Bl[c1]);
            }
            #pragma unroll
            for (int mi = 0; mi < 4; mi++)
                #pragma unroll
                for (int ni = 0; ni < 4; ni++) {
                    mma_tf32(dacc[mi][ni], ah[mi], bh[ni]);
                    mma_tf32(dacc[mi][ni], ah[mi], bl[ni]);
                    mma_tf32(dacc[mi][ni], al[mi], bh[ni]);
                }
        }

        if (have) {
            float* Ah2 = sm + (bf ^ 1) * CV_BUF_FLOATS + CV_AH;
            float* Al2 = sm + (bf ^ 1) * CV_BUF_FLOATS + CV_AL;
            float* Bh2 = sm + (bf ^ 1) * CV_BUF_FLOATS + CV_BH;
            float* Bl2 = sm + (bf ^ 1) * CV_BUF_FLOATS + CV_BL;
            #pragma unroll
            for (int rr = 0; rr < 2; rr++) {
                int row = rr * 64 + la_row;
                float h0 = to_tf32(a_reg[rr].x), h1 = to_tf32(a_reg[rr].y);
                float h2 = to_tf32(a_reg[rr].z), h3 = to_tf32(a_reg[rr].w);
                *(float4*)&Ah2[row * CAH + la_k] = make_float4(h0, h1, h2, h3);
                *(float4*)&Al2[row * CAH + la_k] =
                    make_float4(to_tf32(a_reg[rr].x - h0), to_tf32(a_reg[rr].y - h1),
                                to_tf32(a_reg[rr].z - h2), to_tf32(a_reg[rr].w - h3));
            }
            #pragma unroll
            for (int j = 0; j < 8; j++) {
                float h = to_tf32(b_reg[j]);
                Bh2[lb_k * CBH + lb_s + 16 * j] = h;
                Bl2[lb_k * CBH + lb_s + 16 * j] = to_tf32(b_reg[j] - h);
            }
        }
        __syncthreads();
    }

    #pragma unroll
    for (int mi = 0; mi < 4; mi++) {
        int lr0 = wm + mi * 16 + g;
        float b0 = s_bias[lr0], b1 = s_bias[lr0 + 8];
        #pragma unroll
        for (int ni = 0; ni < 4; ni++) {
            int col = n0 + wn + ni * 8 + 2 * tg;
            float4 d = dacc[mi][ni];
            *(float2*)&out[(size_t)(m0 + lr0) * SS + col]     = make_float2(d.x + b0, d.y + b0);
            *(float2*)&out[(size_t)(m0 + lr0 + 8) * SS + col] = make_float2(d.z + b1, d.w + b1);
        }
    }
}

// ---------------------------------------------------------------------------
// Kernel 3: transpose V conv output [B,D,S] -> [B,S,D]
// ---------------------------------------------------------------------------
__global__ void vt_kernel() {
    __shared__ float tile[32][33];
    int b = blockIdx.z;
    const float* src = &g_qkv[2][b][0][0];
    float* dst = &g_vt[b][0][0];
    int s0 = blockIdx.x * 32, d0 = blockIdx.y * 32;
    int tx = threadIdx.x, ty = threadIdx.y;
    #pragma unroll
    for (int i = ty; i < 32; i += 8)
        tile[i][tx] = src[(size_t)(d0 + i) * SS + s0 + tx];
    __syncthreads();
    #pragma unroll
    for (int i = ty; i < 32; i += 8)
        dst[(size_t)(s0 + i) * DD + d0 + tx] = tile[tx][i];
}

// ---------------------------------------------------------------------------
// Kernel 4: scores + softmax per (b, h, 16-row tile), 2 CTAs/SM.
// sc[16][1024] (64KB) + Kc[64][132] (33KB) + Qt[64][16] (4KB) = 101KB smem.
// micro: 2 rows (1 f32x2) x 4 cols per thread, 1/64 folded into Q.
// ---------------------------------------------------------------------------
#define KC_LD 132
#define SC_SMEM3 ((16 * 1024 + 64 * KC_LD + 64 * 16) * (int)sizeof(float))

__global__ __launch_bounds__(256, 2) void scores_kernel() {
    extern __shared__ float sm[];
    float* sc = sm;                         // 16*1024
    float* Kc = sm + 16 * 1024;             // 64*132
    float* Qt = Kc + 64 * KC_LD;            // 64*16

    const int b = blockIdx.z, h = blockIdx.y, s0 = blockIdx.x * 16;
    const float* Qg = &g_qkv[0][b][h * HD][0];
    const float* Kg = &g_qkv[1][b][h * HD][0];
    const int tid = threadIdx.x;

    // load Q tile [64 d][16 r], fold 1/64
    {
        int d = tid >> 2, r0 = (tid & 3) * 4;
        float4 v = *(const float4*)&Qg[(size_t)d * SS + s0 + r0];
        v.x *= 0.015625f; v.y *= 0.015625f; v.z *= 0.015625f; v.w *= 0.015625f;
        *(float4*)&Qt[d * 16 + r0] = v;
    }

    const int tx = tid & 31, ty = tid >> 5;
    const int col_l = tx * 4, r_l = ty * 2;

    for (int tc = 0; tc < 8; tc++) {
        __syncthreads();
        // fill K chunk [64 d][128 t]
        #pragma unroll
        for (int i = 0; i < 8; i++) {
            int e = i * 1024 + tid * 4;
            int d = e >> 7, t = e & 127;
            *(float4*)&Kc[d * KC_LD + t] =
                *(const float4*)&Kg[(size_t)d * SS + tc * 128 + t];
        }
        __syncthreads();

        ull acc0 = 0ULL, acc1 = 0ULL, acc2 = 0ULL, acc3 = 0ULL;
        #pragma unroll
        for (int d = 0; d < 64; d++) {
            ull q = *(ull*)&Qt[d * 16 + r_l];
            float4 kf = *(float4*)&Kc[d * KC_LD + col_l];
            acc0 = f2fma(q, f2dup(kf.x), acc0);
            acc1 = f2fma(q, f2dup(kf.y), acc1);
            acc2 = f2fma(q, f2dup(kf.z), acc2);
            acc3 = f2fma(q, f2dup(kf.w), acc3);
        }
        float2 v0 = f2unpk(acc0), v1 = f2unpk(acc1);
        float2 v2 = f2unpk(acc2), v3 = f2unpk(acc3);
        *(float4*)&sc[r_l * 1024 + tc * 128 + col_l] =
            make_float4(v0.x, v1.x, v2.x, v3.x);
        *(float4*)&sc[(r_l + 1) * 1024 + tc * 128 + col_l] =
            make_float4(v0.y, v1.y, v2.y, v3.y);
    }
    __syncthreads();

    // softmax: 8 warps x 2 rows
    const int warp = tid >> 5, lane = tid & 31;
    for (int rr = warp; rr < 16; rr += 8) {
        float* row = &sc[rr * 1024];
        float m = -1e30f;
        for (int j = lane; j < 1024; j += 32) m = fmaxf(m, row[j]);
        #pragma unroll
        for (int o = 16; o > 0; o >>= 1) m = fmaxf(m, __shfl_xor_sync(0xffffffffu, m, o));
        float s = 0.0f;
        for (int j = lane; j < 1024; j += 32) {
            float e = __expf(row[j] - m);
            row[j] = e;
            s += e;
        }
        #pragma unroll
        for (int o = 16; o > 0; o >>= 1) s += __shfl_xor_sync(0xffffffffu, s, o);
        float inv = 1.0f / s;
        for (int j = lane; j < 1024; j += 32) row[j] *= inv;
    }
    __syncthreads();

    float* Pg = &g_p[(((size_t)(b * HH + h)) << 20) + (size_t)s0 * SS];
    #pragma unroll
    for (int i = 0; i < 16; i++) {
        int e = i * 1024 + tid * 4;
        *(float4*)&Pg[e] = *(float4*)&sc[e];
    }
}

// ---------------------------------------------------------------------------
// Kernel 5: ave_att = mean over heads of P
// ---------------------------------------------------------------------------
__global__ void ave_kernel(float* __restrict__ ave) {
    size_t idx = (size_t)blockIdx.x * 256 + threadIdx.x;
    size_t e = idx * 4;
    size_t b = e >> 20, st = e & 1048575;
    float4 a = make_float4(0.f, 0.f, 0.f, 0.f);
    #pragma unroll
    for (int h = 0; h < HH; h++) {
        const float4 p = *(const float4*)&g_p[((b * HH + h) << 20) + st];
        a.x += p.x; a.y += p.y; a.z += p.z; a.w += p.w;
    }
    a.x *= 0.125f; a.y *= 0.125f; a.z *= 0.125f; a.w *= 0.125f;
    *(float4*)&ave[e] = a;
}

// ---------------------------------------------------------------------------
// Kernel 6: PV GEMM per (b,h) with transposed V, f32x2 pairs along d.
// ---------------------------------------------------------------------------
__global__ __launch_bounds__(256) void pv_kernel() {
    __shared__ float Ps[128 * 36];
    __shared__ float Vs[32 * 64];
    const int b = blockIdx.z, h = blockIdx.y, s0 = blockIdx.x * 128;
    const float* Pg = &g_p[((size_t)(b * HH + h)) << 20];
    const int tid = threadIdx.x;
    const int tx = tid & 7, ty = tid >> 3;
    const int d_l = tx * 8, r_l = ty * 4;

    ull acc[4][4];
    #pragma unroll
    for (int i = 0; i < 4; i++)
        #pragma unroll
        for (int p = 0; p < 4; p++) acc[i][p] = 0ULL;

    const int pr = tid >> 1, pt = (tid & 1) * 16;
    for (int t0 = 0; t0 < SS; t0 += 32) {
        __syncthreads();
        #pragma unroll
        for (int j = 0; j < 4; j++)
            *(float4*)&Ps[pr * 36 + pt + j * 4] =
                *(const float4*)&Pg[(size_t)(s0 + pr) * SS + t0 + pt + j * 4];
        #pragma unroll
        for (int j = 0; j < 2; j++) {
            int idx = j * 256 + tid;
            int t = idx >> 4, d4 = (idx & 15) * 4;
            *(float4*)&Vs[t * 64 + d4] = *(const float4*)&g_vt[b][t0 + t][h * HD + d4];
        }
        __syncthreads();

        #pragma unroll
        for (int t = 0; t < 32; t++) {
            ull vb[4];
            #pragma unroll
            for (int p = 0; p < 4; p++) vb[p] = *(ull*)&Vs[t * 64 + d_l + 2 * p];
            #pragma unroll
            for (int i = 0; i < 4; i++) {
                ull ad = f2dup(Ps[(r_l + i) * 36 + t]);
                #pragma unroll
                for (int p = 0; p < 4; p++) acc[i][p] = f2fma(ad, vb[p], acc[i][p]);
            }
        }
    }

    #pragma unroll
    for (int i = 0; i < 4; i++)
        #pragma unroll
        for (int p = 0; p < 4; p++)
            *(ull*)&g_o1[b][s0 + r_l + i][h * HD + d_l + 2 * p] = acc[i][p];
}

// ---------------------------------------------------------------------------
// Kernel 7: output projection: out = O1 @ Wo^T + bo  (double-buffered f32x2)
// ---------------------------------------------------------------------------
__global__ __launch_bounds__(256) void proj_kernel(const float* __restrict__ Wo,
                                                   const float* __restrict__ bo,
                                                   float* __restrict__ out) {
    __shared__ float As[2][8][128];
    __shared__ float Bs[2][8][128];
    const int m0 = blockIdx.x * 128, n0 = blockIdx.y * 128;
    const float* A = &g_o1[0][0][0];
    const int tid = threadIdx.x, tx = tid & 15, ty = tid >> 4;
    const int li = tid >> 1, lj = (tid & 1) * 4;

    ull acc[8][4];
    #pragma unroll
    for (int i = 0; i < 8; i++)
        #pragma unroll
        for (int p = 0; p < 4; p++) acc[i][p] = 0ULL;

    float4 avr, bvr;
    {
        avr = *(const float4*)&A[(size_t)(m0 + li) * DD + lj];
        bvr = *(const float4*)&Wo[(size_t)(n0 + li) * DD + lj];
        As[0][lj + 0][li] = avr.x; As[0][lj + 1][li] = avr.y;
        As[0][lj + 2][li] = avr.z; As[0][lj + 3][li] = avr.w;
        Bs[0][lj + 0][li] = bvr.x; Bs[0][lj + 1][li] = bvr.y;
        Bs[0][lj + 2][li] = bvr.z; Bs[0][lj + 3][li] = bvr.w;
    }
    __syncthreads();

    int cur = 0;
    for (int k0 = 0; k0 < DD; k0 += 8) {
        bool hn = (k0 + 8) < DD;
        if (hn) {
            avr = *(const float4*)&A[(size_t)(m0 + li) * DD + k0 + 8 + lj];
            bvr = *(const float4*)&Wo[(size_t)(n0 + li) * DD + k0 + 8 + lj];
        }

        #pragma unroll
        for (int j = 0; j < 8; j++) {
            float4 a0 = *(float4*)&As[cur][j][ty * 8];
            float4 a1 = *(float4*)&As[cur][j][ty * 8 + 4];
            ull b2[4];
            #pragma unroll
            for (int p = 0; p < 4; p++) b2[p] = *(ull*)&Bs[cur][j][tx * 8 + 2 * p];
            float avv[8] = {a0.x, a0.y, a0.z, a0.w, a1.x, a1.y, a1.z, a1.w};
            #pragma unroll
            for (int i = 0; i < 8; i++) {
                ull ad = f2dup(avv[i]);
                #pragma unroll
                for (int p = 0; p < 4; p++) acc[i][p] = f2fma(ad, b2[p], acc[i][p]);
            }
        }

        if (hn) {
            int nb = cur ^ 1;
            As[nb][lj + 0][li] = avr.x; As[nb][lj + 1][li] = avr.y;
            As[nb][lj + 2][li] = avr.z; As[nb][lj + 3][li] = avr.w;
            Bs[nb][lj + 0][li] = bvr.x; Bs[nb][lj + 1][li] = bvr.y;
            Bs[nb][lj + 2][li] = bvr.z; Bs[nb][lj + 3][li] = bvr.w;
        }
        __syncthreads();
        cur ^= 1;
    }

    #pragma unroll
    for (int i = 0; i < 8; i++) {
        int m = m0 + ty * 8 + i;
        #pragma unroll
        for (int p = 0; p < 4; p++) {
            ull bb = *(const ull*)&bo[n0 + tx * 8 + 2 * p];
            ull r = f2add(acc[i][p], bb);
            *(ull*)&out[(size_t)m * DD + n0 + tx * 8 + 2 * p] = r;
        }
    }
}

// ---------------------------------------------------------------------------
extern "C" void kernel_launch(void* const* d_in, const int* in_sizes, int n_in,
                              void* d_out, int out_size) {
    const float* query = (const float*)d_in[0];
    const float* key_t = (const float*)d_in[1];
    const float* value = (const float*)d_in[2];
    const float* Wq    = (const float*)d_in[3];
    const float* bq    = (const float*)d_in[4];
    const float* Wk    = (const float*)d_in[5];
    const float* bk    = (const float*)d_in[6];
    const float* Wv    = (const float*)d_in[7];
    const float* bv    = (const float*)d_in[8];
    const float* Wo    = (const float*)d_in[9];
    const float* bo    = (const float*)d_in[10];

    float* out = (float*)d_out;
    float* ave = out + (size_t)BB * SS * DD;

    cudaFuncSetAttribute(conv_mma, cudaFuncAttributeMaxDynamicSharedMemorySize, CV_SMEM);
    cudaFuncSetAttribute(scores_kernel, cudaFuncAttributeMaxDynamicSharedMemorySize,
                         SC_SMEM3);

    transpose_kernel<<<dim3(SS / 32, DD / 32, 3 * BB), dim3(32, 8)>>>(query, key_t, value);
    conv_mma<<<dim3(DD / 128, SS / 128, 3 * BB), 256, CV_SMEM>>>(Wq, bq, Wk, bk, Wv, bv);
    vt_kernel<<<dim3(SS / 32, DD / 32, BB), dim3(32, 8)>>>();
    scores_kernel<<<dim3(SS / 16, HH, BB), 256, SC_SMEM3>>>();
    pv_kernel<<<dim3(SS / 128, HH, BB), 256>>>();
    ave_kernel<<<(BB * SS * SS / 4) / 256, 256>>>(ave);
    proj_kernel<<<dim3((BB * SS) / 128, DD / 128), 256>>>(Wo, bo, out);
}

// round 8
// speedup vs baseline: 1.2728x; 1.1022x over previous
#include <cuda_runtime.h>
#include <cuda_bf16.h>
#include <cstdint>

// ---------------------------------------------------------------------------
// ConvMultiheadAttention: B=8, S=1024, D=512, H=8, hd=64, KERNEL=3
// out  = [8,1024,512]  ; ave = [8,1024,1024]
// ---------------------------------------------------------------------------

#define BB 8
#define SS 1024
#define DD 512
#define HH 8
#define HD 64

typedef unsigned long long ull;

// ----- f32x2 helpers --------------------------------------------------------
__device__ __forceinline__ ull f2fma(ull a, ull b, ull c) {
    ull d; asm("fma.rn.f32x2 %0, %1, %2, %3;" : "=l"(d) : "l"(a), "l"(b), "l"(c)); return d;
}
__device__ __forceinline__ ull f2dup(float x) {
    ull d; asm("mov.b64 %0, {%1, %1};" : "=l"(d) : "f"(x)); return d;
}
__device__ __forceinline__ ull f2add(ull a, ull b) {
    ull d; asm("add.rn.f32x2 %0, %1, %2;" : "=l"(d) : "l"(a), "l"(b)); return d;
}
__device__ __forceinline__ float2 f2unpk(ull a) {
    float2 r; asm("mov.b64 {%0, %1}, %2;" : "=f"(r.x), "=f"(r.y) : "l"(a)); return r;
}

// ----- bf16 split helpers ----------------------------------------------------
__device__ __forceinline__ void bsplit2(float u, float v, uint32_t& ph, uint32_t& pl) {
    __nv_bfloat16 hu = __float2bfloat16_rn(u);
    __nv_bfloat16 hv = __float2bfloat16_rn(v);
    __nv_bfloat16 lu = __float2bfloat16_rn(u - __bfloat162float(hu));
    __nv_bfloat16 lv = __float2bfloat16_rn(v - __bfloat162float(hv));
    ph = (uint32_t)__bfloat16_as_ushort(hu) | ((uint32_t)__bfloat16_as_ushort(hv) << 16);
    pl = (uint32_t)__bfloat16_as_ushort(lu) | ((uint32_t)__bfloat16_as_ushort(lv) << 16);
}
__device__ __forceinline__ void mma_bf16s(float4& d, uint32_t a0, uint32_t a1,
                                          uint32_t a2, uint32_t a3,
                                          uint32_t b0, uint32_t b1) {
    asm("mma.sync.aligned.m16n8k16.row.col.f32.bf16.bf16.f32 "
        "{%0,%1,%2,%3}, {%4,%5,%6,%7}, {%8,%9}, {%0,%1,%2,%3};"
        : "+f"(d.x), "+f"(d.y), "+f"(d.z), "+f"(d.w)
        : "r"(a0), "r"(a1), "r"(a2), "r"(a3), "r"(b0), "r"(b1));
}

// ----- scratch (static device globals) --------------------------------------
__device__ float g_xt[3][BB][DD][SS];    // transposed inputs  [B,D,S]
__device__ float g_qkv[3][BB][DD][SS];   // conv outputs Q,K,V [B,D,S]
__device__ float g_vt[BB][SS][DD];       // V transposed to [B,S,D]
__device__ float g_p[(size_t)BB * HH * SS * SS]; // attention probs
__device__ float g_o1[BB][SS][DD];       // pre-projection output

// ---------------------------------------------------------------------------
// Kernel 1: transpose [B,S,D] -> [B,D,S] for q, k, v
// ---------------------------------------------------------------------------
__global__ void transpose_kernel(const float* __restrict__ q,
                                 const float* __restrict__ k,
                                 const float* __restrict__ v) {
    __shared__ float tile[32][33];
    int zz = blockIdx.z;
    int tn = zz / BB, b = zz % BB;
    const float* src = (tn == 0) ? q : (tn == 1) ? k : v;
    float* dst = &g_xt[tn][b][0][0];
    int s0 = blockIdx.x * 32, d0 = blockIdx.y * 32;
    int tx = threadIdx.x, ty = threadIdx.y;
    #pragma unroll
    for (int i = ty; i < 32; i += 8)
        tile[i][tx] = src[((size_t)b * SS + s0 + i) * DD + d0 + tx];
    __syncthreads();
    #pragma unroll
    for (int i = ty; i < 32; i += 8)
        dst[(size_t)(d0 + i) * SS + s0 + tx] = tile[tx][i];
}

// ---------------------------------------------------------------------------
// Kernel 2: conv1d projections via mma.sync bf16 m16n8k16 (split, 3 terms).
// C[co 128][s 128] = sum_kk A[co][kk]*B[kk][s]. k-slab 32 (2 k16 steps),
// double-buffered. A=Ah+Al, B=Bh+Bl; D += AhBh + AhBl + AlBh.
// Smem u32 layout: [row][pos] stride 17 (odd -> good bank spread), where
// pos(kp) = (kp&3)*4 + (kp>>2). Fragment gathers are scalar LDS.32 pairs
// (stride 17 is odd: 8B loads would be misaligned on odd rows).
// ---------------------------------------------------------------------------
#define CV_ST 17
#define CV_AH 0
#define CV_AL 2176
#define CV_BH 4352
#define CV_BL 6528
#define CV_BUF_U32 8704
#define CV_SMEM (2 * CV_BUF_U32 * (int)sizeof(uint32_t))

__global__ __launch_bounds__(256, 1)
void conv_mma(const float* __restrict__ Wq, const float* __restrict__ bq,
              const float* __restrict__ Wk, const float* __restrict__ bk,
              const float* __restrict__ Wv, const float* __restrict__ bv) {
    extern __shared__ uint32_t smu[];
    __shared__ float s_bias[128];

    const int zz = blockIdx.z, tn = zz / BB, b = zz % BB;
    const float* W    = (tn == 0) ? Wq : (tn == 1) ? Wk : Wv;
    const float* bias = (tn == 0) ? bq : (tn == 1) ? bk : bv;
    const int KER  = (tn == 2) ? 1 : 3;
    const int Kdim = DD * KER;
    const float* xsrc = &g_xt[tn][b][0][0];
    float* out = &g_qkv[tn][b][0][0];
    const int m0 = blockIdx.x * 128, n0 = blockIdx.y * 128;
    const int tid = threadIdx.x, wid = tid >> 5, lane = tid & 31;
    const int g = lane >> 2, tg = lane & 3;
    const int wm = (wid >> 2) * 64, wn = (wid & 3) * 32;

    if (tid < 128) s_bias[tid] = bias[m0 + tid];

    float4 dacc[4][4];
    #pragma unroll
    for (int mi = 0; mi < 4; mi++)
        #pragma unroll
        for (int ni = 0; ni < 4; ni++) dacc[mi][ni] = make_float4(0.f, 0.f, 0.f, 0.f);

    // staging maps
    const int a_row = tid >> 1, a_kp0 = (tid & 1) * 8;   // A: 8 kpairs each
    const int b_s = tid & 127, b_kp0 = (tid >> 7) * 8;   // B: 8 kpairs at col b_s

    const int NC = Kdim / 32;
    float4 a_reg[4];
    float  b_reg[16];

    auto ldg_slab = [&](int c) {
        #pragma unroll
        for (int q = 0; q < 4; q++)
            a_reg[q] = *(const float4*)&W[(size_t)(m0 + a_row) * Kdim + c * 32
                                          + a_kp0 * 2 + q * 4];
        #pragma unroll
        for (int j = 0; j < 8; j++) {
            #pragma unroll
            for (int e = 0; e < 2; e++) {
                int kk = c * 32 + 2 * (b_kp0 + j) + e;
                int ci, kof;
                if (KER == 3) { ci = kk / 3; kof = kk - ci * 3 - 1; }
                else          { ci = kk;     kof = 0; }
                int s = n0 + b_s + kof;
                b_reg[j * 2 + e] = (s >= 0 && s < SS) ? xsrc[(size_t)ci * SS + s] : 0.0f;
            }
        }
    };
    auto sts_slab = [&](int bf) {
        uint32_t* Ah = smu + bf * CV_BUF_U32 + CV_AH;
        uint32_t* Al = smu + bf * CV_BUF_U32 + CV_AL;
        uint32_t* Bh = smu + bf * CV_BUF_U32 + CV_BH;
        uint32_t* Bl = smu + bf * CV_BUF_U32 + CV_BL;
        #pragma unroll
        for (int q = 0; q < 4; q++) {
            float vv[4] = {a_reg[q].x, a_reg[q].y, a_reg[q].z, a_reg[q].w};
            #pragma unroll
            for (int p = 0; p < 2; p++) {
                int kp = a_kp0 + q * 2 + p;
                int pos = (kp & 3) * 4 + (kp >> 2);
                uint32_t ph, pl;
                bsplit2(vv[2 * p], vv[2 * p + 1], ph, pl);
                Ah[a_row * CV_ST + pos] = ph;
                Al[a_row * CV_ST + pos] = pl;
            }
        }
        #pragma unroll
        for (int j = 0; j < 8; j++) {
            int kp = b_kp0 + j;
            int pos = (kp & 3) * 4 + (kp >> 2);
            uint32_t ph, pl;
            bsplit2(b_reg[j * 2], b_reg[j * 2 + 1], ph, pl);
            Bh[b_s * CV_ST + pos] = ph;
            Bl[b_s * CV_ST + pos] = pl;
        }
    };

    ldg_slab(0);
    sts_slab(0);
    __syncthreads();

    for (int c = 0; c < NC; c++) {
        const int bf = c & 1;
        const bool have = (c + 1) < NC;
        if (have) ldg_slab(c + 1);

        const uint32_t* Ah = smu + bf * CV_BUF_U32 + CV_AH;
        const uint32_t* Al = smu + bf * CV_BUF_U32 + CV_AL;
        const uint32_t* Bh = smu + bf * CV_BUF_U32 + CV_BH;
        const uint32_t* Bl = smu + bf * CV_BUF_U32 + CV_BL;

        #pragma unroll
        for (int s = 0; s < 2; s++) {
            const int fo = tg * 4 + 2 * s;
            // fragments: a = {A[r], A[r+8st], A[r+1], A[r+8st+1]}, b = {B[c], B[c+1]}
            uint32_t ahx[4][4], alx[4][4], bhx[4][2], blx[4][2];
            #pragma unroll
            for (int mi = 0; mi < 4; mi++) {
                int r = (wm + mi * 16 + g) * CV_ST + fo;
                int r8 = r + 8 * CV_ST;
                ahx[mi][0] = Ah[r];     ahx[mi][1] = Ah[r8];
                ahx[mi][2] = Ah[r + 1]; ahx[mi][3] = Ah[r8 + 1];
                alx[mi][0] = Al[r];     alx[mi][1] = Al[r8];
                alx[mi][2] = Al[r + 1]; alx[mi][3] = Al[r8 + 1];
            }
            #pragma unroll
            for (int ni = 0; ni < 4; ni++) {
                int cidx = (wn + ni * 8 + g) * CV_ST + fo;
                bhx[ni][0] = Bh[cidx]; bhx[ni][1] = Bh[cidx + 1];
                blx[ni][0] = Bl[cidx]; blx[ni][1] = Bl[cidx + 1];
            }
            #pragma unroll
            for (int mi = 0; mi < 4; mi++)
                #pragma unroll
                for (int ni = 0; ni < 4; ni++) {
                    mma_bf16s(dacc[mi][ni], ahx[mi][0], ahx[mi][1], ahx[mi][2],
                              ahx[mi][3], bhx[ni][0], bhx[ni][1]);
                    mma_bf16s(dacc[mi][ni], ahx[mi][0], ahx[mi][1], ahx[mi][2],
                              ahx[mi][3], blx[ni][0], blx[ni][1]);
                    mma_bf16s(dacc[mi][ni], alx[mi][0], alx[mi][1], alx[mi][2],
                              alx[mi][3], bhx[ni][0], bhx[ni][1]);
                }
        }

        if (have) sts_slab(bf ^ 1);
        __syncthreads();
    }

    // ---- epilogue: add bias, write [co][s] ----
    #pragma unroll
    for (int mi = 0; mi < 4; mi++) {
        int lr0 = wm + mi * 16 + g;
        float b0 = s_bias[lr0], b1 = s_bias[lr0 + 8];
        #pragma unroll
        for (int ni = 0; ni < 4; ni++) {
            int col = n0 + wn + ni * 8 + 2 * tg;
            float4 d = dacc[mi][ni];
            *(float2*)&out[(size_t)(m0 + lr0) * SS + col]     = make_float2(d.x + b0, d.y + b0);
            *(float2*)&out[(size_t)(m0 + lr0 + 8) * SS + col] = make_float2(d.z + b1, d.w + b1);
        }
    }
}

// ---------------------------------------------------------------------------
// Kernel 3: transpose V conv output [B,D,S] -> [B,S,D]
// ---------------------------------------------------------------------------
__global__ void vt_kernel() {
    __shared__ float tile[32][33];
    int b = blockIdx.z;
    const float* src = &g_qkv[2][b][0][0];
    float* dst = &g_vt[b][0][0];
    int s0 = blockIdx.x * 32, d0 = blockIdx.y * 32;
    int tx = threadIdx.x, ty = threadIdx.y;
    #pragma unroll
    for (int i = ty; i < 32; i += 8)
        tile[i][tx] = src[(size_t)(d0 + i) * SS + s0 + tx];
    __syncthreads();
    #pragma unroll
    for (int i = ty; i < 32; i += 8)
        dst[(size_t)(s0 + i) * DD + d0 + tx] = tile[tx][i];
}

// ---------------------------------------------------------------------------
// Kernel 4: scores + softmax per (b, h, 32-row tile)
// ---------------------------------------------------------------------------
__global__ __launch_bounds__(256) void scores_kernel() {
    extern __shared__ float sm[];
    float* sc = sm;                    // 32*1024
    float* Kc = sm + 32 * 1024;        // 64*256
    float* Qt = sm + 32 * 1024 + 64 * 256; // 64*32

    const int b = blockIdx.z, h = blockIdx.y, s0 = blockIdx.x * 32;
    const float* Qg = &g_qkv[0][b][h * HD][0];
    const float* Kg = &g_qkv[1][b][h * HD][0];
    const int tid = threadIdx.x;

    #pragma unroll
    for (int i = 0; i < 2; i++) {
        int e = i * 1024 + tid * 4;
        int d = e >> 5, r = e & 31;
        *(float4*)&Qt[d * 32 + r] = *(const float4*)&Qg[(size_t)d * SS + s0 + r];
    }

    const int tx = tid & 63, ty = tid >> 6;
    const int t_l = tx * 4, r_l = ty * 8;

    for (int tc = 0; tc < 4; tc++) {
        __syncthreads();
        #pragma unroll
        for (int i = 0; i < 16; i++) {
            int e = i * 1024 + tid * 4;
            int d = e >> 8, t = e & 255;
            *(float4*)&Kc[d * 256 + t] = *(const float4*)&Kg[(size_t)d * SS + tc * 256 + t];
        }
        __syncthreads();

        ull acc[4][4];
        #pragma unroll
        for (int ri = 0; ri < 4; ri++)
            #pragma unroll
            for (int j = 0; j < 4; j++) acc[ri][j] = 0ULL;

        #pragma unroll
        for (int d = 0; d < 64; d++) {
            const float* qr = &Qt[d * 32 + r_l];
            ull q0 = *(ull*)&qr[0], q1 = *(ull*)&qr[2];
            ull q2 = *(ull*)&qr[4], q3 = *(ull*)&qr[6];
            float4 kv = *(float4*)&Kc[d * 256 + t_l];
            ull k0 = f2dup(kv.x), k1 = f2dup(kv.y);
            ull k2 = f2dup(kv.z), k3 = f2dup(kv.w);
            acc[0][0] = f2fma(q0, k0, acc[0][0]); acc[0][1] = f2fma(q0, k1, acc[0][1]);
            acc[0][2] = f2fma(q0, k2, acc[0][2]); acc[0][3] = f2fma(q0, k3, acc[0][3]);
            acc[1][0] = f2fma(q1, k0, acc[1][0]); acc[1][1] = f2fma(q1, k1, acc[1][1]);
            acc[1][2] = f2fma(q1, k2, acc[1][2]); acc[1][3] = f2fma(q1, k3, acc[1][3]);
            acc[2][0] = f2fma(q2, k0, acc[2][0]); acc[2][1] = f2fma(q2, k1, acc[2][1]);
            acc[2][2] = f2fma(q2, k2, acc[2][2]); acc[2][3] = f2fma(q2, k3, acc[2][3]);
            acc[3][0] = f2fma(q3, k0, acc[3][0]); acc[3][1] = f2fma(q3, k1, acc[3][1]);
            acc[3][2] = f2fma(q3, k2, acc[3][2]); acc[3][3] = f2fma(q3, k3, acc[3][3]);
        }

        const float sclf = 1.0f / 64.0f;
        #pragma unroll
        for (int ri = 0; ri < 4; ri++)
            #pragma unroll
            for (int j = 0; j < 4; j++) {
                float2 v = f2unpk(acc[ri][j]);
                sc[(r_l + 2 * ri) * 1024 + tc * 256 + t_l + j]     = v.x * sclf;
                sc[(r_l + 2 * ri + 1) * 1024 + tc * 256 + t_l + j] = v.y * sclf;
            }
    }
    __syncthreads();

    const int warp = tid >> 5, lane = tid & 31;
    for (int rr = warp; rr < 32; rr += 8) {
        float* row = &sc[rr * 1024];
        float m = -1e30f;
        for (int j = lane; j < 1024; j += 32) m = fmaxf(m, row[j]);
        #pragma unroll
        for (int o = 16; o > 0; o >>= 1) m = fmaxf(m, __shfl_xor_sync(0xffffffffu, m, o));
        float s = 0.0f;
        for (int j = lane; j < 1024; j += 32) {
            float e = __expf(row[j] - m);
            row[j] = e;
            s += e;
        }
        #pragma unroll
        for (int o = 16; o > 0; o >>= 1) s += __shfl_xor_sync(0xffffffffu, s, o);
        float inv = 1.0f / s;
        for (int j = lane; j < 1024; j += 32) row[j] *= inv;
    }
    __syncthreads();

    float* Pg = &g_p[(((size_t)(b * HH + h)) << 20) + (size_t)s0 * SS];
    #pragma unroll
    for (int i = 0; i < 32; i++) {
        int e = i * 1024 + tid * 4;
        *(float4*)&Pg[e] = *(float4*)&sc[e];
    }
}

// ---------------------------------------------------------------------------
// Kernel 5: ave_att = mean over heads of P
// ---------------------------------------------------------------------------
__global__ void ave_kernel(float* __restrict__ ave) {
    size_t idx = (size_t)blockIdx.x * 256 + threadIdx.x;
    size_t e = idx * 4;
    size_t b = e >> 20, st = e & 1048575;
    float4 a = make_float4(0.f, 0.f, 0.f, 0.f);
    #pragma unroll
    for (int h = 0; h < HH; h++) {
        const float4 p = *(const float4*)&g_p[((b * HH + h) << 20) + st];
        a.x += p.x; a.y += p.y; a.z += p.z; a.w += p.w;
    }
    a.x *= 0.125f; a.y *= 0.125f; a.z *= 0.125f; a.w *= 0.125f;
    *(float4*)&ave[e] = a;
}

// ---------------------------------------------------------------------------
// Kernel 6: PV GEMM per (b,h) with transposed V, f32x2 pairs along d.
// ---------------------------------------------------------------------------
__global__ __launch_bounds__(256) void pv_kernel() {
    __shared__ float Ps[128 * 36];
    __shared__ float Vs[32 * 64];
    const int b = blockIdx.z, h = blockIdx.y, s0 = blockIdx.x * 128;
    const float* Pg = &g_p[((size_t)(b * HH + h)) << 20];
    const int tid = threadIdx.x;
    const int tx = tid & 7, ty = tid >> 3;
    const int d_l = tx * 8, r_l = ty * 4;

    ull acc[4][4];
    #pragma unroll
    for (int i = 0; i < 4; i++)
        #pragma unroll
        for (int p = 0; p < 4; p++) acc[i][p] = 0ULL;

    const int pr = tid >> 1, pt = (tid & 1) * 16;
    for (int t0 = 0; t0 < SS; t0 += 32) {
        __syncthreads();
        #pragma unroll
        for (int j = 0; j < 4; j++)
            *(float4*)&Ps[pr * 36 + pt + j * 4] =
                *(const float4*)&Pg[(size_t)(s0 + pr) * SS + t0 + pt + j * 4];
        #pragma unroll
        for (int j = 0; j < 2; j++) {
            int idx = j * 256 + tid;
            int t = idx >> 4, d4 = (idx & 15) * 4;
            *(float4*)&Vs[t * 64 + d4] = *(const float4*)&g_vt[b][t0 + t][h * HD + d4];
        }
        __syncthreads();

        #pragma unroll
        for (int t = 0; t < 32; t++) {
            ull vb[4];
            #pragma unroll
            for (int p = 0; p < 4; p++) vb[p] = *(ull*)&Vs[t * 64 + d_l + 2 * p];
            #pragma unroll
            for (int i = 0; i < 4; i++) {
                ull ad = f2dup(Ps[(r_l + i) * 36 + t]);
                #pragma unroll
                for (int p = 0; p < 4; p++) acc[i][p] = f2fma(ad, vb[p], acc[i][p]);
            }
        }
    }

    #pragma unroll
    for (int i = 0; i < 4; i++)
        #pragma unroll
        for (int p = 0; p < 4; p++)
            *(ull*)&g_o1[b][s0 + r_l + i][h * HD + d_l + 2 * p] = acc[i][p];
}

// ---------------------------------------------------------------------------
// Kernel 7: output projection: out = O1 @ Wo^T + bo  (double-buffered f32x2)
// ---------------------------------------------------------------------------
__global__ __launch_bounds__(256) void proj_kernel(const float* __restrict__ Wo,
                                                   const float* __restrict__ bo,
                                                   float* __restrict__ out) {
    __shared__ float As[2][8][128];
    __shared__ float Bs[2][8][128];
    const int m0 = blockIdx.x * 128, n0 = blockIdx.y * 128;
    const float* A = &g_o1[0][0][0];
    const int tid = threadIdx.x, tx = tid & 15, ty = tid >> 4;
    const int li = tid >> 1, lj = (tid & 1) * 4;

    ull acc[8][4];
    #pragma unroll
    for (int i = 0; i < 8; i++)
        #pragma unroll
        for (int p = 0; p < 4; p++) acc[i][p] = 0ULL;

    float4 avr, bvr;
    {
        avr = *(const float4*)&A[(size_t)(m0 + li) * DD + lj];
        bvr = *(const float4*)&Wo[(size_t)(n0 + li) * DD + lj];
        As[0][lj + 0][li] = avr.x; As[0][lj + 1][li] = avr.y;
        As[0][lj + 2][li] = avr.z; As[0][lj + 3][li] = avr.w;
        Bs[0][lj + 0][li] = bvr.x; Bs[0][lj + 1][li] = bvr.y;
        Bs[0][lj + 2][li] = bvr.z; Bs[0][lj + 3][li] = bvr.w;
    }
    __syncthreads();

    int cur = 0;
    for (int k0 = 0; k0 < DD; k0 += 8) {
        bool hn = (k0 + 8) < DD;
        if (hn) {
            avr = *(const float4*)&A[(size_t)(m0 + li) * DD + k0 + 8 + lj];
            bvr = *(const float4*)&Wo[(size_t)(n0 + li) * DD + k0 + 8 + lj];
        }

        #pragma unroll
        for (int j = 0; j < 8; j++) {
            float4 a0 = *(float4*)&As[cur][j][ty * 8];
            float4 a1 = *(float4*)&As[cur][j][ty * 8 + 4];
            ull b2[4];
            #pragma unroll
            for (int p = 0; p < 4; p++) b2[p] = *(ull*)&Bs[cur][j][tx * 8 + 2 * p];
            float avv[8] = {a0.x, a0.y, a0.z, a0.w, a1.x, a1.y, a1.z, a1.w};
            #pragma unroll
            for (int i = 0; i < 8; i++) {
                ull ad = f2dup(avv[i]);
                #pragma unroll
                for (int p = 0; p < 4; p++) acc[i][p] = f2fma(ad, b2[p], acc[i][p]);
            }
        }

        if (hn) {
            int nb = cur ^ 1;
            As[nb][lj + 0][li] = avr.x; As[nb][lj + 1][li] = avr.y;
            As[nb][lj + 2][li] = avr.z; As[nb][lj + 3][li] = avr.w;
            Bs[nb][lj + 0][li] = bvr.x; Bs[nb][lj + 1][li] = bvr.y;
            Bs[nb][lj + 2][li] = bvr.z; Bs[nb][lj + 3][li] = bvr.w;
        }
        __syncthreads();
        cur ^= 1;
    }

    #pragma unroll
    for (int i = 0; i < 8; i++) {
        int m = m0 + ty * 8 + i;
        #pragma unroll
        for (int p = 0; p < 4; p++) {
            ull bb = *(const ull*)&bo[n0 + tx * 8 + 2 * p];
            ull r = f2add(acc[i][p], bb);
            *(ull*)&out[(size_t)m * DD + n0 + tx * 8 + 2 * p] = r;
        }
    }
}

// ---------------------------------------------------------------------------
extern "C" void kernel_launch(void* const* d_in, const int* in_sizes, int n_in,
                              void* d_out, int out_size) {
    const float* query = (const float*)d_in[0];
    const float* key_t = (const float*)d_in[1];
    const float* value = (const float*)d_in[2];
    const float* Wq    = (const float*)d_in[3];
    const float* bq    = (const float*)d_in[4];
    const float* Wk    = (const float*)d_in[5];
    const float* bk    = (const float*)d_in[6];
    const float* Wv    = (const float*)d_in[7];
    const float* bv    = (const float*)d_in[8];
    const float* Wo    = (const float*)d_in[9];
    const float* bo    = (const float*)d_in[10];

    float* out = (float*)d_out;
    float* ave = out + (size_t)BB * SS * DD;

    const size_t SC_SMEM = (size_t)(32 * 1024 + 64 * 256 + 64 * 32) * sizeof(float);
    cudaFuncSetAttribute(conv_mma, cudaFuncAttributeMaxDynamicSharedMemorySize, CV_SMEM);
    cudaFuncSetAttribute(scores_kernel, cudaFuncAttributeMaxDynamicSharedMemorySize,
                         (int)SC_SMEM);

    transpose_kernel<<<dim3(SS / 32, DD / 32, 3 * BB), dim3(32, 8)>>>(query, key_t, value);
    conv_mma<<<dim3(DD / 128, SS / 128, 3 * BB), 256, CV_SMEM>>>(Wq, bq, Wk, bk, Wv, bv);
    vt_kernel<<<dim3(SS / 32, DD / 32, BB), dim3(32, 8)>>>();
    scores_kernel<<<dim3(SS / 32, HH, BB), 256, SC_SMEM>>>();
    pv_kernel<<<dim3(SS / 128, HH, BB), 256>>>();
    ave_kernel<<<(BB * SS * SS / 4) / 256, 256>>>(ave);
    proj_kernel<<<dim3((BB * SS) / 128, DD / 128), 256>>>(Wo, bo, out);
}

// round 9
// speedup vs baseline: 1.4810x; 1.1636x over previous
#include <cuda_runtime.h>
#include <cuda_bf16.h>
#include <cstdint>

// ---------------------------------------------------------------------------
// ConvMultiheadAttention: B=8, S=1024, D=512, H=8, hd=64, KERNEL=3
// out  = [8,1024,512]  ; ave = [8,1024,1024]
// ---------------------------------------------------------------------------

#define BB 8
#define SS 1024
#define DD 512
#define HH 8
#define HD 64

typedef unsigned long long ull;

// ----- f32x2 helpers --------------------------------------------------------
__device__ __forceinline__ ull f2fma(ull a, ull b, ull c) {
    ull d; asm("fma.rn.f32x2 %0, %1, %2, %3;" : "=l"(d) : "l"(a), "l"(b), "l"(c)); return d;
}
__device__ __forceinline__ ull f2dup(float x) {
    ull d; asm("mov.b64 %0, {%1, %1};" : "=l"(d) : "f"(x)); return d;
}
__device__ __forceinline__ ull f2add(ull a, ull b) {
    ull d; asm("add.rn.f32x2 %0, %1, %2;" : "=l"(d) : "l"(a), "l"(b)); return d;
}

// ----- bf16 split helpers ----------------------------------------------------
__device__ __forceinline__ void bsplit2(float u, float v, uint32_t& ph, uint32_t& pl) {
    __nv_bfloat16 hu = __float2bfloat16_rn(u);
    __nv_bfloat16 hv = __float2bfloat16_rn(v);
    __nv_bfloat16 lu = __float2bfloat16_rn(u - __bfloat162float(hu));
    __nv_bfloat16 lv = __float2bfloat16_rn(v - __bfloat162float(hv));
    ph = (uint32_t)__bfloat16_as_ushort(hu) | ((uint32_t)__bfloat16_as_ushort(hv) << 16);
    pl = (uint32_t)__bfloat16_as_ushort(lu) | ((uint32_t)__bfloat16_as_ushort(lv) << 16);
}
__device__ __forceinline__ void mma_bf16s(float4& d, uint32_t a0, uint32_t a1,
                                          uint32_t a2, uint32_t a3,
                                          uint32_t b0, uint32_t b1) {
    asm("mma.sync.aligned.m16n8k16.row.col.f32.bf16.bf16.f32 "
        "{%0,%1,%2,%3}, {%4,%5,%6,%7}, {%8,%9}, {%0,%1,%2,%3};"
        : "+f"(d.x), "+f"(d.y), "+f"(d.z), "+f"(d.w)
        : "r"(a0), "r"(a1), "r"(a2), "r"(a3), "r"(b0), "r"(b1));
}
// kpair position permutation so fragment (tg, k16-step s) reads pos fo, fo+1.
// 16-kpair (slab 32): pos = (kp&3)*4 + (kp>>2),  fo = tg*4 + 2s
// 32-kpair (K=64):    pos = (kp&3)*8 + 2*(kp>>3) + ((kp>>2)&1), fo = tg*8 + 2s
__device__ __forceinline__ int pos16(int kp) { return (kp & 3) * 4 + (kp >> 2); }
__device__ __forceinline__ int pos32(int kp) {
    return (kp & 3) * 8 + 2 * (kp >> 3) + ((kp >> 2) & 1);
}

// ----- scratch (static device globals) --------------------------------------
__device__ float g_xt[3][BB][DD][SS];    // transposed inputs  [B,D,S]
__device__ float g_qkv[3][BB][DD][SS];   // conv outputs Q,K,V [B,D,S]
__device__ uint32_t g_sqh[BB * HH][SS][32]; // Q/64 split hi, kpair-packed
__device__ uint32_t g_sql[BB * HH][SS][32]; // Q/64 split lo
__device__ uint32_t g_skh[BB * HH][SS][32]; // K split hi
__device__ uint32_t g_skl[BB * HH][SS][32]; // K split lo
__device__ float g_p[(size_t)BB * HH * SS * SS]; // raw scores -> probs
__device__ float g_o1[BB][SS][DD];       // pre-projection output

// ---------------------------------------------------------------------------
// Kernel 1: transpose [B,S,D] -> [B,D,S] for q, k, v
// ---------------------------------------------------------------------------
__global__ void transpose_kernel(const float* __restrict__ q,
                                 const float* __restrict__ k,
                                 const float* __restrict__ v) {
    __shared__ float tile[32][33];
    int zz = blockIdx.z;
    int tn = zz / BB, b = zz % BB;
    const float* src = (tn == 0) ? q : (tn == 1) ? k : v;
    float* dst = &g_xt[tn][b][0][0];
    int s0 = blockIdx.x * 32, d0 = blockIdx.y * 32;
    int tx = threadIdx.x, ty = threadIdx.y;
    #pragma unroll
    for (int i = ty; i < 32; i += 8)
        tile[i][tx] = src[((size_t)b * SS + s0 + i) * DD + d0 + tx];
    __syncthreads();
    #pragma unroll
    for (int i = ty; i < 32; i += 8)
        dst[(size_t)(d0 + i) * SS + s0 + tx] = tile[tx][i];
}

// ---------------------------------------------------------------------------
// Kernel 2: conv1d projections via mma.sync bf16 m16n8k16 (split, 3 terms).
// (unchanged from R8 — passed with rel_err 2.6e-5)
// ---------------------------------------------------------------------------
#define CV_ST 17
#define CV_AH 0
#define CV_AL 2176
#define CV_BH 4352
#define CV_BL 6528
#define CV_BUF_U32 8704
#define CV_SMEM (2 * CV_BUF_U32 * (int)sizeof(uint32_t))

__global__ __launch_bounds__(256, 1)
void conv_mma(const float* __restrict__ Wq, const float* __restrict__ bq,
              const float* __restrict__ Wk, const float* __restrict__ bk,
              const float* __restrict__ Wv, const float* __restrict__ bv) {
    extern __shared__ uint32_t smu[];
    __shared__ float s_bias[128];

    const int zz = blockIdx.z, tn = zz / BB, b = zz % BB;
    const float* W    = (tn == 0) ? Wq : (tn == 1) ? Wk : Wv;
    const float* bias = (tn == 0) ? bq : (tn == 1) ? bk : bv;
    const int KER  = (tn == 2) ? 1 : 3;
    const int Kdim = DD * KER;
    const float* xsrc = &g_xt[tn][b][0][0];
    float* out = &g_qkv[tn][b][0][0];
    const int m0 = blockIdx.x * 128, n0 = blockIdx.y * 128;
    const int tid = threadIdx.x, wid = tid >> 5, lane = tid & 31;
    const int g = lane >> 2, tg = lane & 3;
    const int wm = (wid >> 2) * 64, wn = (wid & 3) * 32;

    if (tid < 128) s_bias[tid] = bias[m0 + tid];

    float4 dacc[4][4];
    #pragma unroll
    for (int mi = 0; mi < 4; mi++)
        #pragma unroll
        for (int ni = 0; ni < 4; ni++) dacc[mi][ni] = make_float4(0.f, 0.f, 0.f, 0.f);

    const int a_row = tid >> 1, a_kp0 = (tid & 1) * 8;
    const int b_s = tid & 127, b_kp0 = (tid >> 7) * 8;

    const int NC = Kdim / 32;
    float4 a_reg[4];
    float  b_reg[16];

    auto ldg_slab = [&](int c) {
        #pragma unroll
        for (int q = 0; q < 4; q++)
            a_reg[q] = *(const float4*)&W[(size_t)(m0 + a_row) * Kdim + c * 32
                                          + a_kp0 * 2 + q * 4];
        #pragma unroll
        for (int j = 0; j < 8; j++) {
            #pragma unroll
            for (int e = 0; e < 2; e++) {
                int kk = c * 32 + 2 * (b_kp0 + j) + e;
                int ci, kof;
                if (KER == 3) { ci = kk / 3; kof = kk - ci * 3 - 1; }
                else          { ci = kk;     kof = 0; }
                int s = n0 + b_s + kof;
                b_reg[j * 2 + e] = (s >= 0 && s < SS) ? xsrc[(size_t)ci * SS + s] : 0.0f;
            }
        }
    };
    auto sts_slab = [&](int bf) {
        uint32_t* Ah = smu + bf * CV_BUF_U32 + CV_AH;
        uint32_t* Al = smu + bf * CV_BUF_U32 + CV_AL;
        uint32_t* Bh = smu + bf * CV_BUF_U32 + CV_BH;
        uint32_t* Bl = smu + bf * CV_BUF_U32 + CV_BL;
        #pragma unroll
        for (int q = 0; q < 4; q++) {
            float vv[4] = {a_reg[q].x, a_reg[q].y, a_reg[q].z, a_reg[q].w};
            #pragma unroll
            for (int p = 0; p < 2; p++) {
                int kp = a_kp0 + q * 2 + p;
                int pos = pos16(kp);
                uint32_t ph, pl;
                bsplit2(vv[2 * p], vv[2 * p + 1], ph, pl);
                Ah[a_row * CV_ST + pos] = ph;
                Al[a_row * CV_ST + pos] = pl;
            }
        }
        #pragma unroll
        for (int j = 0; j < 8; j++) {
            int kp = b_kp0 + j;
            int pos = pos16(kp);
            uint32_t ph, pl;
            bsplit2(b_reg[j * 2], b_reg[j * 2 + 1], ph, pl);
            Bh[b_s * CV_ST + pos] = ph;
            Bl[b_s * CV_ST + pos] = pl;
        }
    };

    ldg_slab(0);
    sts_slab(0);
    __syncthreads();

    for (int c = 0; c < NC; c++) {
        const int bf = c & 1;
        const bool have = (c + 1) < NC;
        if (have) ldg_slab(c + 1);

        const uint32_t* Ah = smu + bf * CV_BUF_U32 + CV_AH;
        const uint32_t* Al = smu + bf * CV_BUF_U32 + CV_AL;
        const uint32_t* Bh = smu + bf * CV_BUF_U32 + CV_BH;
        const uint32_t* Bl = smu + bf * CV_BUF_U32 + CV_BL;

        #pragma unroll
        for (int s = 0; s < 2; s++) {
            const int fo = tg * 4 + 2 * s;
            uint32_t ahx[4][4], alx[4][4], bhx[4][2], blx[4][2];
            #pragma unroll
            for (int mi = 0; mi < 4; mi++) {
                int r = (wm + mi * 16 + g) * CV_ST + fo;
                int r8 = r + 8 * CV_ST;
                ahx[mi][0] = Ah[r];     ahx[mi][1] = Ah[r8];
                ahx[mi][2] = Ah[r + 1]; ahx[mi][3] = Ah[r8 + 1];
                alx[mi][0] = Al[r];     alx[mi][1] = Al[r8];
                alx[mi][2] = Al[r + 1]; alx[mi][3] = Al[r8 + 1];
            }
            #pragma unroll
            for (int ni = 0; ni < 4; ni++) {
                int cidx = (wn + ni * 8 + g) * CV_ST + fo;
                bhx[ni][0] = Bh[cidx]; bhx[ni][1] = Bh[cidx + 1];
                blx[ni][0] = Bl[cidx]; blx[ni][1] = Bl[cidx + 1];
            }
            #pragma unroll
            for (int mi = 0; mi < 4; mi++)
                #pragma unroll
                for (int ni = 0; ni < 4; ni++) {
                    mma_bf16s(dacc[mi][ni], ahx[mi][0], ahx[mi][1], ahx[mi][2],
                              ahx[mi][3], bhx[ni][0], bhx[ni][1]);
                    mma_bf16s(dacc[mi][ni], ahx[mi][0], ahx[mi][1], ahx[mi][2],
                              ahx[mi][3], blx[ni][0], blx[ni][1]);
                    mma_bf16s(dacc[mi][ni], alx[mi][0], alx[mi][1], alx[mi][2],
                              alx[mi][3], bhx[ni][0], bhx[ni][1]);
                }
        }

        if (have) sts_slab(bf ^ 1);
        __syncthreads();
    }

    #pragma unroll
    for (int mi = 0; mi < 4; mi++) {
        int lr0 = wm + mi * 16 + g;
        float b0 = s_bias[lr0], b1 = s_bias[lr0 + 8];
        #pragma unroll
        for (int ni = 0; ni < 4; ni++) {
            int col = n0 + wn + ni * 8 + 2 * tg;
            float4 d = dacc[mi][ni];
            *(float2*)&out[(size_t)(m0 + lr0) * SS + col]     = make_float2(d.x + b0, d.y + b0);
            *(float2*)&out[(size_t)(m0 + lr0 + 8) * SS + col] = make_float2(d.z + b1, d.w + b1);
        }
    }
}

// ---------------------------------------------------------------------------
// Kernel 3: qkprep — split Q (x 1/64) and K into kpair-packed bf16 hi/lo.
// [B,D,S] -> [bh][s][pos32(kp)] u32.
// ---------------------------------------------------------------------------
__global__ void qkprep_kernel() {
    __shared__ float tile[32][33];
    int zz = blockIdx.z;
    int tn = zz / BB, b = zz % BB;     // tn: 0=Q, 1=K
    const float* src = &g_qkv[tn][b][0][0];
    int s0 = blockIdx.x * 32, d0 = blockIdx.y * 32;
    int tx = threadIdx.x, ty = threadIdx.y;
    #pragma unroll
    for (int i = ty; i < 32; i += 8)
        tile[i][tx] = src[(size_t)(d0 + i) * SS + s0 + tx];
    __syncthreads();

    const float scale = (tn == 0) ? 0.015625f : 1.0f;
    const int h = d0 >> 6;
    const int kp_base = (d0 & 63) >> 1;    // 0 or 16
    const int bh = b * HH + h;
    uint32_t* dh = (tn == 0) ? &g_sqh[bh][0][0] : &g_skh[bh][0][0];
    uint32_t* dl = (tn == 0) ? &g_sql[bh][0][0] : &g_skl[bh][0][0];

    const int kpl = tx & 15;
    const int half = tx >> 4;              // 0: hi array, 1: lo array
    const int pos = pos32(kp_base + kpl);
    #pragma unroll
    for (int i = ty; i < 32; i += 8) {
        float u = tile[2 * kpl][i] * scale;
        float v = tile[2 * kpl + 1][i] * scale;
        uint32_t ph, pl;
        bsplit2(u, v, ph, pl);
        if (half == 0) dh[(size_t)(s0 + i) * 32 + pos] = ph;
        else           dl[(size_t)(s0 + i) * 32 + pos] = pl;
    }
}

// ---------------------------------------------------------------------------
// Kernel 4: scores GEMM via bf16 mma (3 terms). Per CTA: (b,h,128s,128t),
// K=64 single shot. Raw scores (already x 1/64 via Q) -> g_p.
// smem stride 33: gathers conflict-free (g + 8*tg distinct mod 32).
// ---------------------------------------------------------------------------
#define SG_ST 33
#define SG_A_H 0
#define SG_A_L 4224
#define SG_B_H 8448
#define SG_B_L 12672
#define SG_SMEM (16896 * (int)sizeof(uint32_t))

__global__ __launch_bounds__(256, 2) void scores_gemm() {
    extern __shared__ uint32_t smu[];
    const int b = blockIdx.z, h = blockIdx.y;
    const int s0 = (blockIdx.x >> 3) * 128, t0 = (blockIdx.x & 7) * 128;
    const int bh = b * HH + h;
    const int tid = threadIdx.x, wid = tid >> 5, lane = tid & 31;
    const int g = lane >> 2, tg = lane & 3;
    const int wm = (wid >> 2) * 64, wn = (wid & 3) * 32;

    // ---- staging: straight u32 copies (pre-split/packed in qkprep) ----
    {
        const int row = tid >> 1, c0 = (tid & 1) * 16;
        const uint32_t* sa_h = &g_sqh[bh][s0 + row][c0];
        const uint32_t* sa_l = &g_sql[bh][s0 + row][c0];
        const uint32_t* sb_h = &g_skh[bh][t0 + row][c0];
        const uint32_t* sb_l = &g_skl[bh][t0 + row][c0];
        uint32_t* Ah = smu + SG_A_H + row * SG_ST + c0;
        uint32_t* Al = smu + SG_A_L + row * SG_ST + c0;
        uint32_t* Bh = smu + SG_B_H + row * SG_ST + c0;
        uint32_t* Bl = smu + SG_B_L + row * SG_ST + c0;
        #pragma unroll
        for (int i = 0; i < 4; i++) {
            uint4 va = *(const uint4*)&sa_h[4 * i];
            uint4 vb = *(const uint4*)&sa_l[4 * i];
            uint4 vc = *(const uint4*)&sb_h[4 * i];
            uint4 vd = *(const uint4*)&sb_l[4 * i];
            Ah[4 * i] = va.x; Ah[4 * i + 1] = va.y; Ah[4 * i + 2] = va.z; Ah[4 * i + 3] = va.w;
            Al[4 * i] = vb.x; Al[4 * i + 1] = vb.y; Al[4 * i + 2] = vb.z; Al[4 * i + 3] = vb.w;
            Bh[4 * i] = vc.x; Bh[4 * i + 1] = vc.y; Bh[4 * i + 2] = vc.z; Bh[4 * i + 3] = vc.w;
            Bl[4 * i] = vd.x; Bl[4 * i + 1] = vd.y; Bl[4 * i + 2] = vd.z; Bl[4 * i + 3] = vd.w;
        }
    }
    __syncthreads();

    const uint32_t* Ah = smu + SG_A_H;
    const uint32_t* Al = smu + SG_A_L;
    const uint32_t* Bh = smu + SG_B_H;
    const uint32_t* Bl = smu + SG_B_L;

    float4 dacc[4][4];
    #pragma unroll
    for (int mi = 0; mi < 4; mi++)
        #pragma unroll
        for (int ni = 0; ni < 4; ni++) dacc[mi][ni] = make_float4(0.f, 0.f, 0.f, 0.f);

    #pragma unroll
    for (int s = 0; s < 4; s++) {
        const int fo = tg * 8 + 2 * s;
        uint32_t bhx[4][2], blx[4][2];
        #pragma unroll
        for (int ni = 0; ni < 4; ni++) {
            int c = (wn + ni * 8 + g) * SG_ST + fo;
            bhx[ni][0] = Bh[c]; bhx[ni][1] = Bh[c + 1];
            blx[ni][0] = Bl[c]; blx[ni][1] = Bl[c + 1];
        }
        #pragma unroll
        for (int mi = 0; mi < 4; mi++) {
            int r = (wm + mi * 16 + g) * SG_ST + fo;
            int r8 = r + 8 * SG_ST;
            uint32_t a0 = Ah[r], a1 = Ah[r8], a2 = Ah[r + 1], a3 = Ah[r8 + 1];
            uint32_t l0 = Al[r], l1 = Al[r8], l2 = Al[r + 1], l3 = Al[r8 + 1];
            #pragma unroll
            for (int ni = 0; ni < 4; ni++) {
                mma_bf16s(dacc[mi][ni], a0, a1, a2, a3, bhx[ni][0], bhx[ni][1]);
                mma_bf16s(dacc[mi][ni], a0, a1, a2, a3, blx[ni][0], blx[ni][1]);
                mma_bf16s(dacc[mi][ni], l0, l1, l2, l3, bhx[ni][0], bhx[ni][1]);
            }
        }
    }

    float* Pg = &g_p[((size_t)bh << 20)];
    #pragma unroll
    for (int mi = 0; mi < 4; mi++) {
        int lr0 = s0 + wm + mi * 16 + g;
        #pragma unroll
        for (int ni = 0; ni < 4; ni++) {
            int col = t0 + wn + ni * 8 + 2 * tg;
            float4 d = dacc[mi][ni];
            *(float2*)&Pg[(size_t)lr0 * SS + col]       = make_float2(d.x, d.y);
            *(float2*)&Pg[(size_t)(lr0 + 8) * SS + col] = make_float2(d.z, d.w);
        }
    }
}

// ---------------------------------------------------------------------------
// Kernel 5: softmax over raw scores + fused ave accumulation.
// Per CTA: (b, 16 rows). Loops h=0..7; P written back normalized.
// smem: buf 16x1024 + avebuf 16x1024 = 128KB.
// ---------------------------------------------------------------------------
#define SMA_SMEM (32768 * (int)sizeof(float))

__global__ __launch_bounds__(256, 1) void softmax_ave(float* __restrict__ ave) {
    extern __shared__ float smf[];
    float* buf = smf;            // 16*1024
    float* av  = smf + 16384;    // 16*1024

    const int b = blockIdx.y, s0 = blockIdx.x * 16;
    const int tid = threadIdx.x, w = tid >> 5, lane = tid & 31;

    #pragma unroll
    for (int i = 0; i < 16; i++)
        *(float4*)&av[i * 1024 + tid * 4] = make_float4(0.f, 0.f, 0.f, 0.f);

    for (int h = 0; h < HH; h++) {
        float* Pg = &g_p[(((size_t)(b * HH + h)) << 20) + (size_t)s0 * SS];
        __syncthreads();
        #pragma unroll
        for (int i = 0; i < 16; i++) {
            int off = (i * 256 + tid) * 4;
            *(float4*)&buf[off] = *(const float4*)&Pg[off];
        }
        __syncthreads();

        #pragma unroll
        for (int rr = w * 2; rr < w * 2 + 2; rr++) {
            float* row = &buf[rr * 1024];
            float* arow = &av[rr * 1024];
            float m = -1e30f;
            for (int j = lane; j < 1024; j += 32) m = fmaxf(m, row[j]);
            #pragma unroll
            for (int o = 16; o > 0; o >>= 1)
                m = fmaxf(m, __shfl_xor_sync(0xffffffffu, m, o));
            float s = 0.0f;
            for (int j = lane; j < 1024; j += 32) {
                float e = __expf(row[j] - m);
                row[j] = e;
                s += e;
            }
            #pragma unroll
            for (int o = 16; o > 0; o >>= 1) s += __shfl_xor_sync(0xffffffffu, s, o);
            float inv = 1.0f / s;
            for (int j = lane; j < 1024; j += 32) {
                float p = row[j] * inv;
                row[j] = p;
                arow[j] += 0.125f * p;
            }
        }
        __syncthreads();
        #pragma unroll
        for (int i = 0; i < 16; i++) {
            int off = (i * 256 + tid) * 4;
            *(float4*)&Pg[off] = *(float4*)&buf[off];
        }
    }

    __syncthreads();
    #pragma unroll
    for (int i = 0; i < 16; i++) {
        int off = (i * 256 + tid) * 4;
        int r = off >> 10, c = off & 1023;
        *(float4*)&ave[((size_t)b * SS + s0 + r) * SS + c] = *(float4*)&av[off];
    }
}

// ---------------------------------------------------------------------------
// Kernel 6: PV GEMM via bf16 mma (3 terms). Per CTA: (b,h,128 s-rows),
// output 128x64 into g_o1. A=P (t-contiguous), B=V[d][t] (t-contiguous).
// k-slab 32 t, double buffered, conv-identical layout (stride 17, pos16).
// ---------------------------------------------------------------------------
#define PV_ST 17
#define PV_A_H 0
#define PV_A_L 2176
#define PV_B_H 4352
#define PV_B_L 5440
#define PV_BUF_U32 6528
#define PV_SMEM (2 * PV_BUF_U32 * (int)sizeof(uint32_t))

__global__ __launch_bounds__(256, 2) void pv_mma() {
    extern __shared__ uint32_t smu[];
    const int b = blockIdx.z, h = blockIdx.y, s0 = blockIdx.x * 128;
    const int bh = b * HH + h;
    const float* Pg = &g_p[((size_t)bh << 20)];
    const float* Vg = &g_qkv[2][b][h * HD][0];
    const int tid = threadIdx.x, wid = tid >> 5, lane = tid & 31;
    const int g = lane >> 2, tg = lane & 3;
    const int wm = (wid >> 2) * 64, wn = (wid & 3) * 16;

    float4 dacc[4][2];
    #pragma unroll
    for (int mi = 0; mi < 4; mi++)
        #pragma unroll
        for (int ni = 0; ni < 2; ni++) dacc[mi][ni] = make_float4(0.f, 0.f, 0.f, 0.f);

    const int a_row = tid >> 1, a_kp0 = (tid & 1) * 8;  // P: 16 t each
    const int b_d = tid >> 2, b_t0 = (tid & 3) * 8;     // V: 8 t each

    float4 a_reg[4];
    float4 v_reg[2];

    auto ldg_slab = [&](int c) {
        const float* pr = &Pg[(size_t)(s0 + a_row) * SS + c * 32 + a_kp0 * 2];
        #pragma unroll
        for (int q = 0; q < 4; q++) a_reg[q] = *(const float4*)&pr[q * 4];
        const float* vr = &Vg[(size_t)b_d * SS + c * 32 + b_t0];
        v_reg[0] = *(const float4*)&vr[0];
        v_reg[1] = *(const float4*)&vr[4];
    };
    auto sts_slab = [&](int bf) {
        uint32_t* Ah = smu + bf * PV_BUF_U32 + PV_A_H;
        uint32_t* Al = smu + bf * PV_BUF_U32 + PV_A_L;
        uint32_t* Bh = smu + bf * PV_BUF_U32 + PV_B_H;
        uint32_t* Bl = smu + bf * PV_BUF_U32 + PV_B_L;
        #pragma unroll
        for (int q = 0; q < 4; q++) {
            float vv[4] = {a_reg[q].x, a_reg[q].y, a_reg[q].z, a_reg[q].w};
            #pragma unroll
            for (int p = 0; p < 2; p++) {
                int kp = a_kp0 + q * 2 + p;
                uint32_t ph, pl;
                bsplit2(vv[2 * p], vv[2 * p + 1], ph, pl);
                Ah[a_row * PV_ST + pos16(kp)] = ph;
                Al[a_row * PV_ST + pos16(kp)] = pl;
            }
        }
        float vv[8] = {v_reg[0].x, v_reg[0].y, v_reg[0].z, v_reg[0].w,
                       v_reg[1].x, v_reg[1].y, v_reg[1].z, v_reg[1].w};
        #pragma unroll
        for (int p = 0; p < 4; p++) {
            int kp = (b_t0 >> 1) + p;
            uint32_t ph, pl;
            bsplit2(vv[2 * p], vv[2 * p + 1], ph, pl);
            Bh[b_d * PV_ST + pos16(kp)] = ph;
            Bl[b_d * PV_ST + pos16(kp)] = pl;
        }
    };

    ldg_slab(0);
    sts_slab(0);
    __syncthreads();

    for (int c = 0; c < 32; c++) {
        const int bf = c & 1;
        const bool have = (c + 1) < 32;
        if (have) ldg_slab(c + 1);

        const uint32_t* Ah = smu + bf * PV_BUF_U32 + PV_A_H;
        const uint32_t* Al = smu + bf * PV_BUF_U32 + PV_A_L;
        const uint32_t* Bh = smu + bf * PV_BUF_U32 + PV_B_H;
        const uint32_t* Bl = smu + bf * PV_BUF_U32 + PV_B_L;

        #pragma unroll
        for (int s = 0; s < 2; s++) {
            const int fo = tg * 4 + 2 * s;
            uint32_t bhx[2][2], blx[2][2];
            #pragma unroll
            for (int ni = 0; ni < 2; ni++) {
                int cidx = (wn + ni * 8 + g) * PV_ST + fo;
                bhx[ni][0] = Bh[cidx]; bhx[ni][1] = Bh[cidx + 1];
                blx[ni][0] = Bl[cidx]; blx[ni][1] = Bl[cidx + 1];
            }
            #pragma unroll
            for (int mi = 0; mi < 4; mi++) {
                int r = (wm + mi * 16 + g) * PV_ST + fo;
                int r8 = r + 8 * PV_ST;
                uint32_t a0 = Ah[r], a1 = Ah[r8], a2 = Ah[r + 1], a3 = Ah[r8 + 1];
                uint32_t l0 = Al[r], l1 = Al[r8], l2 = Al[r + 1], l3 = Al[r8 + 1];
                #pragma unroll
                for (int ni = 0; ni < 2; ni++) {
                    mma_bf16s(dacc[mi][ni], a0, a1, a2, a3, bhx[ni][0], bhx[ni][1]);
                    mma_bf16s(dacc[mi][ni], a0, a1, a2, a3, blx[ni][0], blx[ni][1]);
                    mma_bf16s(dacc[mi][ni], l0, l1, l2, l3, bhx[ni][0], bhx[ni][1]);
                }
            }
        }

        if (have) sts_slab(bf ^ 1);
        __syncthreads();
    }

    #pragma unroll
    for (int mi = 0; mi < 4; mi++) {
        int lr0 = s0 + wm + mi * 16 + g;
        #pragma unroll
        for (int ni = 0; ni < 2; ni++) {
            int col = h * HD + wn + ni * 8 + 2 * tg;
            float4 d = dacc[mi][ni];
            *(float2*)&g_o1[b][lr0][col]     = make_float2(d.x, d.y);
            *(float2*)&g_o1[b][lr0 + 8][col] = make_float2(d.z, d.w);
        }
    }
}

// ---------------------------------------------------------------------------
// Kernel 7: output projection: out = O1 @ Wo^T + bo  (double-buffered f32x2)
// ---------------------------------------------------------------------------
__global__ __launch_bounds__(256) void proj_kernel(const float* __restrict__ Wo,
                                                   const float* __restrict__ bo,
                                                   float* __restrict__ out) {
    __shared__ float As[2][8][128];
    __shared__ float Bs[2][8][128];
    const int m0 = blockIdx.x * 128, n0 = blockIdx.y * 128;
    const float* A = &g_o1[0][0][0];
    const int tid = threadIdx.x, tx = tid & 15, ty = tid >> 4;
    const int li = tid >> 1, lj = (tid & 1) * 4;

    ull acc[8][4];
    #pragma unroll
    for (int i = 0; i < 8; i++)
        #pragma unroll
        for (int p = 0; p < 4; p++) acc[i][p] = 0ULL;

    float4 avr, bvr;
    {
        avr = *(const float4*)&A[(size_t)(m0 + li) * DD + lj];
        bvr = *(const float4*)&Wo[(size_t)(n0 + li) * DD + lj];
        As[0][lj + 0][li] = avr.x; As[0][lj + 1][li] = avr.y;
        As[0][lj + 2][li] = avr.z; As[0][lj + 3][li] = avr.w;
        Bs[0][lj + 0][li] = bvr.x; Bs[0][lj + 1][li] = bvr.y;
        Bs[0][lj + 2][li] = bvr.z; Bs[0][lj + 3][li] = bvr.w;
    }
    __syncthreads();

    int cur = 0;
    for (int k0 = 0; k0 < DD; k0 += 8) {
        bool hn = (k0 + 8) < DD;
        if (hn) {
            avr = *(const float4*)&A[(size_t)(m0 + li) * DD + k0 + 8 + lj];
            bvr = *(const float4*)&Wo[(size_t)(n0 + li) * DD + k0 + 8 + lj];
        }

        #pragma unroll
        for (int j = 0; j < 8; j++) {
            float4 a0 = *(float4*)&As[cur][j][ty * 8];
            float4 a1 = *(float4*)&As[cur][j][ty * 8 + 4];
            ull b2[4];
            #pragma unroll
            for (int p = 0; p < 4; p++) b2[p] = *(ull*)&Bs[cur][j][tx * 8 + 2 * p];
            float avv[8] = {a0.x, a0.y, a0.z, a0.w, a1.x, a1.y, a1.z, a1.w};
            #pragma unroll
            for (int i = 0; i < 8; i++) {
                ull ad = f2dup(avv[i]);
                #pragma unroll
                for (int p = 0; p < 4; p++) acc[i][p] = f2fma(ad, b2[p], acc[i][p]);
            }
        }

        if (hn) {
            int nb = cur ^ 1;
            As[nb][lj + 0][li] = avr.x; As[nb][lj + 1][li] = avr.y;
            As[nb][lj + 2][li] = avr.z; As[nb][lj + 3][li] = avr.w;
            Bs[nb][lj + 0][li] = bvr.x; Bs[nb][lj + 1][li] = bvr.y;
            Bs[nb][lj + 2][li] = bvr.z; Bs[nb][lj + 3][li] = bvr.w;
        }
        __syncthreads();
        cur ^= 1;
    }

    #pragma unroll
    for (int i = 0; i < 8; i++) {
        int m = m0 + ty * 8 + i;
        #pragma unroll
        for (int p = 0; p < 4; p++) {
            ull bb = *(const ull*)&bo[n0 + tx * 8 + 2 * p];
            ull r = f2add(acc[i][p], bb);
            *(ull*)&out[(size_t)m * DD + n0 + tx * 8 + 2 * p] = r;
        }
    }
}

// ---------------------------------------------------------------------------
extern "C" void kernel_launch(void* const* d_in, const int* in_sizes, int n_in,
                              void* d_out, int out_size) {
    const float* query = (const float*)d_in[0];
    const float* key_t = (const float*)d_in[1];
    const float* value = (const float*)d_in[2];
    const float* Wq    = (const float*)d_in[3];
    const float* bq    = (const float*)d_in[4];
    const float* Wk    = (const float*)d_in[5];
    const float* bk    = (const float*)d_in[6];
    const float* Wv    = (const float*)d_in[7];
    const float* bv    = (const float*)d_in[8];
    const float* Wo    = (const float*)d_in[9];
    const float* bo    = (const float*)d_in[10];

    float* out = (float*)d_out;
    float* ave = out + (size_t)BB * SS * DD;

    cudaFuncSetAttribute(conv_mma, cudaFuncAttributeMaxDynamicSharedMemorySize, CV_SMEM);
    cudaFuncSetAttribute(scores_gemm, cudaFuncAttributeMaxDynamicSharedMemorySize, SG_SMEM);
    cudaFuncSetAttribute(softmax_ave, cudaFuncAttributeMaxDynamicSharedMemorySize, SMA_SMEM);
    cudaFuncSetAttribute(pv_mma, cudaFuncAttributeMaxDynamicSharedMemorySize, PV_SMEM);

    transpose_kernel<<<dim3(SS / 32, DD / 32, 3 * BB), dim3(32, 8)>>>(query, key_t, value);
    conv_mma<<<dim3(DD / 128, SS / 128, 3 * BB), 256, CV_SMEM>>>(Wq, bq, Wk, bk, Wv, bv);
    qkprep_kernel<<<dim3(SS / 32, DD / 32, 2 * BB), dim3(32, 8)>>>();
    scores_gemm<<<dim3(64, HH, BB), 256, SG_SMEM>>>();
    softmax_ave<<<dim3(SS / 16, BB), 256, SMA_SMEM>>>(ave);
    pv_mma<<<dim3(SS / 128, HH, BB), 256, PV_SMEM>>>();
    proj_kernel<<<dim3((BB * SS) / 128, DD / 128), 256>>>(Wo, bo, out);
}

// round 10
// speedup vs baseline: 1.4936x; 1.0085x over previous
#include <cuda_runtime.h>
#include <cuda_bf16.h>
#include <cstdint>

// ---------------------------------------------------------------------------
// ConvMultiheadAttention: B=8, S=1024, D=512, H=8, hd=64, KERNEL=3
// out  = [8,1024,512]  ; ave = [8,1024,1024]
// ---------------------------------------------------------------------------

#define BB 8
#define SS 1024
#define DD 512
#define HH 8
#define HD 64

typedef unsigned long long ull;

// ----- f32x2 helpers --------------------------------------------------------
__device__ __forceinline__ ull f2fma(ull a, ull b, ull c) {
    ull d; asm("fma.rn.f32x2 %0, %1, %2, %3;" : "=l"(d) : "l"(a), "l"(b), "l"(c)); return d;
}
__device__ __forceinline__ ull f2dup(float x) {
    ull d; asm("mov.b64 %0, {%1, %1};" : "=l"(d) : "f"(x)); return d;
}
__device__ __forceinline__ ull f2add(ull a, ull b) {
    ull d; asm("add.rn.f32x2 %0, %1, %2;" : "=l"(d) : "l"(a), "l"(b)); return d;
}

// ----- bf16 split helpers ----------------------------------------------------
__device__ __forceinline__ void bsplit2(float u, float v, uint32_t& ph, uint32_t& pl) {
    __nv_bfloat16 hu = __float2bfloat16_rn(u);
    __nv_bfloat16 hv = __float2bfloat16_rn(v);
    __nv_bfloat16 lu = __float2bfloat16_rn(u - __bfloat162float(hu));
    __nv_bfloat16 lv = __float2bfloat16_rn(v - __bfloat162float(hv));
    ph = (uint32_t)__bfloat16_as_ushort(hu) | ((uint32_t)__bfloat16_as_ushort(hv) << 16);
    pl = (uint32_t)__bfloat16_as_ushort(lu) | ((uint32_t)__bfloat16_as_ushort(lv) << 16);
}
__device__ __forceinline__ void mma_bf16s(float4& d, uint32_t a0, uint32_t a1,
                                          uint32_t a2, uint32_t a3,
                                          uint32_t b0, uint32_t b1) {
    asm("mma.sync.aligned.m16n8k16.row.col.f32.bf16.bf16.f32 "
        "{%0,%1,%2,%3}, {%4,%5,%6,%7}, {%8,%9}, {%0,%1,%2,%3};"
        : "+f"(d.x), "+f"(d.y), "+f"(d.z), "+f"(d.w)
        : "r"(a0), "r"(a1), "r"(a2), "r"(a3), "r"(b0), "r"(b1));
}
// kpair position permutations (fragment (tg, k16-step s) reads pos fo, fo+1)
__device__ __forceinline__ int pos16(int kp) { return (kp & 3) * 4 + (kp >> 2); }
__device__ __forceinline__ int pos32(int kp) {
    return (kp & 3) * 8 + 2 * (kp >> 3) + ((kp >> 2) & 1);
}

// ----- scratch (static device globals) --------------------------------------
__device__ float g_qkv[3][BB][DD][SS];       // conv outputs Q,K,V [B,D,S]
__device__ uint32_t g_xh[3][BB][SS][256];    // inputs split hi, ci-kpair packed
__device__ uint32_t g_xl[3][BB][SS][256];    // inputs split lo
__device__ uint32_t g_wh[3][3][DD][256];     // weights split hi, per tap
__device__ uint32_t g_wl[3][3][DD][256];     // weights split lo
__device__ uint32_t g_sqh[BB * HH][SS][32];  // Q/64 split hi (pos32 packed)
__device__ uint32_t g_sql[BB * HH][SS][32];
__device__ uint32_t g_skh[BB * HH][SS][32];  // K split hi
__device__ uint32_t g_skl[BB * HH][SS][32];
__device__ float g_p[(size_t)BB * HH * SS * SS]; // raw scores -> probs
__device__ float g_o1[BB][SS][DD];           // pre-projection output

// ---------------------------------------------------------------------------
// Kernel 1: xprep — split inputs [B,S,D] into kpair-packed bf16 hi/lo
// (pos16 prebaked within each 16-kpair group). No transpose needed.
// ---------------------------------------------------------------------------
__global__ void xprep_kernel(const float* __restrict__ q,
                             const float* __restrict__ k,
                             const float* __restrict__ v) {
    const int tn = blockIdx.z, b = blockIdx.y, s0 = blockIdx.x * 128;
    const float* src = (tn == 0) ? q : (tn == 1) ? k : v;
    const int kp = threadIdx.x;             // 0..255
    const int idx = (kp & ~15) | pos16(kp & 15);
    for (int i = 0; i < 128; i++) {
        int s = s0 + i;
        float2 uv = *(const float2*)&src[((size_t)b * SS + s) * DD + 2 * kp];
        uint32_t ph, pl;
        bsplit2(uv.x, uv.y, ph, pl);
        g_xh[tn][b][s][idx] = ph;
        g_xl[tn][b][s][idx] = pl;
    }
}

// ---------------------------------------------------------------------------
// Kernel 2: wprep — split weights per tap into kpair-packed bf16 hi/lo.
// W[co][ci][tap] -> g_wh[tn][tap][co][packed ci-kpair]
// ---------------------------------------------------------------------------
__global__ void wprep_kernel(const float* __restrict__ Wq,
                             const float* __restrict__ Wk,
                             const float* __restrict__ Wv) {
    const int tn = blockIdx.y;
    const float* W = (tn == 0) ? Wq : (tn == 1) ? Wk : Wv;
    const int KER = (tn == 2) ? 1 : 3;
    const int Kdim = DD * KER;
    const int co0 = blockIdx.x * 64;
    const int kp = threadIdx.x;              // 0..255 (ci pair)
    const int idx = (kp & ~15) | pos16(kp & 15);
    for (int tap = 0; tap < KER; tap++)
        for (int i = 0; i < 64; i++) {
            int co = co0 + i;
            float u = W[(size_t)co * Kdim + (2 * kp) * KER + tap];
            float vv = W[(size_t)co * Kdim + (2 * kp + 1) * KER + tap];
            uint32_t ph, pl;
            bsplit2(u, vv, ph, pl);
            g_wh[tn][tap][co][idx] = ph;
            g_wl[tn][tap][co][idx] = pl;
        }
}

// ---------------------------------------------------------------------------
// Kernel 3: conv1d as tap-decomposed bf16 MMA GEMM (split, 3 terms).
// C[co][s] = sum_tap sum_ci W_tap[co][ci] * x[ci][s+tap-pad].
// Staging = pure u32 copies from prepped arrays. MMA core identical to R8.
// ---------------------------------------------------------------------------
#define CV_ST 17
#define CV_AH 0
#define CV_AL 2176
#define CV_BH 4352
#define CV_BL 6528
#define CV_BUF_U32 8704
#define CV_SMEM (2 * CV_BUF_U32 * (int)sizeof(uint32_t))

__global__ __launch_bounds__(256)
void conv_mma(const float* __restrict__ bq, const float* __restrict__ bk,
              const float* __restrict__ bv) {
    extern __shared__ uint32_t smu[];
    __shared__ float s_bias[128];

    const int zz = blockIdx.z, tn = zz / BB, b = zz % BB;
    const float* bias = (tn == 0) ? bq : (tn == 1) ? bk : bv;
    const int KER = (tn == 2) ? 1 : 3;
    const int pad = KER >> 1;
    const int NIT = KER * 16;
    float* out = &g_qkv[tn][b][0][0];
    const int m0 = blockIdx.x * 128, n0 = blockIdx.y * 128;
    const int tid = threadIdx.x, wid = tid >> 5, lane = tid & 31;
    const int g = lane >> 2, tg = lane & 3;
    const int wm = (wid >> 2) * 64, wn = (wid & 3) * 32;

    if (tid < 128) s_bias[tid] = bias[m0 + tid];

    float4 dacc[4][4];
    #pragma unroll
    for (int mi = 0; mi < 4; mi++)
        #pragma unroll
        for (int ni = 0; ni < 4; ni++) dacc[mi][ni] = make_float4(0.f, 0.f, 0.f, 0.f);

    const int a_row = tid >> 1, a_half = (tid & 1) * 8;
    const int b_s = tid & 127, b_half = (tid >> 7) * 8;

    uint4 rah0, rah1, ral0, ral1, rbh0, rbh1, rbl0, rbl1;

    auto ldg_slab = [&](int it) {
        int tap = it >> 4, c = it & 15;
        const uint32_t* wh = &g_wh[tn][tap][m0 + a_row][c * 16 + a_half];
        const uint32_t* wl = &g_wl[tn][tap][m0 + a_row][c * 16 + a_half];
        rah0 = *(const uint4*)&wh[0]; rah1 = *(const uint4*)&wh[4];
        ral0 = *(const uint4*)&wl[0]; ral1 = *(const uint4*)&wl[4];
        int s_glob = n0 + b_s + tap - pad;
        if ((unsigned)s_glob < (unsigned)SS) {
            const uint32_t* xh = &g_xh[tn][b][s_glob][c * 16 + b_half];
            const uint32_t* xl = &g_xl[tn][b][s_glob][c * 16 + b_half];
            rbh0 = *(const uint4*)&xh[0]; rbh1 = *(const uint4*)&xh[4];
            rbl0 = *(const uint4*)&xl[0]; rbl1 = *(const uint4*)&xl[4];
        } else {
            rbh0 = make_uint4(0, 0, 0, 0); rbh1 = rbh0;
            rbl0 = rbh0; rbl1 = rbh0;
        }
    };
    auto sts_slab = [&](int bf) {
        uint32_t* Ah = smu + bf * CV_BUF_U32 + CV_AH + a_row * CV_ST + a_half;
        uint32_t* Al = smu + bf * CV_BUF_U32 + CV_AL + a_row * CV_ST + a_half;
        uint32_t* Bh = smu + bf * CV_BUF_U32 + CV_BH + b_s * CV_ST + b_half;
        uint32_t* Bl = smu + bf * CV_BUF_U32 + CV_BL + b_s * CV_ST + b_half;
        Ah[0] = rah0.x; Ah[1] = rah0.y; Ah[2] = rah0.z; Ah[3] = rah0.w;
        Ah[4] = rah1.x; Ah[5] = rah1.y; Ah[6] = rah1.z; Ah[7] = rah1.w;
        Al[0] = ral0.x; Al[1] = ral0.y; Al[2] = ral0.z; Al[3] = ral0.w;
        Al[4] = ral1.x; Al[5] = ral1.y; Al[6] = ral1.z; Al[7] = ral1.w;
        Bh[0] = rbh0.x; Bh[1] = rbh0.y; Bh[2] = rbh0.z; Bh[3] = rbh0.w;
        Bh[4] = rbh1.x; Bh[5] = rbh1.y; Bh[6] = rbh1.z; Bh[7] = rbh1.w;
        Bl[0] = rbl0.x; Bl[1] = rbl0.y; Bl[2] = rbl0.z; Bl[3] = rbl0.w;
        Bl[4] = rbl1.x; Bl[5] = rbl1.y; Bl[6] = rbl1.z; Bl[7] = rbl1.w;
    };

    ldg_slab(0);
    sts_slab(0);
    __syncthreads();

    for (int it = 0; it < NIT; it++) {
        const int bf = it & 1;
        const bool have = (it + 1) < NIT;
        if (have) ldg_slab(it + 1);

        const uint32_t* Ah = smu + bf * CV_BUF_U32 + CV_AH;
        const uint32_t* Al = smu + bf * CV_BUF_U32 + CV_AL;
        const uint32_t* Bh = smu + bf * CV_BUF_U32 + CV_BH;
        const uint32_t* Bl = smu + bf * CV_BUF_U32 + CV_BL;

        #pragma unroll
        for (int s = 0; s < 2; s++) {
            const int fo = tg * 4 + 2 * s;
            uint32_t ahx[4][4], alx[4][4], bhx[4][2], blx[4][2];
            #pragma unroll
            for (int mi = 0; mi < 4; mi++) {
                int r = (wm + mi * 16 + g) * CV_ST + fo;
                int r8 = r + 8 * CV_ST;
                ahx[mi][0] = Ah[r];     ahx[mi][1] = Ah[r8];
                ahx[mi][2] = Ah[r + 1]; ahx[mi][3] = Ah[r8 + 1];
                alx[mi][0] = Al[r];     alx[mi][1] = Al[r8];
                alx[mi][2] = Al[r + 1]; alx[mi][3] = Al[r8 + 1];
            }
            #pragma unroll
            for (int ni = 0; ni < 4; ni++) {
                int cidx = (wn + ni * 8 + g) * CV_ST + fo;
                bhx[ni][0] = Bh[cidx]; bhx[ni][1] = Bh[cidx + 1];
                blx[ni][0] = Bl[cidx]; blx[ni][1] = Bl[cidx + 1];
            }
            #pragma unroll
            for (int mi = 0; mi < 4; mi++)
                #pragma unroll
                for (int ni = 0; ni < 4; ni++) {
                    mma_bf16s(dacc[mi][ni], ahx[mi][0], ahx[mi][1], ahx[mi][2],
                              ahx[mi][3], bhx[ni][0], bhx[ni][1]);
                    mma_bf16s(dacc[mi][ni], ahx[mi][0], ahx[mi][1], ahx[mi][2],
                              ahx[mi][3], blx[ni][0], blx[ni][1]);
                    mma_bf16s(dacc[mi][ni], alx[mi][0], alx[mi][1], alx[mi][2],
                              alx[mi][3], bhx[ni][0], bhx[ni][1]);
                }
        }

        if (have) sts_slab(bf ^ 1);
        __syncthreads();
    }

    #pragma unroll
    for (int mi = 0; mi < 4; mi++) {
        int lr0 = wm + mi * 16 + g;
        float b0 = s_bias[lr0], b1 = s_bias[lr0 + 8];
        #pragma unroll
        for (int ni = 0; ni < 4; ni++) {
            int col = n0 + wn + ni * 8 + 2 * tg;
            float4 d = dacc[mi][ni];
            *(float2*)&out[(size_t)(m0 + lr0) * SS + col]     = make_float2(d.x + b0, d.y + b0);
            *(float2*)&out[(size_t)(m0 + lr0 + 8) * SS + col] = make_float2(d.z + b1, d.w + b1);
        }
    }
}

// ---------------------------------------------------------------------------
// Kernel 4: qkprep — split Q (x 1/64) and K into kpair-packed bf16 hi/lo.
// [B,D,S] -> [bh][s][pos32(kp)] u32.
// ---------------------------------------------------------------------------
__global__ void qkprep_kernel() {
    __shared__ float tile[32][33];
    int zz = blockIdx.z;
    int tn = zz / BB, b = zz % BB;     // tn: 0=Q, 1=K
    const float* src = &g_qkv[tn][b][0][0];
    int s0 = blockIdx.x * 32, d0 = blockIdx.y * 32;
    int tx = threadIdx.x, ty = threadIdx.y;
    #pragma unroll
    for (int i = ty; i < 32; i += 8)
        tile[i][tx] = src[(size_t)(d0 + i) * SS + s0 + tx];
    __syncthreads();

    const float scale = (tn == 0) ? 0.015625f : 1.0f;
    const int h = d0 >> 6;
    const int kp_base = (d0 & 63) >> 1;    // 0 or 16
    const int bh = b * HH + h;
    uint32_t* dh = (tn == 0) ? &g_sqh[bh][0][0] : &g_skh[bh][0][0];
    uint32_t* dl = (tn == 0) ? &g_sql[bh][0][0] : &g_skl[bh][0][0];

    const int kpl = tx & 15;
    const int half = tx >> 4;              // 0: hi array, 1: lo array
    const int pos = pos32(kp_base + kpl);
    #pragma unroll
    for (int i = ty; i < 32; i += 8) {
        float u = tile[2 * kpl][i] * scale;
        float v = tile[2 * kpl + 1][i] * scale;
        uint32_t ph, pl;
        bsplit2(u, v, ph, pl);
        if (half == 0) dh[(size_t)(s0 + i) * 32 + pos] = ph;
        else           dl[(size_t)(s0 + i) * 32 + pos] = pl;
    }
}

// ---------------------------------------------------------------------------
// Kernel 5: scores GEMM via bf16 mma (3 terms). Per CTA: (b,h,128s,128t),
// K=64 single shot. Raw scores (already x 1/64 via Q) -> g_p.
// ---------------------------------------------------------------------------
#define SG_ST 33
#define SG_A_H 0
#define SG_A_L 4224
#define SG_B_H 8448
#define SG_B_L 12672
#define SG_SMEM (16896 * (int)sizeof(uint32_t))

__global__ __launch_bounds__(256, 2) void scores_gemm() {
    extern __shared__ uint32_t smu[];
    const int b = blockIdx.z, h = blockIdx.y;
    const int s0 = (blockIdx.x >> 3) * 128, t0 = (blockIdx.x & 7) * 128;
    const int bh = b * HH + h;
    const int tid = threadIdx.x, wid = tid >> 5, lane = tid & 31;
    const int g = lane >> 2, tg = lane & 3;
    const int wm = (wid >> 2) * 64, wn = (wid & 3) * 32;

    {
        const int row = tid >> 1, c0 = (tid & 1) * 16;
        const uint32_t* sa_h = &g_sqh[bh][s0 + row][c0];
        const uint32_t* sa_l = &g_sql[bh][s0 + row][c0];
        const uint32_t* sb_h = &g_skh[bh][t0 + row][c0];
        const uint32_t* sb_l = &g_skl[bh][t0 + row][c0];
        uint32_t* Ah = smu + SG_A_H + row * SG_ST + c0;
        uint32_t* Al = smu + SG_A_L + row * SG_ST + c0;
        uint32_t* Bh = smu + SG_B_H + row * SG_ST + c0;
        uint32_t* Bl = smu + SG_B_L + row * SG_ST + c0;
        #pragma unroll
        for (int i = 0; i < 4; i++) {
            uint4 va = *(const uint4*)&sa_h[4 * i];
            uint4 vb = *(const uint4*)&sa_l[4 * i];
            uint4 vc = *(const uint4*)&sb_h[4 * i];
            uint4 vd = *(const uint4*)&sb_l[4 * i];
            Ah[4 * i] = va.x; Ah[4 * i + 1] = va.y; Ah[4 * i + 2] = va.z; Ah[4 * i + 3] = va.w;
            Al[4 * i] = vb.x; Al[4 * i + 1] = vb.y; Al[4 * i + 2] = vb.z; Al[4 * i + 3] = vb.w;
            Bh[4 * i] = vc.x; Bh[4 * i + 1] = vc.y; Bh[4 * i + 2] = vc.z; Bh[4 * i + 3] = vc.w;
            Bl[4 * i] = vd.x; Bl[4 * i + 1] = vd.y; Bl[4 * i + 2] = vd.z; Bl[4 * i + 3] = vd.w;
        }
    }
    __syncthreads();

    const uint32_t* Ah = smu + SG_A_H;
    const uint32_t* Al = smu + SG_A_L;
    const uint32_t* Bh = smu + SG_B_H;
    const uint32_t* Bl = smu + SG_B_L;

    float4 dacc[4][4];
    #pragma unroll
    for (int mi = 0; mi < 4; mi++)
        #pragma unroll
        for (int ni = 0; ni < 4; ni++) dacc[mi][ni] = make_float4(0.f, 0.f, 0.f, 0.f);

    #pragma unroll
    for (int s = 0; s < 4; s++) {
        const int fo = tg * 8 + 2 * s;
        uint32_t bhx[4][2], blx[4][2];
        #pragma unroll
        for (int ni = 0; ni < 4; ni++) {
            int c = (wn + ni * 8 + g) * SG_ST + fo;
            bhx[ni][0] = Bh[c]; bhx[ni][1] = Bh[c + 1];
            blx[ni][0] = Bl[c]; blx[ni][1] = Bl[c + 1];
        }
        #pragma unroll
        for (int mi = 0; mi < 4; mi++) {
            int r = (wm + mi * 16 + g) * SG_ST + fo;
            int r8 = r + 8 * SG_ST;
            uint32_t a0 = Ah[r], a1 = Ah[r8], a2 = Ah[r + 1], a3 = Ah[r8 + 1];
            uint32_t l0 = Al[r], l1 = Al[r8], l2 = Al[r + 1], l3 = Al[r8 + 1];
            #pragma unroll
            for (int ni = 0; ni < 4; ni++) {
                mma_bf16s(dacc[mi][ni], a0, a1, a2, a3, bhx[ni][0], bhx[ni][1]);
                mma_bf16s(dacc[mi][ni], a0, a1, a2, a3, blx[ni][0], blx[ni][1]);
                mma_bf16s(dacc[mi][ni], l0, l1, l2, l3, bhx[ni][0], bhx[ni][1]);
            }
        }
    }

    float* Pg = &g_p[((size_t)bh << 20)];
    #pragma unroll
    for (int mi = 0; mi < 4; mi++) {
        int lr0 = s0 + wm + mi * 16 + g;
        #pragma unroll
        for (int ni = 0; ni < 4; ni++) {
            int col = t0 + wn + ni * 8 + 2 * tg;
            float4 d = dacc[mi][ni];
            *(float2*)&Pg[(size_t)lr0 * SS + col]       = make_float2(d.x, d.y);
            *(float2*)&Pg[(size_t)(lr0 + 8) * SS + col] = make_float2(d.z, d.w);
        }
    }
}

// ---------------------------------------------------------------------------
// Kernel 6: softmax over raw scores + fused ave accumulation.
// ---------------------------------------------------------------------------
#define SMA_SMEM (32768 * (int)sizeof(float))

__global__ __launch_bounds__(256, 1) void softmax_ave(float* __restrict__ ave) {
    extern __shared__ float smf[];
    float* buf = smf;            // 16*1024
    float* av  = smf + 16384;    // 16*1024

    const int b = blockIdx.y, s0 = blockIdx.x * 16;
    const int tid = threadIdx.x, w = tid >> 5, lane = tid & 31;

    #pragma unroll
    for (int i = 0; i < 16; i++)
        *(float4*)&av[i * 1024 + tid * 4] = make_float4(0.f, 0.f, 0.f, 0.f);

    for (int h = 0; h < HH; h++) {
        float* Pg = &g_p[(((size_t)(b * HH + h)) << 20) + (size_t)s0 * SS];
        __syncthreads();
        #pragma unroll
        for (int i = 0; i < 16; i++) {
            int off = (i * 256 + tid) * 4;
            *(float4*)&buf[off] = *(const float4*)&Pg[off];
        }
        __syncthreads();

        #pragma unroll
        for (int rr = w * 2; rr < w * 2 + 2; rr++) {
            float* row = &buf[rr * 1024];
            float* arow = &av[rr * 1024];
            float m = -1e30f;
            for (int j = lane; j < 1024; j += 32) m = fmaxf(m, row[j]);
            #pragma unroll
            for (int o = 16; o > 0; o >>= 1)
                m = fmaxf(m, __shfl_xor_sync(0xffffffffu, m, o));
            float s = 0.0f;
            for (int j = lane; j < 1024; j += 32) {
                float e = __expf(row[j] - m);
                row[j] = e;
                s += e;
            }
            #pragma unroll
            for (int o = 16; o > 0; o >>= 1) s += __shfl_xor_sync(0xffffffffu, s, o);
            float inv = 1.0f / s;
            for (int j = lane; j < 1024; j += 32) {
                float p = row[j] * inv;
                row[j] = p;
                arow[j] += 0.125f * p;
            }
        }
        __syncthreads();
        #pragma unroll
        for (int i = 0; i < 16; i++) {
            int off = (i * 256 + tid) * 4;
            *(float4*)&Pg[off] = *(float4*)&buf[off];
        }
    }

    __syncthreads();
    #pragma unroll
    for (int i = 0; i < 16; i++) {
        int off = (i * 256 + tid) * 4;
        int r = off >> 10, c = off & 1023;
        *(float4*)&ave[((size_t)b * SS + s0 + r) * SS + c] = *(float4*)&av[off];
    }
}

// ---------------------------------------------------------------------------
// Kernel 7: PV GEMM via bf16 mma (3 terms). (unchanged from R9)
// ---------------------------------------------------------------------------
#define PV_ST 17
#define PV_A_H 0
#define PV_A_L 2176
#define PV_B_H 4352
#define PV_B_L 5440
#define PV_BUF_U32 6528
#define PV_SMEM (2 * PV_BUF_U32 * (int)sizeof(uint32_t))

__global__ __launch_bounds__(256, 2) void pv_mma() {
    extern __shared__ uint32_t smu[];
    const int b = blockIdx.z, h = blockIdx.y, s0 = blockIdx.x * 128;
    const int bh = b * HH + h;
    const float* Pg = &g_p[((size_t)bh << 20)];
    const float* Vg = &g_qkv[2][b][h * HD][0];
    const int tid = threadIdx.x, wid = tid >> 5, lane = tid & 31;
    const int g = lane >> 2, tg = lane & 3;
    const int wm = (wid >> 2) * 64, wn = (wid & 3) * 16;

    float4 dacc[4][2];
    #pragma unroll
    for (int mi = 0; mi < 4; mi++)
        #pragma unroll
        for (int ni = 0; ni < 2; ni++) dacc[mi][ni] = make_float4(0.f, 0.f, 0.f, 0.f);

    const int a_row = tid >> 1, a_kp0 = (tid & 1) * 8;
    const int b_d = tid >> 2, b_t0 = (tid & 3) * 8;

    float4 a_reg[4];
    float4 v_reg[2];

    auto ldg_slab = [&](int c) {
        const float* pr = &Pg[(size_t)(s0 + a_row) * SS + c * 32 + a_kp0 * 2];
        #pragma unroll
        for (int q = 0; q < 4; q++) a_reg[q] = *(const float4*)&pr[q * 4];
        const float* vr = &Vg[(size_t)b_d * SS + c * 32 + b_t0];
        v_reg[0] = *(const float4*)&vr[0];
        v_reg[1] = *(const float4*)&vr[4];
    };
    auto sts_slab = [&](int bf) {
        uint32_t* Ah = smu + bf * PV_BUF_U32 + PV_A_H;
        uint32_t* Al = smu + bf * PV_BUF_U32 + PV_A_L;
        uint32_t* Bh = smu + bf * PV_BUF_U32 + PV_B_H;
        uint32_t* Bl = smu + bf * PV_BUF_U32 + PV_B_L;
        #pragma unroll
        for (int q = 0; q < 4; q++) {
            float vv[4] = {a_reg[q].x, a_reg[q].y, a_reg[q].z, a_reg[q].w};
            #pragma unroll
            for (int p = 0; p < 2; p++) {
                int kp = a_kp0 + q * 2 + p;
                uint32_t ph, pl;
                bsplit2(vv[2 * p], vv[2 * p + 1], ph, pl);
                Ah[a_row * PV_ST + pos16(kp)] = ph;
                Al[a_row * PV_ST + pos16(kp)] = pl;
            }
        }
        float vv[8] = {v_reg[0].x, v_reg[0].y, v_reg[0].z, v_reg[0].w,
                       v_reg[1].x, v_reg[1].y, v_reg[1].z, v_reg[1].w};
        #pragma unroll
        for (int p = 0; p < 4; p++) {
            int kp = (b_t0 >> 1) + p;
            uint32_t ph, pl;
            bsplit2(vv[2 * p], vv[2 * p + 1], ph, pl);
            Bh[b_d * PV_ST + pos16(kp)] = ph;
            Bl[b_d * PV_ST + pos16(kp)] = pl;
        }
    };

    ldg_slab(0);
    sts_slab(0);
    __syncthreads();

    for (int c = 0; c < 32; c++) {
        const int bf = c & 1;
        const bool have = (c + 1) < 32;
        if (have) ldg_slab(c + 1);

        const uint32_t* Ah = smu + bf * PV_BUF_U32 + PV_A_H;
        const uint32_t* Al = smu + bf * PV_BUF_U32 + PV_A_L;
        const uint32_t* Bh = smu + bf * PV_BUF_U32 + PV_B_H;
        const uint32_t* Bl = smu + bf * PV_BUF_U32 + PV_B_L;

        #pragma unroll
        for (int s = 0; s < 2; s++) {
            const int fo = tg * 4 + 2 * s;
            uint32_t bhx[2][2], blx[2][2];
            #pragma unroll
            for (int ni = 0; ni < 2; ni++) {
                int cidx = (wn + ni * 8 + g) * PV_ST + fo;
                bhx[ni][0] = Bh[cidx]; bhx[ni][1] = Bh[cidx + 1];
                blx[ni][0] = Bl[cidx]; blx[ni][1] = Bl[cidx + 1];
            }
            #pragma unroll
            for (int mi = 0; mi < 4; mi++) {
                int r = (wm + mi * 16 + g) * PV_ST + fo;
                int r8 = r + 8 * PV_ST;
                uint32_t a0 = Ah[r], a1 = Ah[r8], a2 = Ah[r + 1], a3 = Ah[r8 + 1];
                uint32_t l0 = Al[r], l1 = Al[r8], l2 = Al[r + 1], l3 = Al[r8 + 1];
                #pragma unroll
                for (int ni = 0; ni < 2; ni++) {
                    mma_bf16s(dacc[mi][ni], a0, a1, a2, a3, bhx[ni][0], bhx[ni][1]);
                    mma_bf16s(dacc[mi][ni], a0, a1, a2, a3, blx[ni][0], blx[ni][1]);
                    mma_bf16s(dacc[mi][ni], l0, l1, l2, l3, bhx[ni][0], bhx[ni][1]);
                }
            }
        }

        if (have) sts_slab(bf ^ 1);
        __syncthreads();
    }

    #pragma unroll
    for (int mi = 0; mi < 4; mi++) {
        int lr0 = s0 + wm + mi * 16 + g;
        #pragma unroll
        for (int ni = 0; ni < 2; ni++) {
            int col = h * HD + wn + ni * 8 + 2 * tg;
            float4 d = dacc[mi][ni];
            *(float2*)&g_o1[b][lr0][col]     = make_float2(d.x, d.y);
            *(float2*)&g_o1[b][lr0 + 8][col] = make_float2(d.z, d.w);
        }
    }
}

// ---------------------------------------------------------------------------
// Kernel 8: output projection: out = O1 @ Wo^T + bo  (double-buffered f32x2)
// ---------------------------------------------------------------------------
__global__ __launch_bounds__(256) void proj_kernel(const float* __restrict__ Wo,
                                                   const float* __restrict__ bo,
                                                   float* __restrict__ out) {
    __shared__ float As[2][8][128];
    __shared__ float Bs[2][8][128];
    const int m0 = blockIdx.x * 128, n0 = blockIdx.y * 128;
    const float* A = &g_o1[0][0][0];
    const int tid = threadIdx.x, tx = tid & 15, ty = tid >> 4;
    const int li = tid >> 1, lj = (tid & 1) * 4;

    ull acc[8][4];
    #pragma unroll
    for (int i = 0; i < 8; i++)
        #pragma unroll
        for (int p = 0; p < 4; p++) acc[i][p] = 0ULL;

    float4 avr, bvr;
    {
        avr = *(const float4*)&A[(size_t)(m0 + li) * DD + lj];
        bvr = *(const float4*)&Wo[(size_t)(n0 + li) * DD + lj];
        As[0][lj + 0][li] = avr.x; As[0][lj + 1][li] = avr.y;
        As[0][lj + 2][li] = avr.z; As[0][lj + 3][li] = avr.w;
        Bs[0][lj + 0][li] = bvr.x; Bs[0][lj + 1][li] = bvr.y;
        Bs[0][lj + 2][li] = bvr.z; Bs[0][lj + 3][li] = bvr.w;
    }
    __syncthreads();

    int cur = 0;
    for (int k0 = 0; k0 < DD; k0 += 8) {
        bool hn = (k0 + 8) < DD;
        if (hn) {
            avr = *(const float4*)&A[(size_t)(m0 + li) * DD + k0 + 8 + lj];
            bvr = *(const float4*)&Wo[(size_t)(n0 + li) * DD + k0 + 8 + lj];
        }

        #pragma unroll
        for (int j = 0; j < 8; j++) {
            float4 a0 = *(float4*)&As[cur][j][ty * 8];
            float4 a1 = *(float4*)&As[cur][j][ty * 8 + 4];
            ull b2[4];
            #pragma unroll
            for (int p = 0; p < 4; p++) b2[p] = *(ull*)&Bs[cur][j][tx * 8 + 2 * p];
            float avv[8] = {a0.x, a0.y, a0.z, a0.w, a1.x, a1.y, a1.z, a1.w};
            #pragma unroll
            for (int i = 0; i < 8; i++) {
                ull ad = f2dup(avv[i]);
                #pragma unroll
                for (int p = 0; p < 4; p++) acc[i][p] = f2fma(ad, b2[p], acc[i][p]);
            }
        }

        if (hn) {
            int nb = cur ^ 1;
            As[nb][lj + 0][li] = avr.x; As[nb][lj + 1][li] = avr.y;
            As[nb][lj + 2][li] = avr.z; As[nb][lj + 3][li] = avr.w;
            Bs[nb][lj + 0][li] = bvr.x; Bs[nb][lj + 1][li] = bvr.y;
            Bs[nb][lj + 2][li] = bvr.z; Bs[nb][lj + 3][li] = bvr.w;
        }
        __syncthreads();
        cur ^= 1;
    }

    #pragma unroll
    for (int i = 0; i < 8; i++) {
        int m = m0 + ty * 8 + i;
        #pragma unroll
        for (int p = 0; p < 4; p++) {
            ull bb = *(const ull*)&bo[n0 + tx * 8 + 2 * p];
            ull r = f2add(acc[i][p], bb);
            *(ull*)&out[(size_t)m * DD + n0 + tx * 8 + 2 * p] = r;
        }
    }
}

// ---------------------------------------------------------------------------
extern "C" void kernel_launch(void* const* d_in, const int* in_sizes, int n_in,
                              void* d_out, int out_size) {
    const float* query = (const float*)d_in[0];
    const float* key_t = (const float*)d_in[1];
    const float* value = (const float*)d_in[2];
    const float* Wq    = (const float*)d_in[3];
    const float* bq    = (const float*)d_in[4];
    const float* Wk    = (const float*)d_in[5];
    const float* bk    = (const float*)d_in[6];
    const float* Wv    = (const float*)d_in[7];
    const float* bv    = (const float*)d_in[8];
    const float* Wo    = (const float*)d_in[9];
    const float* bo    = (const float*)d_in[10];

    float* out = (float*)d_out;
    float* ave = out + (size_t)BB * SS * DD;

    cudaFuncSetAttribute(conv_mma, cudaFuncAttributeMaxDynamicSharedMemorySize, CV_SMEM);
    cudaFuncSetAttribute(scores_gemm, cudaFuncAttributeMaxDynamicSharedMemorySize, SG_SMEM);
    cudaFuncSetAttribute(softmax_ave, cudaFuncAttributeMaxDynamicSharedMemorySize, SMA_SMEM);
    cudaFuncSetAttribute(pv_mma, cudaFuncAttributeMaxDynamicSharedMemorySize, PV_SMEM);

    xprep_kernel<<<dim3(SS / 128, BB, 3), 256>>>(query, key_t, value);
    wprep_kernel<<<dim3(DD / 64, 3), 256>>>(Wq, Wk, Wv);
    conv_mma<<<dim3(DD / 128, SS / 128, 3 * BB), 256, CV_SMEM>>>(bq, bk, bv);
    qkprep_kernel<<<dim3(SS / 32, DD / 32, 2 * BB), dim3(32, 8)>>>();
    scores_gemm<<<dim3(64, HH, BB), 256, SG_SMEM>>>();
    softmax_ave<<<dim3(SS / 16, BB), 256, SMA_SMEM>>>(ave);
    pv_mma<<<dim3(SS / 128, HH, BB), 256, PV_SMEM>>>();
    proj_kernel<<<dim3((BB * SS) / 128, DD / 128), 256>>>(Wo, bo, out);
}

// round 11
// speedup vs baseline: 1.6364x; 1.0957x over previous
#include <cuda_runtime.h>
#include <cuda_bf16.h>
#include <cstdint>

// ---------------------------------------------------------------------------
// ConvMultiheadAttention: B=8, S=1024, D=512, H=8, hd=64, KERNEL=3
// out  = [8,1024,512]  ; ave = [8,1024,1024]
// ---------------------------------------------------------------------------

#define BB 8
#define SS 1024
#define DD 512
#define HH 8
#define HD 64

typedef unsigned long long ull;

// ----- f32x2 helpers --------------------------------------------------------
__device__ __forceinline__ ull f2fma(ull a, ull b, ull c) {
    ull d; asm("fma.rn.f32x2 %0, %1, %2, %3;" : "=l"(d) : "l"(a), "l"(b), "l"(c)); return d;
}
__device__ __forceinline__ ull f2dup(float x) {
    ull d; asm("mov.b64 %0, {%1, %1};" : "=l"(d) : "f"(x)); return d;
}
__device__ __forceinline__ ull f2add(ull a, ull b) {
    ull d; asm("add.rn.f32x2 %0, %1, %2;" : "=l"(d) : "l"(a), "l"(b)); return d;
}

// ----- bf16 split helpers ----------------------------------------------------
__device__ __forceinline__ void bsplit2(float u, float v, uint32_t& ph, uint32_t& pl) {
    __nv_bfloat16 hu = __float2bfloat16_rn(u);
    __nv_bfloat16 hv = __float2bfloat16_rn(v);
    __nv_bfloat16 lu = __float2bfloat16_rn(u - __bfloat162float(hu));
    __nv_bfloat16 lv = __float2bfloat16_rn(v - __bfloat162float(hv));
    ph = (uint32_t)__bfloat16_as_ushort(hu) | ((uint32_t)__bfloat16_as_ushort(hv) << 16);
    pl = (uint32_t)__bfloat16_as_ushort(lu) | ((uint32_t)__bfloat16_as_ushort(lv) << 16);
}
__device__ __forceinline__ void mma_bf16s(float4& d, uint32_t a0, uint32_t a1,
                                          uint32_t a2, uint32_t a3,
                                          uint32_t b0, uint32_t b1) {
    asm("mma.sync.aligned.m16n8k16.row.col.f32.bf16.bf16.f32 "
        "{%0,%1,%2,%3}, {%4,%5,%6,%7}, {%8,%9}, {%0,%1,%2,%3};"
        : "+f"(d.x), "+f"(d.y), "+f"(d.z), "+f"(d.w)
        : "r"(a0), "r"(a1), "r"(a2), "r"(a3), "r"(b0), "r"(b1));
}
// kpair position permutations (fragment (tg, k16-step s) reads pos fo, fo+1)
__device__ __forceinline__ int pos16(int kp) { return (kp & 3) * 4 + (kp >> 2); }
__device__ __forceinline__ int pos32(int kp) {
    return (kp & 3) * 8 + 2 * (kp >> 3) + ((kp >> 2) & 1);
}

// ----- scratch (static device globals) --------------------------------------
__device__ float g_qkv[3][BB][DD][SS];       // conv outputs Q,K,V [B,D,S]
__device__ uint32_t g_xh[3][BB][SS][256];    // inputs split hi, ci-kpair packed
__device__ uint32_t g_xl[3][BB][SS][256];    // inputs split lo
__device__ uint32_t g_wh[3][3][DD][256];     // weights split hi, per tap
__device__ uint32_t g_wl[3][3][DD][256];     // weights split lo
__device__ uint32_t g_sqh[BB * HH][SS][32];  // Q/64 split hi (pos32 packed)
__device__ uint32_t g_sql[BB * HH][SS][32];
__device__ uint32_t g_skh[BB * HH][SS][32];  // K split hi
__device__ uint32_t g_skl[BB * HH][SS][32];
__device__ float g_p[(size_t)BB * HH * SS * SS]; // raw scores
__device__ uint32_t g_ph[BB * HH][SS][512];  // probs split hi (pos16 packed)
__device__ uint32_t g_pl[BB * HH][SS][512];  // probs split lo
__device__ uint32_t g_vh[BB * HH][HD][512];  // V split hi (pos16 packed)
__device__ uint32_t g_vl[BB * HH][HD][512];  // V split lo
__device__ float g_o1[BB][SS][DD];           // pre-projection output

// ---------------------------------------------------------------------------
// Kernel 1: xprep — split inputs [B,S,D] into kpair-packed bf16 hi/lo
// ---------------------------------------------------------------------------
__global__ void xprep_kernel(const float* __restrict__ q,
                             const float* __restrict__ k,
                             const float* __restrict__ v) {
    const int tn = blockIdx.z, b = blockIdx.y, s0 = blockIdx.x * 128;
    const float* src = (tn == 0) ? q : (tn == 1) ? k : v;
    const int kp = threadIdx.x;             // 0..255
    const int idx = (kp & ~15) | pos16(kp & 15);
    for (int i = 0; i < 128; i++) {
        int s = s0 + i;
        float2 uv = *(const float2*)&src[((size_t)b * SS + s) * DD + 2 * kp];
        uint32_t ph, pl;
        bsplit2(uv.x, uv.y, ph, pl);
        g_xh[tn][b][s][idx] = ph;
        g_xl[tn][b][s][idx] = pl;
    }
}

// ---------------------------------------------------------------------------
// Kernel 2: wprep — split weights per tap into kpair-packed bf16 hi/lo.
// ---------------------------------------------------------------------------
__global__ void wprep_kernel(const float* __restrict__ Wq,
                             const float* __restrict__ Wk,
                             const float* __restrict__ Wv) {
    const int tn = blockIdx.y;
    const float* W = (tn == 0) ? Wq : (tn == 1) ? Wk : Wv;
    const int KER = (tn == 2) ? 1 : 3;
    const int Kdim = DD * KER;
    const int co0 = blockIdx.x * 64;
    const int kp = threadIdx.x;              // 0..255 (ci pair)
    const int idx = (kp & ~15) | pos16(kp & 15);
    for (int tap = 0; tap < KER; tap++)
        for (int i = 0; i < 64; i++) {
            int co = co0 + i;
            float u = W[(size_t)co * Kdim + (2 * kp) * KER + tap];
            float vv = W[(size_t)co * Kdim + (2 * kp + 1) * KER + tap];
            uint32_t ph, pl;
            bsplit2(u, vv, ph, pl);
            g_wh[tn][tap][co][idx] = ph;
            g_wl[tn][tap][co][idx] = pl;
        }
}

// ---------------------------------------------------------------------------
// Kernel 3: conv1d as tap-decomposed bf16 MMA GEMM (split, 3 terms).
// ---------------------------------------------------------------------------
#define CV_ST 17
#define CV_AH 0
#define CV_AL 2176
#define CV_BH 4352
#define CV_BL 6528
#define CV_BUF_U32 8704
#define CV_SMEM (2 * CV_BUF_U32 * (int)sizeof(uint32_t))

__global__ __launch_bounds__(256)
void conv_mma(const float* __restrict__ bq, const float* __restrict__ bk,
              const float* __restrict__ bv) {
    extern __shared__ uint32_t smu[];
    __shared__ float s_bias[128];

    const int zz = blockIdx.z, tn = zz / BB, b = zz % BB;
    const float* bias = (tn == 0) ? bq : (tn == 1) ? bk : bv;
    const int KER = (tn == 2) ? 1 : 3;
    const int pad = KER >> 1;
    const int NIT = KER * 16;
    float* out = &g_qkv[tn][b][0][0];
    const int m0 = blockIdx.x * 128, n0 = blockIdx.y * 128;
    const int tid = threadIdx.x, wid = tid >> 5, lane = tid & 31;
    const int g = lane >> 2, tg = lane & 3;
    const int wm = (wid >> 2) * 64, wn = (wid & 3) * 32;

    if (tid < 128) s_bias[tid] = bias[m0 + tid];

    float4 dacc[4][4];
    #pragma unroll
    for (int mi = 0; mi < 4; mi++)
        #pragma unroll
        for (int ni = 0; ni < 4; ni++) dacc[mi][ni] = make_float4(0.f, 0.f, 0.f, 0.f);

    const int a_row = tid >> 1, a_half = (tid & 1) * 8;
    const int b_s = tid & 127, b_half = (tid >> 7) * 8;

    uint4 rah0, rah1, ral0, ral1, rbh0, rbh1, rbl0, rbl1;

    auto ldg_slab = [&](int it) {
        int tap = it >> 4, c = it & 15;
        const uint32_t* wh = &g_wh[tn][tap][m0 + a_row][c * 16 + a_half];
        const uint32_t* wl = &g_wl[tn][tap][m0 + a_row][c * 16 + a_half];
        rah0 = *(const uint4*)&wh[0]; rah1 = *(const uint4*)&wh[4];
        ral0 = *(const uint4*)&wl[0]; ral1 = *(const uint4*)&wl[4];
        int s_glob = n0 + b_s + tap - pad;
        if ((unsigned)s_glob < (unsigned)SS) {
            const uint32_t* xh = &g_xh[tn][b][s_glob][c * 16 + b_half];
            const uint32_t* xl = &g_xl[tn][b][s_glob][c * 16 + b_half];
            rbh0 = *(const uint4*)&xh[0]; rbh1 = *(const uint4*)&xh[4];
            rbl0 = *(const uint4*)&xl[0]; rbl1 = *(const uint4*)&xl[4];
        } else {
            rbh0 = make_uint4(0, 0, 0, 0); rbh1 = rbh0;
            rbl0 = rbh0; rbl1 = rbh0;
        }
    };
    auto sts_slab = [&](int bf) {
        uint32_t* Ah = smu + bf * CV_BUF_U32 + CV_AH + a_row * CV_ST + a_half;
        uint32_t* Al = smu + bf * CV_BUF_U32 + CV_AL + a_row * CV_ST + a_half;
        uint32_t* Bh = smu + bf * CV_BUF_U32 + CV_BH + b_s * CV_ST + b_half;
        uint32_t* Bl = smu + bf * CV_BUF_U32 + CV_BL + b_s * CV_ST + b_half;
        Ah[0] = rah0.x; Ah[1] = rah0.y; Ah[2] = rah0.z; Ah[3] = rah0.w;
        Ah[4] = rah1.x; Ah[5] = rah1.y; Ah[6] = rah1.z; Ah[7] = rah1.w;
        Al[0] = ral0.x; Al[1] = ral0.y; Al[2] = ral0.z; Al[3] = ral0.w;
        Al[4] = ral1.x; Al[5] = ral1.y; Al[6] = ral1.z; Al[7] = ral1.w;
        Bh[0] = rbh0.x; Bh[1] = rbh0.y; Bh[2] = rbh0.z; Bh[3] = rbh0.w;
        Bh[4] = rbh1.x; Bh[5] = rbh1.y; Bh[6] = rbh1.z; Bh[7] = rbh1.w;
        Bl[0] = rbl0.x; Bl[1] = rbl0.y; Bl[2] = rbl0.z; Bl[3] = rbl0.w;
        Bl[4] = rbl1.x; Bl[5] = rbl1.y; Bl[6] = rbl1.z; Bl[7] = rbl1.w;
    };

    ldg_slab(0);
    sts_slab(0);
    __syncthreads();

    for (int it = 0; it < NIT; it++) {
        const int bf = it & 1;
        const bool have = (it + 1) < NIT;
        if (have) ldg_slab(it + 1);

        const uint32_t* Ah = smu + bf * CV_BUF_U32 + CV_AH;
        const uint32_t* Al = smu + bf * CV_BUF_U32 + CV_AL;
        const uint32_t* Bh = smu + bf * CV_BUF_U32 + CV_BH;
        const uint32_t* Bl = smu + bf * CV_BUF_U32 + CV_BL;

        #pragma unroll
        for (int s = 0; s < 2; s++) {
            const int fo = tg * 4 + 2 * s;
            uint32_t ahx[4][4], alx[4][4], bhx[4][2], blx[4][2];
            #pragma unroll
            for (int mi = 0; mi < 4; mi++) {
                int r = (wm + mi * 16 + g) * CV_ST + fo;
                int r8 = r + 8 * CV_ST;
                ahx[mi][0] = Ah[r];     ahx[mi][1] = Ah[r8];
                ahx[mi][2] = Ah[r + 1]; ahx[mi][3] = Ah[r8 + 1];
                alx[mi][0] = Al[r];     alx[mi][1] = Al[r8];
                alx[mi][2] = Al[r + 1]; alx[mi][3] = Al[r8 + 1];
            }
            #pragma unroll
            for (int ni = 0; ni < 4; ni++) {
                int cidx = (wn + ni * 8 + g) * CV_ST + fo;
                bhx[ni][0] = Bh[cidx]; bhx[ni][1] = Bh[cidx + 1];
                blx[ni][0] = Bl[cidx]; blx[ni][1] = Bl[cidx + 1];
            }
            #pragma unroll
            for (int mi = 0; mi < 4; mi++)
                #pragma unroll
                for (int ni = 0; ni < 4; ni++) {
                    mma_bf16s(dacc[mi][ni], ahx[mi][0], ahx[mi][1], ahx[mi][2],
                              ahx[mi][3], bhx[ni][0], bhx[ni][1]);
                    mma_bf16s(dacc[mi][ni], ahx[mi][0], ahx[mi][1], ahx[mi][2],
                              ahx[mi][3], blx[ni][0], blx[ni][1]);
                    mma_bf16s(dacc[mi][ni], alx[mi][0], alx[mi][1], alx[mi][2],
                              alx[mi][3], bhx[ni][0], bhx[ni][1]);
                }
        }

        if (have) sts_slab(bf ^ 1);
        __syncthreads();
    }

    #pragma unroll
    for (int mi = 0; mi < 4; mi++) {
        int lr0 = wm + mi * 16 + g;
        float b0 = s_bias[lr0], b1 = s_bias[lr0 + 8];
        #pragma unroll
        for (int ni = 0; ni < 4; ni++) {
            int col = n0 + wn + ni * 8 + 2 * tg;
            float4 d = dacc[mi][ni];
            *(float2*)&out[(size_t)(m0 + lr0) * SS + col]     = make_float2(d.x + b0, d.y + b0);
            *(float2*)&out[(size_t)(m0 + lr0 + 8) * SS + col] = make_float2(d.z + b1, d.w + b1);
        }
    }
}

// ---------------------------------------------------------------------------
// Kernel 4: qkprep — split Q (x 1/64) and K into kpair-packed bf16 hi/lo.
// ---------------------------------------------------------------------------
__global__ void qkprep_kernel() {
    __shared__ float tile[32][33];
    int zz = blockIdx.z;
    int tn = zz / BB, b = zz % BB;     // tn: 0=Q, 1=K
    const float* src = &g_qkv[tn][b][0][0];
    int s0 = blockIdx.x * 32, d0 = blockIdx.y * 32;
    int tx = threadIdx.x, ty = threadIdx.y;
    #pragma unroll
    for (int i = ty; i < 32; i += 8)
        tile[i][tx] = src[(size_t)(d0 + i) * SS + s0 + tx];
    __syncthreads();

    const float scale = (tn == 0) ? 0.015625f : 1.0f;
    const int h = d0 >> 6;
    const int kp_base = (d0 & 63) >> 1;
    const int bh = b * HH + h;
    uint32_t* dh = (tn == 0) ? &g_sqh[bh][0][0] : &g_skh[bh][0][0];
    uint32_t* dl = (tn == 0) ? &g_sql[bh][0][0] : &g_skl[bh][0][0];

    const int kpl = tx & 15;
    const int half = tx >> 4;
    const int pos = pos32(kp_base + kpl);
    #pragma unroll
    for (int i = ty; i < 32; i += 8) {
        float u = tile[2 * kpl][i] * scale;
        float v = tile[2 * kpl + 1][i] * scale;
        uint32_t ph, pl;
        bsplit2(u, v, ph, pl);
        if (half == 0) dh[(size_t)(s0 + i) * 32 + pos] = ph;
        else           dl[(size_t)(s0 + i) * 32 + pos] = pl;
    }
}

// ---------------------------------------------------------------------------
// Kernel 5: vprep — split V per (b,h) into kpair-packed bf16 hi/lo.
// V[d][t] rows are t-contiguous; kpair over t, pos16-prebaked.
// ---------------------------------------------------------------------------
__global__ void vprep_kernel() {
    const int b = blockIdx.z, h = blockIdx.y, d0 = blockIdx.x * 8;
    const int bh = b * HH + h;
    const int tid = threadIdx.x;
    for (int dr = 0; dr < 8; dr++) {
        const float* src = &g_qkv[2][b][h * HD + d0 + dr][0];
        #pragma unroll
        for (int p = 0; p < 2; p++) {
            int kk = p * 256 + tid;
            float2 uv = *(const float2*)&src[2 * kk];
            uint32_t ph, pl;
            bsplit2(uv.x, uv.y, ph, pl);
            int idx = (kk & ~15) | pos16(kk & 15);
            g_vh[bh][d0 + dr][idx] = ph;
            g_vl[bh][d0 + dr][idx] = pl;
        }
    }
}

// ---------------------------------------------------------------------------
// Kernel 6: scores GEMM via bf16 mma (3 terms). Raw scores -> g_p.
// ---------------------------------------------------------------------------
#define SG_ST 33
#define SG_A_H 0
#define SG_A_L 4224
#define SG_B_H 8448
#define SG_B_L 12672
#define SG_SMEM (16896 * (int)sizeof(uint32_t))

__global__ __launch_bounds__(256, 2) void scores_gemm() {
    extern __shared__ uint32_t smu[];
    const int b = blockIdx.z, h = blockIdx.y;
    const int s0 = (blockIdx.x >> 3) * 128, t0 = (blockIdx.x & 7) * 128;
    const int bh = b * HH + h;
    const int tid = threadIdx.x, wid = tid >> 5, lane = tid & 31;
    const int g = lane >> 2, tg = lane & 3;
    const int wm = (wid >> 2) * 64, wn = (wid & 3) * 32;

    {
        const int row = tid >> 1, c0 = (tid & 1) * 16;
        const uint32_t* sa_h = &g_sqh[bh][s0 + row][c0];
        const uint32_t* sa_l = &g_sql[bh][s0 + row][c0];
        const uint32_t* sb_h = &g_skh[bh][t0 + row][c0];
        const uint32_t* sb_l = &g_skl[bh][t0 + row][c0];
        uint32_t* Ah = smu + SG_A_H + row * SG_ST + c0;
        uint32_t* Al = smu + SG_A_L + row * SG_ST + c0;
        uint32_t* Bh = smu + SG_B_H + row * SG_ST + c0;
        uint32_t* Bl = smu + SG_B_L + row * SG_ST + c0;
        #pragma unroll
        for (int i = 0; i < 4; i++) {
            uint4 va = *(const uint4*)&sa_h[4 * i];
            uint4 vb = *(const uint4*)&sa_l[4 * i];
            uint4 vc = *(const uint4*)&sb_h[4 * i];
            uint4 vd = *(const uint4*)&sb_l[4 * i];
            Ah[4 * i] = va.x; Ah[4 * i + 1] = va.y; Ah[4 * i + 2] = va.z; Ah[4 * i + 3] = va.w;
            Al[4 * i] = vb.x; Al[4 * i + 1] = vb.y; Al[4 * i + 2] = vb.z; Al[4 * i + 3] = vb.w;
            Bh[4 * i] = vc.x; Bh[4 * i + 1] = vc.y; Bh[4 * i + 2] = vc.z; Bh[4 * i + 3] = vc.w;
            Bl[4 * i] = vd.x; Bl[4 * i + 1] = vd.y; Bl[4 * i + 2] = vd.z; Bl[4 * i + 3] = vd.w;
        }
    }
    __syncthreads();

    const uint32_t* Ah = smu + SG_A_H;
    const uint32_t* Al = smu + SG_A_L;
    const uint32_t* Bh = smu + SG_B_H;
    const uint32_t* Bl = smu + SG_B_L;

    float4 dacc[4][4];
    #pragma unroll
    for (int mi = 0; mi < 4; mi++)
        #pragma unroll
        for (int ni = 0; ni < 4; ni++) dacc[mi][ni] = make_float4(0.f, 0.f, 0.f, 0.f);

    #pragma unroll
    for (int s = 0; s < 4; s++) {
        const int fo = tg * 8 + 2 * s;
        uint32_t bhx[4][2], blx[4][2];
        #pragma unroll
        for (int ni = 0; ni < 4; ni++) {
            int c = (wn + ni * 8 + g) * SG_ST + fo;
            bhx[ni][0] = Bh[c]; bhx[ni][1] = Bh[c + 1];
            blx[ni][0] = Bl[c]; blx[ni][1] = Bl[c + 1];
        }
        #pragma unroll
        for (int mi = 0; mi < 4; mi++) {
            int r = (wm + mi * 16 + g) * SG_ST + fo;
            int r8 = r + 8 * SG_ST;
            uint32_t a0 = Ah[r], a1 = Ah[r8], a2 = Ah[r + 1], a3 = Ah[r8 + 1];
            uint32_t l0 = Al[r], l1 = Al[r8], l2 = Al[r + 1], l3 = Al[r8 + 1];
            #pragma unroll
            for (int ni = 0; ni < 4; ni++) {
                mma_bf16s(dacc[mi][ni], a0, a1, a2, a3, bhx[ni][0], bhx[ni][1]);
                mma_bf16s(dacc[mi][ni], a0, a1, a2, a3, blx[ni][0], blx[ni][1]);
                mma_bf16s(dacc[mi][ni], l0, l1, l2, l3, bhx[ni][0], bhx[ni][1]);
            }
        }
    }

    float* Pg = &g_p[((size_t)bh << 20)];
    #pragma unroll
    for (int mi = 0; mi < 4; mi++) {
        int lr0 = s0 + wm + mi * 16 + g;
        #pragma unroll
        for (int ni = 0; ni < 4; ni++) {
            int col = t0 + wn + ni * 8 + 2 * tg;
            float4 d = dacc[mi][ni];
            *(float2*)&Pg[(size_t)lr0 * SS + col]       = make_float2(d.x, d.y);
            *(float2*)&Pg[(size_t)(lr0 + 8) * SS + col] = make_float2(d.z, d.w);
        }
    }
}

// ---------------------------------------------------------------------------
// Kernel 7: softmax + fused ave + packed bf16 split P emission.
// Per CTA: (b, 8 rows), 64KB smem (3 CTAs/SM). Loops h=0..7.
// ---------------------------------------------------------------------------
#define SMA_SMEM (16384 * (int)sizeof(float))

__global__ __launch_bounds__(256) void softmax_ave(float* __restrict__ ave) {
    extern __shared__ float smf[];
    float* buf = smf;            // 8*1024
    float* av  = smf + 8192;     // 8*1024

    const int b = blockIdx.y, s0 = blockIdx.x * 8;
    const int tid = threadIdx.x, w = tid >> 5, lane = tid & 31;

    #pragma unroll
    for (int i = 0; i < 8; i++)
        *(float4*)&av[(i * 256 + tid) * 4] = make_float4(0.f, 0.f, 0.f, 0.f);

    for (int h = 0; h < HH; h++) {
        const int bh = b * HH + h;
        const float* Pg = &g_p[(((size_t)bh) << 20) + (size_t)s0 * SS];
        __syncthreads();
        #pragma unroll
        for (int i = 0; i < 8; i++) {
            int off = (i * 256 + tid) * 4;
            *(float4*)&buf[off] = *(const float4*)&Pg[off];
        }
        __syncthreads();

        {
            float* row = &buf[w * 1024];
            float* arow = &av[w * 1024];
            float m = -1e30f;
            for (int j = lane; j < 1024; j += 32) m = fmaxf(m, row[j]);
            #pragma unroll
            for (int o = 16; o > 0; o >>= 1)
                m = fmaxf(m, __shfl_xor_sync(0xffffffffu, m, o));
            float s = 0.0f;
            for (int j = lane; j < 1024; j += 32) {
                float e = __expf(row[j] - m);
                row[j] = e;
                s += e;
            }
            #pragma unroll
            for (int o = 16; o > 0; o >>= 1) s += __shfl_xor_sync(0xffffffffu, s, o);
            float inv = 1.0f / s;
            for (int j = lane; j < 1024; j += 32) {
                float p = row[j] * inv;
                row[j] = p;
                arow[j] += 0.125f * p;
            }
        }
        __syncthreads();

        // pack normalized P to bf16 hi/lo, pos16-prebaked
        #pragma unroll
        for (int i = 0; i < 16; i++) {
            int tt = i * 256 + tid;          // 0..4095
            int r = tt >> 9, kk = tt & 511;
            float2 uv = *(float2*)&buf[r * 1024 + 2 * kk];
            uint32_t ph, pl;
            bsplit2(uv.x, uv.y, ph, pl);
            int idx = (kk & ~15) | pos16(kk & 15);
            g_ph[bh][s0 + r][idx] = ph;
            g_pl[bh][s0 + r][idx] = pl;
        }
    }

    __syncthreads();
    #pragma unroll
    for (int i = 0; i < 8; i++) {
        int off = (i * 256 + tid) * 4;
        int r = off >> 10, c = off & 1023;
        *(float4*)&ave[((size_t)b * SS + s0 + r) * SS + c] = *(float4*)&av[off];
    }
}

// ---------------------------------------------------------------------------
// Kernel 8: PV GEMM via bf16 mma (3 terms), pure-copy staging from packed
// P and V. Per CTA: (b,h,128 s-rows) -> 128x64 into g_o1.
// ---------------------------------------------------------------------------
#define PV_ST 17
#define PV_A_H 0
#define PV_A_L 2176
#define PV_B_H 4352
#define PV_B_L 5440
#define PV_BUF_U32 6528
#define PV_SMEM (2 * PV_BUF_U32 * (int)sizeof(uint32_t))

__global__ __launch_bounds__(256, 2) void pv_mma() {
    extern __shared__ uint32_t smu[];
    const int b = blockIdx.z, h = blockIdx.y, s0 = blockIdx.x * 128;
    const int bh = b * HH + h;
    const int tid = threadIdx.x, wid = tid >> 5, lane = tid & 31;
    const int g = lane >> 2, tg = lane & 3;
    const int wm = (wid >> 2) * 64, wn = (wid & 3) * 16;

    float4 dacc[4][2];
    #pragma unroll
    for (int mi = 0; mi < 4; mi++)
        #pragma unroll
        for (int ni = 0; ni < 2; ni++) dacc[mi][ni] = make_float4(0.f, 0.f, 0.f, 0.f);

    const int a_row = tid >> 1, a_c0 = (tid & 1) * 8;   // 2 thr/row, 8 u32 each
    const int b_d = tid >> 2, b_c0 = (tid & 3) * 4;     // 4 thr/row, 4 u32 each

    uint4 rah0, rah1, ral0, ral1, rbh, rbl;

    auto ldg_slab = [&](int c) {
        const uint32_t* ph = &g_ph[bh][s0 + a_row][c * 16 + a_c0];
        const uint32_t* pl = &g_pl[bh][s0 + a_row][c * 16 + a_c0];
        rah0 = *(const uint4*)&ph[0]; rah1 = *(const uint4*)&ph[4];
        ral0 = *(const uint4*)&pl[0]; ral1 = *(const uint4*)&pl[4];
        rbh = *(const uint4*)&g_vh[bh][b_d][c * 16 + b_c0];
        rbl = *(const uint4*)&g_vl[bh][b_d][c * 16 + b_c0];
    };
    auto sts_slab = [&](int bf) {
        uint32_t* Ah = smu + bf * PV_BUF_U32 + PV_A_H + a_row * PV_ST + a_c0;
        uint32_t* Al = smu + bf * PV_BUF_U32 + PV_A_L + a_row * PV_ST + a_c0;
        uint32_t* Bh = smu + bf * PV_BUF_U32 + PV_B_H + b_d * PV_ST + b_c0;
        uint32_t* Bl = smu + bf * PV_BUF_U32 + PV_B_L + b_d * PV_ST + b_c0;
        Ah[0] = rah0.x; Ah[1] = rah0.y; Ah[2] = rah0.z; Ah[3] = rah0.w;
        Ah[4] = rah1.x; Ah[5] = rah1.y; Ah[6] = rah1.z; Ah[7] = rah1.w;
        Al[0] = ral0.x; Al[1] = ral0.y; Al[2] = ral0.z; Al[3] = ral0.w;
        Al[4] = ral1.x; Al[5] = ral1.y; Al[6] = ral1.z; Al[7] = ral1.w;
        Bh[0] = rbh.x; Bh[1] = rbh.y; Bh[2] = rbh.z; Bh[3] = rbh.w;
        Bl[0] = rbl.x; Bl[1] = rbl.y; Bl[2] = rbl.z; Bl[3] = rbl.w;
    };

    ldg_slab(0);
    sts_slab(0);
    __syncthreads();

    for (int c = 0; c < 32; c++) {
        const int bf = c & 1;
        const bool have = (c + 1) < 32;
        if (have) ldg_slab(c + 1);

        const uint32_t* Ah = smu + bf * PV_BUF_U32 + PV_A_H;
        const uint32_t* Al = smu + bf * PV_BUF_U32 + PV_A_L;
        const uint32_t* Bh = smu + bf * PV_BUF_U32 + PV_B_H;
        const uint32_t* Bl = smu + bf * PV_BUF_U32 + PV_B_L;

        #pragma unroll
        for (int s = 0; s < 2; s++) {
            const int fo = tg * 4 + 2 * s;
            uint32_t bhx[2][2], blx[2][2];
            #pragma unroll
            for (int ni = 0; ni < 2; ni++) {
                int cidx = (wn + ni * 8 + g) * PV_ST + fo;
                bhx[ni][0] = Bh[cidx]; bhx[ni][1] = Bh[cidx + 1];
                blx[ni][0] = Bl[cidx]; blx[ni][1] = Bl[cidx + 1];
            }
            #pragma unroll
            for (int mi = 0; mi < 4; mi++) {
                int r = (wm + mi * 16 + g) * PV_ST + fo;
                int r8 = r + 8 * PV_ST;
                uint32_t a0 = Ah[r], a1 = Ah[r8], a2 = Ah[r + 1], a3 = Ah[r8 + 1];
                uint32_t l0 = Al[r], l1 = Al[r8], l2 = Al[r + 1], l3 = Al[r8 + 1];
                #pragma unroll
                for (int ni = 0; ni < 2; ni++) {
                    mma_bf16s(dacc[mi][ni], a0, a1, a2, a3, bhx[ni][0], bhx[ni][1]);
                    mma_bf16s(dacc[mi][ni], a0, a1, a2, a3, blx[ni][0], blx[ni][1]);
                    mma_bf16s(dacc[mi][ni], l0, l1, l2, l3, bhx[ni][0], bhx[ni][1]);
                }
            }
        }

        if (have) sts_slab(bf ^ 1);
        __syncthreads();
    }

    #pragma unroll
    for (int mi = 0; mi < 4; mi++) {
        int lr0 = s0 + wm + mi * 16 + g;
        #pragma unroll
        for (int ni = 0; ni < 2; ni++) {
            int col = h * HD + wn + ni * 8 + 2 * tg;
            float4 d = dacc[mi][ni];
            *(float2*)&g_o1[b][lr0][col]     = make_float2(d.x, d.y);
            *(float2*)&g_o1[b][lr0 + 8][col] = make_float2(d.z, d.w);
        }
    }
}

// ---------------------------------------------------------------------------
// Kernel 9: output projection: out = O1 @ Wo^T + bo  (double-buffered f32x2)
// ---------------------------------------------------------------------------
__global__ __launch_bounds__(256) void proj_kernel(const float* __restrict__ Wo,
                                                   const float* __restrict__ bo,
                                                   float* __restrict__ out) {
    __shared__ float As[2][8][128];
    __shared__ float Bs[2][8][128];
    const int m0 = blockIdx.x * 128, n0 = blockIdx.y * 128;
    const float* A = &g_o1[0][0][0];
    const int tid = threadIdx.x, tx = tid & 15, ty = tid >> 4;
    const int li = tid >> 1, lj = (tid & 1) * 4;

    ull acc[8][4];
    #pragma unroll
    for (int i = 0; i < 8; i++)
        #pragma unroll
        for (int p = 0; p < 4; p++) acc[i][p] = 0ULL;

    float4 avr, bvr;
    {
        avr = *(const float4*)&A[(size_t)(m0 + li) * DD + lj];
        bvr = *(const float4*)&Wo[(size_t)(n0 + li) * DD + lj];
        As[0][lj + 0][li] = avr.x; As[0][lj + 1][li] = avr.y;
        As[0][lj + 2][li] = avr.z; As[0][lj + 3][li] = avr.w;
        Bs[0][lj + 0][li] = bvr.x; Bs[0][lj + 1][li] = bvr.y;
        Bs[0][lj + 2][li] = bvr.z; Bs[0][lj + 3][li] = bvr.w;
    }
    __syncthreads();

    int cur = 0;
    for (int k0 = 0; k0 < DD; k0 += 8) {
        bool hn = (k0 + 8) < DD;
        if (hn) {
            avr = *(const float4*)&A[(size_t)(m0 + li) * DD + k0 + 8 + lj];
            bvr = *(const float4*)&Wo[(size_t)(n0 + li) * DD + k0 + 8 + lj];
        }

        #pragma unroll
        for (int j = 0; j < 8; j++) {
            float4 a0 = *(float4*)&As[cur][j][ty * 8];
            float4 a1 = *(float4*)&As[cur][j][ty * 8 + 4];
            ull b2[4];
            #pragma unroll
            for (int p = 0; p < 4; p++) b2[p] = *(ull*)&Bs[cur][j][tx * 8 + 2 * p];
            float avv[8] = {a0.x, a0.y, a0.z, a0.w, a1.x, a1.y, a1.z, a1.w};
            #pragma unroll
            for (int i = 0; i < 8; i++) {
                ull ad = f2dup(avv[i]);
                #pragma unroll
                for (int p = 0; p < 4; p++) acc[i][p] = f2fma(ad, b2[p], acc[i][p]);
            }
        }

        if (hn) {
            int nb = cur ^ 1;
            As[nb][lj + 0][li] = avr.x; As[nb][lj + 1][li] = avr.y;
            As[nb][lj + 2][li] = avr.z; As[nb][lj + 3][li] = avr.w;
            Bs[nb][lj + 0][li] = bvr.x; Bs[nb][lj + 1][li] = bvr.y;
            Bs[nb][lj + 2][li] = bvr.z; Bs[nb][lj + 3][li] = bvr.w;
        }
        __syncthreads();
        cur ^= 1;
    }

    #pragma unroll
    for (int i = 0; i < 8; i++) {
        int m = m0 + ty * 8 + i;
        #pragma unroll
        for (int p = 0; p < 4; p++) {
            ull bb = *(const ull*)&bo[n0 + tx * 8 + 2 * p];
            ull r = f2add(acc[i][p], bb);
            *(ull*)&out[(size_t)m * DD + n0 + tx * 8 + 2 * p] = r;
        }
    }
}

// ---------------------------------------------------------------------------
extern "C" void kernel_launch(void* const* d_in, const int* in_sizes, int n_in,
                              void* d_out, int out_size) {
    const float* query = (const float*)d_in[0];
    const float* key_t = (const float*)d_in[1];
    const float* value = (const float*)d_in[2];
    const float* Wq    = (const float*)d_in[3];
    const float* bq    = (const float*)d_in[4];
    const float* Wk    = (const float*)d_in[5];
    const float* bk    = (const float*)d_in[6];
    const float* Wv    = (const float*)d_in[7];
    const float* bv    = (const float*)d_in[8];
    const float* Wo    = (const float*)d_in[9];
    const float* bo    = (const float*)d_in[10];

    float* out = (float*)d_out;
    float* ave = out + (size_t)BB * SS * DD;

    cudaFuncSetAttribute(conv_mma, cudaFuncAttributeMaxDynamicSharedMemorySize, CV_SMEM);
    cudaFuncSetAttribute(scores_gemm, cudaFuncAttributeMaxDynamicSharedMemorySize, SG_SMEM);
    cudaFuncSetAttribute(softmax_ave, cudaFuncAttributeMaxDynamicSharedMemorySize, SMA_SMEM);
    cudaFuncSetAttribute(pv_mma, cudaFuncAttributeMaxDynamicSharedMemorySize, PV_SMEM);

    xprep_kernel<<<dim3(SS / 128, BB, 3), 256>>>(query, key_t, value);
    wprep_kernel<<<dim3(DD / 64, 3), 256>>>(Wq, Wk, Wv);
    conv_mma<<<dim3(DD / 128, SS / 128, 3 * BB), 256, CV_SMEM>>>(bq, bk, bv);
    qkprep_kernel<<<dim3(SS / 32, DD / 32, 2 * BB), dim3(32, 8)>>>();
    vprep_kernel<<<dim3(HD / 8, HH, BB), 256>>>();
    scores_gemm<<<dim3(64, HH, BB), 256, SG_SMEM>>>();
    softmax_ave<<<dim3(SS / 8, BB), 256, SMA_SMEM>>>(ave);
    pv_mma<<<dim3(SS / 128, HH, BB), 256, PV_SMEM>>>();
    proj_kernel<<<dim3((BB * SS) / 128, DD / 128), 256>>>(Wo, bo, out);
}

// round 12
// speedup vs baseline: 1.6876x; 1.0313x over previous
#include <cuda_runtime.h>
#include <cuda_bf16.h>
#include <cstdint>

// ---------------------------------------------------------------------------
// ConvMultiheadAttention: B=8, S=1024, D=512, H=8, hd=64, KERNEL=3
// out  = [8,1024,512]  ; ave = [8,1024,1024]
// ---------------------------------------------------------------------------

#define BB 8
#define SS 1024
#define DD 512
#define HH 8
#define HD 64

typedef unsigned long long ull;

// ----- bf16 split helpers ----------------------------------------------------
__device__ __forceinline__ void bsplit2(float u, float v, uint32_t& ph, uint32_t& pl) {
    __nv_bfloat16 hu = __float2bfloat16_rn(u);
    __nv_bfloat16 hv = __float2bfloat16_rn(v);
    __nv_bfloat16 lu = __float2bfloat16_rn(u - __bfloat162float(hu));
    __nv_bfloat16 lv = __float2bfloat16_rn(v - __bfloat162float(hv));
    ph = (uint32_t)__bfloat16_as_ushort(hu) | ((uint32_t)__bfloat16_as_ushort(hv) << 16);
    pl = (uint32_t)__bfloat16_as_ushort(lu) | ((uint32_t)__bfloat16_as_ushort(lv) << 16);
}
__device__ __forceinline__ void mma_bf16s(float4& d, uint32_t a0, uint32_t a1,
                                          uint32_t a2, uint32_t a3,
                                          uint32_t b0, uint32_t b1) {
    asm("mma.sync.aligned.m16n8k16.row.col.f32.bf16.bf16.f32 "
        "{%0,%1,%2,%3}, {%4,%5,%6,%7}, {%8,%9}, {%0,%1,%2,%3};"
        : "+f"(d.x), "+f"(d.y), "+f"(d.z), "+f"(d.w)
        : "r"(a0), "r"(a1), "r"(a2), "r"(a3), "r"(b0), "r"(b1));
}
// kpair position permutations (fragment (tg, k16-step s) reads pos fo, fo+1)
__device__ __forceinline__ int pos16(int kp) { return (kp & 3) * 4 + (kp >> 2); }
__device__ __forceinline__ int pos32(int kp) {
    return (kp & 3) * 8 + 2 * (kp >> 3) + ((kp >> 2) & 1);
}

// ----- scratch (static device globals) --------------------------------------
__device__ float g_qkv[2][BB][DD][SS];       // conv outputs Q,K [B,D,S]
__device__ uint32_t g_xh[3][BB][SS][256];    // inputs split hi, ci-kpair packed
__device__ uint32_t g_xl[3][BB][SS][256];    // inputs split lo
__device__ uint32_t g_wh[4][3][DD][256];     // weights split hi, per tap (3=Wo)
__device__ uint32_t g_wl[4][3][DD][256];     // weights split lo
__device__ uint32_t g_sqh[BB * HH][SS][32];  // Q/64 split hi (pos32 packed)
__device__ uint32_t g_sql[BB * HH][SS][32];
__device__ uint32_t g_skh[BB * HH][SS][32];  // K split hi
__device__ uint32_t g_skl[BB * HH][SS][32];
__device__ float g_p[(size_t)BB * HH * SS * SS]; // raw scores
__device__ uint32_t g_ph[BB * HH][SS][512];  // probs split hi (pos16 packed)
__device__ uint32_t g_pl[BB * HH][SS][512];  // probs split lo
__device__ uint32_t g_vh[BB * HH][HD][512];  // V split hi (pos16 packed)
__device__ uint32_t g_vl[BB * HH][HD][512];  // V split lo
__device__ uint32_t g_oh[BB * SS][256];      // o1 split hi (pos16 packed)
__device__ uint32_t g_ol[BB * SS][256];      // o1 split lo

// ---------------------------------------------------------------------------
// Kernel 1: xprep — split inputs [B,S,D] into kpair-packed bf16 hi/lo
// ---------------------------------------------------------------------------
__global__ void xprep_kernel(const float* __restrict__ q,
                             const float* __restrict__ k,
                             const float* __restrict__ v) {
    const int tn = blockIdx.z, b = blockIdx.y, s0 = blockIdx.x * 128;
    const float* src = (tn == 0) ? q : (tn == 1) ? k : v;
    const int kp = threadIdx.x;             // 0..255
    const int idx = (kp & ~15) | pos16(kp & 15);
    for (int i = 0; i < 128; i++) {
        int s = s0 + i;
        float2 uv = *(const float2*)&src[((size_t)b * SS + s) * DD + 2 * kp];
        uint32_t ph, pl;
        bsplit2(uv.x, uv.y, ph, pl);
        g_xh[tn][b][s][idx] = ph;
        g_xl[tn][b][s][idx] = pl;
    }
}

// ---------------------------------------------------------------------------
// Kernel 2: wprep — split weights (Wq/Wk/Wv per tap, Wo) into packed hi/lo.
// ---------------------------------------------------------------------------
__global__ void wprep_kernel(const float* __restrict__ Wq,
                             const float* __restrict__ Wk,
                             const float* __restrict__ Wv,
                             const float* __restrict__ Wo) {
    const int tn = blockIdx.y;
    const float* W = (tn == 0) ? Wq : (tn == 1) ? Wk : (tn == 2) ? Wv : Wo;
    const int KER = (tn == 0 || tn == 1) ? 3 : 1;
    const int Kdim = DD * KER;
    const int co0 = blockIdx.x * 64;
    const int kp = threadIdx.x;              // 0..255 (ci pair)
    const int idx = (kp & ~15) | pos16(kp & 15);
    for (int tap = 0; tap < KER; tap++)
        for (int i = 0; i < 64; i++) {
            int co = co0 + i;
            float u = W[(size_t)co * Kdim + (2 * kp) * KER + tap];
            float vv = W[(size_t)co * Kdim + (2 * kp + 1) * KER + tap];
            uint32_t ph, pl;
            bsplit2(u, vv, ph, pl);
            g_wh[tn][tap][co][idx] = ph;
            g_wl[tn][tap][co][idx] = pl;
        }
}

// ---------------------------------------------------------------------------
// Kernel 3: conv1d as tap-decomposed bf16 MMA GEMM (split, 3 terms).
// Q/K epilogue -> g_qkv; V epilogue -> packed g_vh/g_vl directly.
// ---------------------------------------------------------------------------
#define CV_ST 17
#define CV_AH 0
#define CV_AL 2176
#define CV_BH 4352
#define CV_BL 6528
#define CV_BUF_U32 8704
#define CV_SMEM (2 * CV_BUF_U32 * (int)sizeof(uint32_t))

__global__ __launch_bounds__(256)
void conv_mma(const float* __restrict__ bq, const float* __restrict__ bk,
              const float* __restrict__ bv) {
    extern __shared__ uint32_t smu[];
    __shared__ float s_bias[128];

    const int zz = blockIdx.z, tn = zz / BB, b = zz % BB;
    const float* bias = (tn == 0) ? bq : (tn == 1) ? bk : bv;
    const int KER = (tn == 2) ? 1 : 3;
    const int pad = KER >> 1;
    const int NIT = KER * 16;
    const int m0 = blockIdx.x * 128, n0 = blockIdx.y * 128;
    const int tid = threadIdx.x, wid = tid >> 5, lane = tid & 31;
    const int g = lane >> 2, tg = lane & 3;
    const int wm = (wid >> 2) * 64, wn = (wid & 3) * 32;

    if (tid < 128) s_bias[tid] = bias[m0 + tid];

    float4 dacc[4][4];
    #pragma unroll
    for (int mi = 0; mi < 4; mi++)
        #pragma unroll
        for (int ni = 0; ni < 4; ni++) dacc[mi][ni] = make_float4(0.f, 0.f, 0.f, 0.f);

    const int a_row = tid >> 1, a_half = (tid & 1) * 8;
    const int b_s = tid & 127, b_half = (tid >> 7) * 8;

    uint4 rah0, rah1, ral0, ral1, rbh0, rbh1, rbl0, rbl1;

    auto ldg_slab = [&](int it) {
        int tap = it >> 4, c = it & 15;
        const uint32_t* wh = &g_wh[tn][tap][m0 + a_row][c * 16 + a_half];
        const uint32_t* wl = &g_wl[tn][tap][m0 + a_row][c * 16 + a_half];
        rah0 = *(const uint4*)&wh[0]; rah1 = *(const uint4*)&wh[4];
        ral0 = *(const uint4*)&wl[0]; ral1 = *(const uint4*)&wl[4];
        int s_glob = n0 + b_s + tap - pad;
        if ((unsigned)s_glob < (unsigned)SS) {
            const uint32_t* xh = &g_xh[tn][b][s_glob][c * 16 + b_half];
            const uint32_t* xl = &g_xl[tn][b][s_glob][c * 16 + b_half];
            rbh0 = *(const uint4*)&xh[0]; rbh1 = *(const uint4*)&xh[4];
            rbl0 = *(const uint4*)&xl[0]; rbl1 = *(const uint4*)&xl[4];
        } else {
            rbh0 = make_uint4(0, 0, 0, 0); rbh1 = rbh0;
            rbl0 = rbh0; rbl1 = rbh0;
        }
    };
    auto sts_slab = [&](int bf) {
        uint32_t* Ah = smu + bf * CV_BUF_U32 + CV_AH + a_row * CV_ST + a_half;
        uint32_t* Al = smu + bf * CV_BUF_U32 + CV_AL + a_row * CV_ST + a_half;
        uint32_t* Bh = smu + bf * CV_BUF_U32 + CV_BH + b_s * CV_ST + b_half;
        uint32_t* Bl = smu + bf * CV_BUF_U32 + CV_BL + b_s * CV_ST + b_half;
        Ah[0] = rah0.x; Ah[1] = rah0.y; Ah[2] = rah0.z; Ah[3] = rah0.w;
        Ah[4] = rah1.x; Ah[5] = rah1.y; Ah[6] = rah1.z; Ah[7] = rah1.w;
        Al[0] = ral0.x; Al[1] = ral0.y; Al[2] = ral0.z; Al[3] = ral0.w;
        Al[4] = ral1.x; Al[5] = ral1.y; Al[6] = ral1.z; Al[7] = ral1.w;
        Bh[0] = rbh0.x; Bh[1] = rbh0.y; Bh[2] = rbh0.z; Bh[3] = rbh0.w;
        Bh[4] = rbh1.x; Bh[5] = rbh1.y; Bh[6] = rbh1.z; Bh[7] = rbh1.w;
        Bl[0] = rbl0.x; Bl[1] = rbl0.y; Bl[2] = rbl0.z; Bl[3] = rbl0.w;
        Bl[4] = rbl1.x; Bl[5] = rbl1.y; Bl[6] = rbl1.z; Bl[7] = rbl1.w;
    };

    ldg_slab(0);
    sts_slab(0);
    __syncthreads();

    for (int it = 0; it < NIT; it++) {
        const int bf = it & 1;
        const bool have = (it + 1) < NIT;
        if (have) ldg_slab(it + 1);

        const uint32_t* Ah = smu + bf * CV_BUF_U32 + CV_AH;
        const uint32_t* Al = smu + bf * CV_BUF_U32 + CV_AL;
        const uint32_t* Bh = smu + bf * CV_BUF_U32 + CV_BH;
        const uint32_t* Bl = smu + bf * CV_BUF_U32 + CV_BL;

        #pragma unroll
        for (int s = 0; s < 2; s++) {
            const int fo = tg * 4 + 2 * s;
            uint32_t ahx[4][4], alx[4][4], bhx[4][2], blx[4][2];
            #pragma unroll
            for (int mi = 0; mi < 4; mi++) {
                int r = (wm + mi * 16 + g) * CV_ST + fo;
                int r8 = r + 8 * CV_ST;
                ahx[mi][0] = Ah[r];     ahx[mi][1] = Ah[r8];
                ahx[mi][2] = Ah[r + 1]; ahx[mi][3] = Ah[r8 + 1];
                alx[mi][0] = Al[r];     alx[mi][1] = Al[r8];
                alx[mi][2] = Al[r + 1]; alx[mi][3] = Al[r8 + 1];
            }
            #pragma unroll
            for (int ni = 0; ni < 4; ni++) {
                int cidx = (wn + ni * 8 + g) * CV_ST + fo;
                bhx[ni][0] = Bh[cidx]; bhx[ni][1] = Bh[cidx + 1];
                blx[ni][0] = Bl[cidx]; blx[ni][1] = Bl[cidx + 1];
            }
            #pragma unroll
            for (int mi = 0; mi < 4; mi++)
                #pragma unroll
                for (int ni = 0; ni < 4; ni++) {
                    mma_bf16s(dacc[mi][ni], ahx[mi][0], ahx[mi][1], ahx[mi][2],
                              ahx[mi][3], bhx[ni][0], bhx[ni][1]);
                    mma_bf16s(dacc[mi][ni], ahx[mi][0], ahx[mi][1], ahx[mi][2],
                              ahx[mi][3], blx[ni][0], blx[ni][1]);
                    mma_bf16s(dacc[mi][ni], alx[mi][0], alx[mi][1], alx[mi][2],
                              alx[mi][3], bhx[ni][0], bhx[ni][1]);
                }
        }

        if (have) sts_slab(bf ^ 1);
        __syncthreads();
    }

    if (tn != 2) {
        float* out = &g_qkv[tn][b][0][0];
        #pragma unroll
        for (int mi = 0; mi < 4; mi++) {
            int lr0 = wm + mi * 16 + g;
            float b0 = s_bias[lr0], b1 = s_bias[lr0 + 8];
            #pragma unroll
            for (int ni = 0; ni < 4; ni++) {
                int col = n0 + wn + ni * 8 + 2 * tg;
                float4 d = dacc[mi][ni];
                *(float2*)&out[(size_t)(m0 + lr0) * SS + col] =
                    make_float2(d.x + b0, d.y + b0);
                *(float2*)&out[(size_t)(m0 + lr0 + 8) * SS + col] =
                    make_float2(d.z + b1, d.w + b1);
            }
        }
    } else {
        // V: emit packed bf16 hi/lo directly (kpair over s = adjacent cols)
        #pragma unroll
        for (int mi = 0; mi < 4; mi++) {
            int lr0 = wm + mi * 16 + g;
            float b0 = s_bias[lr0], b1 = s_bias[lr0 + 8];
            int row0 = m0 + lr0, row1 = row0 + 8;
            int bh0 = b * HH + (row0 >> 6), bh1 = b * HH + (row1 >> 6);
            int dd0 = row0 & 63, dd1 = row1 & 63;
            #pragma unroll
            for (int ni = 0; ni < 4; ni++) {
                int col = n0 + wn + ni * 8 + 2 * tg;
                int kp = col >> 1;
                int idx = (kp & ~15) | pos16(kp & 15);
                float4 d = dacc[mi][ni];
                uint32_t ph, pl;
                bsplit2(d.x + b0, d.y + b0, ph, pl);
                g_vh[bh0][dd0][idx] = ph; g_vl[bh0][dd0][idx] = pl;
                bsplit2(d.z + b1, d.w + b1, ph, pl);
                g_vh[bh1][dd1][idx] = ph; g_vl[bh1][dd1][idx] = pl;
            }
        }
    }
}

// ---------------------------------------------------------------------------
// Kernel 4: qkprep — split Q (x 1/64) and K into kpair-packed bf16 hi/lo.
// ---------------------------------------------------------------------------
__global__ void qkprep_kernel() {
    __shared__ float tile[32][33];
    int zz = blockIdx.z;
    int tn = zz / BB, b = zz % BB;     // tn: 0=Q, 1=K
    const float* src = &g_qkv[tn][b][0][0];
    int s0 = blockIdx.x * 32, d0 = blockIdx.y * 32;
    int tx = threadIdx.x, ty = threadIdx.y;
    #pragma unroll
    for (int i = ty; i < 32; i += 8)
        tile[i][tx] = src[(size_t)(d0 + i) * SS + s0 + tx];
    __syncthreads();

    const float scale = (tn == 0) ? 0.015625f : 1.0f;
    const int h = d0 >> 6;
    const int kp_base = (d0 & 63) >> 1;
    const int bh = b * HH + h;
    uint32_t* dh = (tn == 0) ? &g_sqh[bh][0][0] : &g_skh[bh][0][0];
    uint32_t* dl = (tn == 0) ? &g_sql[bh][0][0] : &g_skl[bh][0][0];

    const int kpl = tx & 15;
    const int half = tx >> 4;
    const int pos = pos32(kp_base + kpl);
    #pragma unroll
    for (int i = ty; i < 32; i += 8) {
        float u = tile[2 * kpl][i] * scale;
        float v = tile[2 * kpl + 1][i] * scale;
        uint32_t ph, pl;
        bsplit2(u, v, ph, pl);
        if (half == 0) dh[(size_t)(s0 + i) * 32 + pos] = ph;
        else           dl[(size_t)(s0 + i) * 32 + pos] = pl;
    }
}

// ---------------------------------------------------------------------------
// Kernel 5: scores GEMM via bf16 mma (3 terms). Raw scores -> g_p.
// ---------------------------------------------------------------------------
#define SG_ST 33
#define SG_A_H 0
#define SG_A_L 4224
#define SG_B_H 8448
#define SG_B_L 12672
#define SG_SMEM (16896 * (int)sizeof(uint32_t))

__global__ __launch_bounds__(256, 2) void scores_gemm() {
    extern __shared__ uint32_t smu[];
    const int b = blockIdx.z, h = blockIdx.y;
    const int s0 = (blockIdx.x >> 3) * 128, t0 = (blockIdx.x & 7) * 128;
    const int bh = b * HH + h;
    const int tid = threadIdx.x, wid = tid >> 5, lane = tid & 31;
    const int g = lane >> 2, tg = lane & 3;
    const int wm = (wid >> 2) * 64, wn = (wid & 3) * 32;

    {
        const int row = tid >> 1, c0 = (tid & 1) * 16;
        const uint32_t* sa_h = &g_sqh[bh][s0 + row][c0];
        const uint32_t* sa_l = &g_sql[bh][s0 + row][c0];
        const uint32_t* sb_h = &g_skh[bh][t0 + row][c0];
        const uint32_t* sb_l = &g_skl[bh][t0 + row][c0];
        uint32_t* Ah = smu + SG_A_H + row * SG_ST + c0;
        uint32_t* Al = smu + SG_A_L + row * SG_ST + c0;
        uint32_t* Bh = smu + SG_B_H + row * SG_ST + c0;
        uint32_t* Bl = smu + SG_B_L + row * SG_ST + c0;
        #pragma unroll
        for (int i = 0; i < 4; i++) {
            uint4 va = *(const uint4*)&sa_h[4 * i];
            uint4 vb = *(const uint4*)&sa_l[4 * i];
            uint4 vc = *(const uint4*)&sb_h[4 * i];
            uint4 vd = *(const uint4*)&sb_l[4 * i];
            Ah[4 * i] = va.x; Ah[4 * i + 1] = va.y; Ah[4 * i + 2] = va.z; Ah[4 * i + 3] = va.w;
            Al[4 * i] = vb.x; Al[4 * i + 1] = vb.y; Al[4 * i + 2] = vb.z; Al[4 * i + 3] = vb.w;
            Bh[4 * i] = vc.x; Bh[4 * i + 1] = vc.y; Bh[4 * i + 2] = vc.z; Bh[4 * i + 3] = vc.w;
            Bl[4 * i] = vd.x; Bl[4 * i + 1] = vd.y; Bl[4 * i + 2] = vd.z; Bl[4 * i + 3] = vd.w;
        }
    }
    __syncthreads();

    const uint32_t* Ah = smu + SG_A_H;
    const uint32_t* Al = smu + SG_A_L;
    const uint32_t* Bh = smu + SG_B_H;
    const uint32_t* Bl = smu + SG_B_L;

    float4 dacc[4][4];
    #pragma unroll
    for (int mi = 0; mi < 4; mi++)
        #pragma unroll
        for (int ni = 0; ni < 4; ni++) dacc[mi][ni] = make_float4(0.f, 0.f, 0.f, 0.f);

    #pragma unroll
    for (int s = 0; s < 4; s++) {
        const int fo = tg * 8 + 2 * s;
        uint32_t bhx[4][2], blx[4][2];
        #pragma unroll
        for (int ni = 0; ni < 4; ni++) {
            int c = (wn + ni * 8 + g) * SG_ST + fo;
            bhx[ni][0] = Bh[c]; bhx[ni][1] = Bh[c + 1];
            blx[ni][0] = Bl[c]; blx[ni][1] = Bl[c + 1];
        }
        #pragma unroll
        for (int mi = 0; mi < 4; mi++) {
            int r = (wm + mi * 16 + g) * SG_ST + fo;
            int r8 = r + 8 * SG_ST;
            uint32_t a0 = Ah[r], a1 = Ah[r8], a2 = Ah[r + 1], a3 = Ah[r8 + 1];
            uint32_t l0 = Al[r], l1 = Al[r8], l2 = Al[r + 1], l3 = Al[r8 + 1];
            #pragma unroll
            for (int ni = 0; ni < 4; ni++) {
                mma_bf16s(dacc[mi][ni], a0, a1, a2, a3, bhx[ni][0], bhx[ni][1]);
                mma_bf16s(dacc[mi][ni], a0, a1, a2, a3, blx[ni][0], blx[ni][1]);
                mma_bf16s(dacc[mi][ni], l0, l1, l2, l3, bhx[ni][0], bhx[ni][1]);
            }
        }
    }

    float* Pg = &g_p[((size_t)bh << 20)];
    #pragma unroll
    for (int mi = 0; mi < 4; mi++) {
        int lr0 = s0 + wm + mi * 16 + g;
        #pragma unroll
        for (int ni = 0; ni < 4; ni++) {
            int col = t0 + wn + ni * 8 + 2 * tg;
            float4 d = dacc[mi][ni];
            *(float2*)&Pg[(size_t)lr0 * SS + col]       = make_float2(d.x, d.y);
            *(float2*)&Pg[(size_t)(lr0 + 8) * SS + col] = make_float2(d.z, d.w);
        }
    }
}

// ---------------------------------------------------------------------------
// Kernel 6: softmax + fused ave + packed bf16 split P emission.
// ---------------------------------------------------------------------------
#define SMA_SMEM (16384 * (int)sizeof(float))

__global__ __launch_bounds__(256) void softmax_ave(float* __restrict__ ave) {
    extern __shared__ float smf[];
    float* buf = smf;            // 8*1024
    float* av  = smf + 8192;     // 8*1024

    const int b = blockIdx.y, s0 = blockIdx.x * 8;
    const int tid = threadIdx.x, w = tid >> 5, lane = tid & 31;

    #pragma unroll
    for (int i = 0; i < 8; i++)
        *(float4*)&av[(i * 256 + tid) * 4] = make_float4(0.f, 0.f, 0.f, 0.f);

    for (int h = 0; h < HH; h++) {
        const int bh = b * HH + h;
        const float* Pg = &g_p[(((size_t)bh) << 20) + (size_t)s0 * SS];
        __syncthreads();
        #pragma unroll
        for (int i = 0; i < 8; i++) {
            int off = (i * 256 + tid) * 4;
            *(float4*)&buf[off] = *(const float4*)&Pg[off];
        }
        __syncthreads();

        {
            float* row = &buf[w * 1024];
            float* arow = &av[w * 1024];
            float m = -1e30f;
            for (int j = lane; j < 1024; j += 32) m = fmaxf(m, row[j]);
            #pragma unroll
            for (int o = 16; o > 0; o >>= 1)
                m = fmaxf(m, __shfl_xor_sync(0xffffffffu, m, o));
            float s = 0.0f;
            for (int j = lane; j < 1024; j += 32) {
                float e = __expf(row[j] - m);
                row[j] = e;
                s += e;
            }
            #pragma unroll
            for (int o = 16; o > 0; o >>= 1) s += __shfl_xor_sync(0xffffffffu, s, o);
            float inv = 1.0f / s;
            for (int j = lane; j < 1024; j += 32) {
                float p = row[j] * inv;
                row[j] = p;
                arow[j] += 0.125f * p;
            }
        }
        __syncthreads();

        #pragma unroll
        for (int i = 0; i < 16; i++) {
            int tt = i * 256 + tid;          // 0..4095
            int r = tt >> 9, kk = tt & 511;
            float2 uv = *(float2*)&buf[r * 1024 + 2 * kk];
            uint32_t ph, pl;
            bsplit2(uv.x, uv.y, ph, pl);
            int idx = (kk & ~15) | pos16(kk & 15);
            g_ph[bh][s0 + r][idx] = ph;
            g_pl[bh][s0 + r][idx] = pl;
        }
    }

    __syncthreads();
    #pragma unroll
    for (int i = 0; i < 8; i++) {
        int off = (i * 256 + tid) * 4;
        int r = off >> 10, c = off & 1023;
        *(float4*)&ave[((size_t)b * SS + s0 + r) * SS + c] = *(float4*)&av[off];
    }
}

// ---------------------------------------------------------------------------
// Kernel 7: PV GEMM via bf16 mma (3 terms), pure-copy staging. Epilogue emits
// packed o1 (kpair over d = adjacent output cols).
// ---------------------------------------------------------------------------
#define PV_ST 17
#define PV_A_H 0
#define PV_A_L 2176
#define PV_B_H 4352
#define PV_B_L 5440
#define PV_BUF_U32 6528
#define PV_SMEM (2 * PV_BUF_U32 * (int)sizeof(uint32_t))

__global__ __launch_bounds__(256, 2) void pv_mma() {
    extern __shared__ uint32_t smu[];
    const int b = blockIdx.z, h = blockIdx.y, s0 = blockIdx.x * 128;
    const int bh = b * HH + h;
    const int tid = threadIdx.x, wid = tid >> 5, lane = tid & 31;
    const int g = lane >> 2, tg = lane & 3;
    const int wm = (wid >> 2) * 64, wn = (wid & 3) * 16;

    float4 dacc[4][2];
    #pragma unroll
    for (int mi = 0; mi < 4; mi++)
        #pragma unroll
        for (int ni = 0; ni < 2; ni++) dacc[mi][ni] = make_float4(0.f, 0.f, 0.f, 0.f);

    const int a_row = tid >> 1, a_c0 = (tid & 1) * 8;
    const int b_d = tid >> 2, b_c0 = (tid & 3) * 4;

    uint4 rah0, rah1, ral0, ral1, rbh, rbl;

    auto ldg_slab = [&](int c) {
        const uint32_t* ph = &g_ph[bh][s0 + a_row][c * 16 + a_c0];
        const uint32_t* pl = &g_pl[bh][s0 + a_row][c * 16 + a_c0];
        rah0 = *(const uint4*)&ph[0]; rah1 = *(const uint4*)&ph[4];
        ral0 = *(const uint4*)&pl[0]; ral1 = *(const uint4*)&pl[4];
        rbh = *(const uint4*)&g_vh[bh][b_d][c * 16 + b_c0];
        rbl = *(const uint4*)&g_vl[bh][b_d][c * 16 + b_c0];
    };
    auto sts_slab = [&](int bf) {
        uint32_t* Ah = smu + bf * PV_BUF_U32 + PV_A_H + a_row * PV_ST + a_c0;
        uint32_t* Al = smu + bf * PV_BUF_U32 + PV_A_L + a_row * PV_ST + a_c0;
        uint32_t* Bh = smu + bf * PV_BUF_U32 + PV_B_H + b_d * PV_ST + b_c0;
        uint32_t* Bl = smu + bf * PV_BUF_U32 + PV_B_L + b_d * PV_ST + b_c0;
        Ah[0] = rah0.x; Ah[1] = rah0.y; Ah[2] = rah0.z; Ah[3] = rah0.w;
        Ah[4] = rah1.x; Ah[5] = rah1.y; Ah[6] = rah1.z; Ah[7] = rah1.w;
        Al[0] = ral0.x; Al[1] = ral0.y; Al[2] = ral0.z; Al[3] = ral0.w;
        Al[4] = ral1.x; Al[5] = ral1.y; Al[6] = ral1.z; Al[7] = ral1.w;
        Bh[0] = rbh.x; Bh[1] = rbh.y; Bh[2] = rbh.z; Bh[3] = rbh.w;
        Bl[0] = rbl.x; Bl[1] = rbl.y; Bl[2] = rbl.z; Bl[3] = rbl.w;
    };

    ldg_slab(0);
    sts_slab(0);
    __syncthreads();

    for (int c = 0; c < 32; c++) {
        const int bf = c & 1;
        const bool have = (c + 1) < 32;
        if (have) ldg_slab(c + 1);

        const uint32_t* Ah = smu + bf * PV_BUF_U32 + PV_A_H;
        const uint32_t* Al = smu + bf * PV_BUF_U32 + PV_A_L;
        const uint32_t* Bh = smu + bf * PV_BUF_U32 + PV_B_H;
        const uint32_t* Bl = smu + bf * PV_BUF_U32 + PV_B_L;

        #pragma unroll
        for (int s = 0; s < 2; s++) {
            const int fo = tg * 4 + 2 * s;
            uint32_t bhx[2][2], blx[2][2];
            #pragma unroll
            for (int ni = 0; ni < 2; ni++) {
                int cidx = (wn + ni * 8 + g) * PV_ST + fo;
                bhx[ni][0] = Bh[cidx]; bhx[ni][1] = Bh[cidx + 1];
                blx[ni][0] = Bl[cidx]; blx[ni][1] = Bl[cidx + 1];
            }
            #pragma unroll
            for (int mi = 0; mi < 4; mi++) {
                int r = (wm + mi * 16 + g) * PV_ST + fo;
                int r8 = r + 8 * PV_ST;
                uint32_t a0 = Ah[r], a1 = Ah[r8], a2 = Ah[r + 1], a3 = Ah[r8 + 1];
                uint32_t l0 = Al[r], l1 = Al[r8], l2 = Al[r + 1], l3 = Al[r8 + 1];
                #pragma unroll
                for (int ni = 0; ni < 2; ni++) {
                    mma_bf16s(dacc[mi][ni], a0, a1, a2, a3, bhx[ni][0], bhx[ni][1]);
                    mma_bf16s(dacc[mi][ni], a0, a1, a2, a3, blx[ni][0], blx[ni][1]);
                    mma_bf16s(dacc[mi][ni], l0, l1, l2, l3, bhx[ni][0], bhx[ni][1]);
                }
            }
        }

        if (have) sts_slab(bf ^ 1);
        __syncthreads();
    }

    // epilogue: pack (col, col+1) pairs = one kpair over d
    #pragma unroll
    for (int mi = 0; mi < 4; mi++) {
        int lr0 = s0 + wm + mi * 16 + g;
        int row0 = b * SS + lr0, row1 = row0 + 8;
        #pragma unroll
        for (int ni = 0; ni < 2; ni++) {
            int col = h * HD + wn + ni * 8 + 2 * tg;
            int kp = col >> 1;
            int idx = (kp & ~15) | pos16(kp & 15);
            float4 d = dacc[mi][ni];
            uint32_t ph, pl;
            bsplit2(d.x, d.y, ph, pl);
            g_oh[row0][idx] = ph; g_ol[row0][idx] = pl;
            bsplit2(d.z, d.w, ph, pl);
            g_oh[row1][idx] = ph; g_ol[row1][idx] = pl;
        }
    }
}

// ---------------------------------------------------------------------------
// Kernel 8: output projection via bf16 mma (3 terms): out = O1 @ Wo^T + bo.
// A = packed o1 [8192][256], B = packed Wo [512][256]. K=512, 16 slabs.
// ---------------------------------------------------------------------------
__global__ __launch_bounds__(256) void proj_mma(const float* __restrict__ bo,
                                                float* __restrict__ out) {
    extern __shared__ uint32_t smu[];
    const int m0 = blockIdx.x * 128, n0 = blockIdx.y * 128;
    const int tid = threadIdx.x, wid = tid >> 5, lane = tid & 31;
    const int g = lane >> 2, tg = lane & 3;
    const int wm = (wid >> 2) * 64, wn = (wid & 3) * 32;

    float4 dacc[4][4];
    #pragma unroll
    for (int mi = 0; mi < 4; mi++)
        #pragma unroll
        for (int ni = 0; ni < 4; ni++) dacc[mi][ni] = make_float4(0.f, 0.f, 0.f, 0.f);

    const int a_row = tid >> 1, a_half = (tid & 1) * 8;

    uint4 rah0, rah1, ral0, ral1, rbh0, rbh1, rbl0, rbl1;

    auto ldg_slab = [&](int c) {
        const uint32_t* oh = &g_oh[m0 + a_row][c * 16 + a_half];
        const uint32_t* ol = &g_ol[m0 + a_row][c * 16 + a_half];
        rah0 = *(const uint4*)&oh[0]; rah1 = *(const uint4*)&oh[4];
        ral0 = *(const uint4*)&ol[0]; ral1 = *(const uint4*)&ol[4];
        const uint32_t* wh = &g_wh[3][0][n0 + a_row][c * 16 + a_half];
        const uint32_t* wl = &g_wl[3][0][n0 + a_row][c * 16 + a_half];
        rbh0 = *(const uint4*)&wh[0]; rbh1 = *(const uint4*)&wh[4];
        rbl0 = *(const uint4*)&wl[0]; rbl1 = *(const uint4*)&wl[4];
    };
    auto sts_slab = [&](int bf) {
        uint32_t* Ah = smu + bf * CV_BUF_U32 + CV_AH + a_row * CV_ST + a_half;
        uint32_t* Al = smu + bf * CV_BUF_U32 + CV_AL + a_row * CV_ST + a_half;
        uint32_t* Bh = smu + bf * CV_BUF_U32 + CV_BH + a_row * CV_ST + a_half;
        uint32_t* Bl = smu + bf * CV_BUF_U32 + CV_BL + a_row * CV_ST + a_half;
        Ah[0] = rah0.x; Ah[1] = rah0.y; Ah[2] = rah0.z; Ah[3] = rah0.w;
        Ah[4] = rah1.x; Ah[5] = rah1.y; Ah[6] = rah1.z; Ah[7] = rah1.w;
        Al[0] = ral0.x; Al[1] = ral0.y; Al[2] = ral0.z; Al[3] = ral0.w;
        Al[4] = ral1.x; Al[5] = ral1.y; Al[6] = ral1.z; Al[7] = ral1.w;
        Bh[0] = rbh0.x; Bh[1] = rbh0.y; Bh[2] = rbh0.z; Bh[3] = rbh0.w;
        Bh[4] = rbh1.x; Bh[5] = rbh1.y; Bh[6] = rbh1.z; Bh[7] = rbh1.w;
        Bl[0] = rbl0.x; Bl[1] = rbl0.y; Bl[2] = rbl0.z; Bl[3] = rbl0.w;
        Bl[4] = rbl1.x; Bl[5] = rbl1.y; Bl[6] = rbl1.z; Bl[7] = rbl1.w;
    };

    ldg_slab(0);
    sts_slab(0);
    __syncthreads();

    for (int c = 0; c < 16; c++) {
        const int bf = c & 1;
        const bool have = (c + 1) < 16;
        if (have) ldg_slab(c + 1);

        const uint32_t* Ah = smu + bf * CV_BUF_U32 + CV_AH;
        const uint32_t* Al = smu + bf * CV_BUF_U32 + CV_AL;
        const uint32_t* Bh = smu + bf * CV_BUF_U32 + CV_BH;
        const uint32_t* Bl = smu + bf * CV_BUF_U32 + CV_BL;

        #pragma unroll
        for (int s = 0; s < 2; s++) {
            const int fo = tg * 4 + 2 * s;
            uint32_t ahx[4][4], alx[4][4], bhx[4][2], blx[4][2];
            #pragma unroll
            for (int mi = 0; mi < 4; mi++) {
                int r = (wm + mi * 16 + g) * CV_ST + fo;
                int r8 = r + 8 * CV_ST;
                ahx[mi][0] = Ah[r];     ahx[mi][1] = Ah[r8];
                ahx[mi][2] = Ah[r + 1]; ahx[mi][3] = Ah[r8 + 1];
                alx[mi][0] = Al[r];     alx[mi][1] = Al[r8];
                alx[mi][2] = Al[r + 1]; alx[mi][3] = Al[r8 + 1];
            }
            #pragma unroll
            for (int ni = 0; ni < 4; ni++) {
                int cidx = (wn + ni * 8 + g) * CV_ST + fo;
                bhx[ni][0] = Bh[cidx]; bhx[ni][1] = Bh[cidx + 1];
                blx[ni][0] = Bl[cidx]; blx[ni][1] = Bl[cidx + 1];
            }
            #pragma unroll
            for (int mi = 0; mi < 4; mi++)
                #pragma unroll
                for (int ni = 0; ni < 4; ni++) {
                    mma_bf16s(dacc[mi][ni], ahx[mi][0], ahx[mi][1], ahx[mi][2],
                              ahx[mi][3], bhx[ni][0], bhx[ni][1]);
                    mma_bf16s(dacc[mi][ni], ahx[mi][0], ahx[mi][1], ahx[mi][2],
                              ahx[mi][3], blx[ni][0], blx[ni][1]);
                    mma_bf16s(dacc[mi][ni], alx[mi][0], alx[mi][1], alx[mi][2],
                              alx[mi][3], bhx[ni][0], bhx[ni][1]);
                }
        }

        if (have) sts_slab(bf ^ 1);
        __syncthreads();
    }

    #pragma unroll
    for (int mi = 0; mi < 4; mi++) {
        int lr0 = m0 + wm + mi * 16 + g;
        #pragma unroll
        for (int ni = 0; ni < 4; ni++) {
            int col = n0 + wn + ni * 8 + 2 * tg;
            float2 bb = *(const float2*)&bo[col];
            float4 d = dacc[mi][ni];
            *(float2*)&out[(size_t)lr0 * DD + col]       = make_float2(d.x + bb.x, d.y + bb.y);
            *(float2*)&out[(size_t)(lr0 + 8) * DD + col] = make_float2(d.z + bb.x, d.w + bb.y);
        }
    }
}

// ---------------------------------------------------------------------------
extern "C" void kernel_launch(void* const* d_in, const int* in_sizes, int n_in,
                              void* d_out, int out_size) {
    const float* query = (const float*)d_in[0];
    const float* key_t = (const float*)d_in[1];
    const float* value = (const float*)d_in[2];
    const float* Wq    = (const float*)d_in[3];
    const float* bq    = (const float*)d_in[4];
    const float* Wk    = (const float*)d_in[5];
    const float* bk    = (const float*)d_in[6];
    const float* Wv    = (const float*)d_in[7];
    const float* bv    = (const float*)d_in[8];
    const float* Wo    = (const float*)d_in[9];
    const float* bo    = (const float*)d_in[10];

    float* out = (float*)d_out;
    float* ave = out + (size_t)BB * SS * DD;

    cudaFuncSetAttribute(conv_mma, cudaFuncAttributeMaxDynamicSharedMemorySize, CV_SMEM);
    cudaFuncSetAttribute(scores_gemm, cudaFuncAttributeMaxDynamicSharedMemorySize, SG_SMEM);
    cudaFuncSetAttribute(softmax_ave, cudaFuncAttributeMaxDynamicSharedMemorySize, SMA_SMEM);
    cudaFuncSetAttribute(pv_mma, cudaFuncAttributeMaxDynamicSharedMemorySize, PV_SMEM);
    cudaFuncSetAttribute(proj_mma, cudaFuncAttributeMaxDynamicSharedMemorySize, CV_SMEM);

    xprep_kernel<<<dim3(SS / 128, BB, 3), 256>>>(query, key_t, value);
    wprep_kernel<<<dim3(DD / 64, 4), 256>>>(Wq, Wk, Wv, Wo);
    conv_mma<<<dim3(DD / 128, SS / 128, 3 * BB), 256, CV_SMEM>>>(bq, bk, bv);
    qkprep_kernel<<<dim3(SS / 32, DD / 32, 2 * BB), dim3(32, 8)>>>();
    scores_gemm<<<dim3(64, HH, BB), 256, SG_SMEM>>>();
    softmax_ave<<<dim3(SS / 8, BB), 256, SMA_SMEM>>>(ave);
    pv_mma<<<dim3(SS / 128, HH, BB), 256, PV_SMEM>>>();
    proj_mma<<<dim3((BB * SS) / 128, DD / 128), 256, CV_SMEM>>>(bo, out);
}

// round 13
// speedup vs baseline: 1.7193x; 1.0188x over previous
#include <cuda_runtime.h>
#include <cuda_bf16.h>
#include <cstdint>

// ---------------------------------------------------------------------------
// ConvMultiheadAttention: B=8, S=1024, D=512, H=8, hd=64, KERNEL=3
// out  = [8,1024,512]  ; ave = [8,1024,1024]
// ---------------------------------------------------------------------------

#define BB 8
#define SS 1024
#define DD 512
#define HH 8
#define HD 64

typedef unsigned long long ull;

// ----- bf16 split helpers ----------------------------------------------------
__device__ __forceinline__ void bsplit2(float u, float v, uint32_t& ph, uint32_t& pl) {
    __nv_bfloat16 hu = __float2bfloat16_rn(u);
    __nv_bfloat16 hv = __float2bfloat16_rn(v);
    __nv_bfloat16 lu = __float2bfloat16_rn(u - __bfloat162float(hu));
    __nv_bfloat16 lv = __float2bfloat16_rn(v - __bfloat162float(hv));
    ph = (uint32_t)__bfloat16_as_ushort(hu) | ((uint32_t)__bfloat16_as_ushort(hv) << 16);
    pl = (uint32_t)__bfloat16_as_ushort(lu) | ((uint32_t)__bfloat16_as_ushort(lv) << 16);
}
__device__ __forceinline__ void mma_bf16s(float4& d, uint32_t a0, uint32_t a1,
                                          uint32_t a2, uint32_t a3,
                                          uint32_t b0, uint32_t b1) {
    asm("mma.sync.aligned.m16n8k16.row.col.f32.bf16.bf16.f32 "
        "{%0,%1,%2,%3}, {%4,%5,%6,%7}, {%8,%9}, {%0,%1,%2,%3};"
        : "+f"(d.x), "+f"(d.y), "+f"(d.z), "+f"(d.w)
        : "r"(a0), "r"(a1), "r"(a2), "r"(a3), "r"(b0), "r"(b1));
}
// kpair position permutations (fragment (tg, k16-step s) reads pos fo, fo+1)
__device__ __forceinline__ int pos16(int kp) { return (kp & 3) * 4 + (kp >> 2); }
__device__ __forceinline__ int pos32(int kp) {
    return (kp & 3) * 8 + 2 * (kp >> 3) + ((kp >> 2) & 1);
}

// ----- scratch (static device globals) --------------------------------------
__device__ float g_qkv[2][BB][DD][SS];       // conv outputs Q,K [B,D,S]
__device__ uint32_t g_xh[3][BB][SS][256];    // inputs split hi, ci-kpair packed
__device__ uint32_t g_xl[3][BB][SS][256];    // inputs split lo
__device__ uint32_t g_wh[4][3][DD][256];     // weights split hi, per tap (3=Wo)
__device__ uint32_t g_wl[4][3][DD][256];     // weights split lo
__device__ uint32_t g_sqh[BB * HH][SS][32];  // Q/64 split hi (pos32 packed)
__device__ uint32_t g_sql[BB * HH][SS][32];
__device__ uint32_t g_skh[BB * HH][SS][32];  // K split hi
__device__ uint32_t g_skl[BB * HH][SS][32];
__device__ float g_p[(size_t)BB * HH * SS * SS]; // raw scores
__device__ uint32_t g_ph[BB * HH][SS][512];  // probs split hi (pos16 packed)
__device__ uint32_t g_pl[BB * HH][SS][512];  // probs split lo
__device__ uint32_t g_vh[BB * HH][HD][512];  // V split hi (pos16 packed)
__device__ uint32_t g_vl[BB * HH][HD][512];  // V split lo
__device__ uint32_t g_oh[BB * SS][256];      // o1 split hi (pos16 packed)
__device__ uint32_t g_ol[BB * SS][256];      // o1 split lo

// ---------------------------------------------------------------------------
// Kernel 1: xprep — split inputs [B,S,D] into kpair-packed bf16 hi/lo
// ---------------------------------------------------------------------------
__global__ void xprep_kernel(const float* __restrict__ q,
                             const float* __restrict__ k,
                             const float* __restrict__ v) {
    const int tn = blockIdx.z, b = blockIdx.y, s0 = blockIdx.x * 128;
    const float* src = (tn == 0) ? q : (tn == 1) ? k : v;
    const int kp = threadIdx.x;             // 0..255
    const int idx = (kp & ~15) | pos16(kp & 15);
    for (int i = 0; i < 128; i++) {
        int s = s0 + i;
        float2 uv = *(const float2*)&src[((size_t)b * SS + s) * DD + 2 * kp];
        uint32_t ph, pl;
        bsplit2(uv.x, uv.y, ph, pl);
        g_xh[tn][b][s][idx] = ph;
        g_xl[tn][b][s][idx] = pl;
    }
}

// ---------------------------------------------------------------------------
// Kernel 2: wprep — split weights (Wq/Wk/Wv per tap, Wo) into packed hi/lo.
// ---------------------------------------------------------------------------
__global__ void wprep_kernel(const float* __restrict__ Wq,
                             const float* __restrict__ Wk,
                             const float* __restrict__ Wv,
                             const float* __restrict__ Wo) {
    const int tn = blockIdx.y;
    const float* W = (tn == 0) ? Wq : (tn == 1) ? Wk : (tn == 2) ? Wv : Wo;
    const int KER = (tn == 0 || tn == 1) ? 3 : 1;
    const int Kdim = DD * KER;
    const int co0 = blockIdx.x * 64;
    const int kp = threadIdx.x;              // 0..255 (ci pair)
    const int idx = (kp & ~15) | pos16(kp & 15);
    for (int tap = 0; tap < KER; tap++)
        for (int i = 0; i < 64; i++) {
            int co = co0 + i;
            float u = W[(size_t)co * Kdim + (2 * kp) * KER + tap];
            float vv = W[(size_t)co * Kdim + (2 * kp + 1) * KER + tap];
            uint32_t ph, pl;
            bsplit2(u, vv, ph, pl);
            g_wh[tn][tap][co][idx] = ph;
            g_wl[tn][tap][co][idx] = pl;
        }
}

// ---------------------------------------------------------------------------
// Kernel 3: conv1d as tap-decomposed bf16 MMA GEMM (split, 3 terms).
// 2 CTAs/SM; A-fragments loaded inside mi-loop to fit 128 regs.
// Q/K epilogue -> g_qkv; V epilogue -> packed g_vh/g_vl directly.
// ---------------------------------------------------------------------------
#define CV_ST 17
#define CV_AH 0
#define CV_AL 2176
#define CV_BH 4352
#define CV_BL 6528
#define CV_BUF_U32 8704
#define CV_SMEM (2 * CV_BUF_U32 * (int)sizeof(uint32_t))

__global__ __launch_bounds__(256, 2)
void conv_mma(const float* __restrict__ bq, const float* __restrict__ bk,
              const float* __restrict__ bv) {
    extern __shared__ uint32_t smu[];
    __shared__ float s_bias[128];

    const int zz = blockIdx.z, tn = zz / BB, b = zz % BB;
    const float* bias = (tn == 0) ? bq : (tn == 1) ? bk : bv;
    const int KER = (tn == 2) ? 1 : 3;
    const int pad = KER >> 1;
    const int NIT = KER * 16;
    const int m0 = blockIdx.x * 128, n0 = blockIdx.y * 128;
    const int tid = threadIdx.x, wid = tid >> 5, lane = tid & 31;
    const int g = lane >> 2, tg = lane & 3;
    const int wm = (wid >> 2) * 64, wn = (wid & 3) * 32;

    if (tid < 128) s_bias[tid] = bias[m0 + tid];

    float4 dacc[4][4];
    #pragma unroll
    for (int mi = 0; mi < 4; mi++)
        #pragma unroll
        for (int ni = 0; ni < 4; ni++) dacc[mi][ni] = make_float4(0.f, 0.f, 0.f, 0.f);

    const int a_row = tid >> 1, a_half = (tid & 1) * 8;
    const int b_s = tid & 127, b_half = (tid >> 7) * 8;

    uint4 rah0, rah1, ral0, ral1, rbh0, rbh1, rbl0, rbl1;

    auto ldg_slab = [&](int it) {
        int tap = it >> 4, c = it & 15;
        const uint32_t* wh = &g_wh[tn][tap][m0 + a_row][c * 16 + a_half];
        const uint32_t* wl = &g_wl[tn][tap][m0 + a_row][c * 16 + a_half];
        rah0 = *(const uint4*)&wh[0]; rah1 = *(const uint4*)&wh[4];
        ral0 = *(const uint4*)&wl[0]; ral1 = *(const uint4*)&wl[4];
        int s_glob = n0 + b_s + tap - pad;
        if ((unsigned)s_glob < (unsigned)SS) {
            const uint32_t* xh = &g_xh[tn][b][s_glob][c * 16 + b_half];
            const uint32_t* xl = &g_xl[tn][b][s_glob][c * 16 + b_half];
            rbh0 = *(const uint4*)&xh[0]; rbh1 = *(const uint4*)&xh[4];
            rbl0 = *(const uint4*)&xl[0]; rbl1 = *(const uint4*)&xl[4];
        } else {
            rbh0 = make_uint4(0, 0, 0, 0); rbh1 = rbh0;
            rbl0 = rbh0; rbl1 = rbh0;
        }
    };
    auto sts_slab = [&](int bf) {
        uint32_t* Ah = smu + bf * CV_BUF_U32 + CV_AH + a_row * CV_ST + a_half;
        uint32_t* Al = smu + bf * CV_BUF_U32 + CV_AL + a_row * CV_ST + a_half;
        uint32_t* Bh = smu + bf * CV_BUF_U32 + CV_BH + b_s * CV_ST + b_half;
        uint32_t* Bl = smu + bf * CV_BUF_U32 + CV_BL + b_s * CV_ST + b_half;
        Ah[0] = rah0.x; Ah[1] = rah0.y; Ah[2] = rah0.z; Ah[3] = rah0.w;
        Ah[4] = rah1.x; Ah[5] = rah1.y; Ah[6] = rah1.z; Ah[7] = rah1.w;
        Al[0] = ral0.x; Al[1] = ral0.y; Al[2] = ral0.z; Al[3] = ral0.w;
        Al[4] = ral1.x; Al[5] = ral1.y; Al[6] = ral1.z; Al[7] = ral1.w;
        Bh[0] = rbh0.x; Bh[1] = rbh0.y; Bh[2] = rbh0.z; Bh[3] = rbh0.w;
        Bh[4] = rbh1.x; Bh[5] = rbh1.y; Bh[6] = rbh1.z; Bh[7] = rbh1.w;
        Bl[0] = rbl0.x; Bl[1] = rbl0.y; Bl[2] = rbl0.z; Bl[3] = rbl0.w;
        Bl[4] = rbl1.x; Bl[5] = rbl1.y; Bl[6] = rbl1.z; Bl[7] = rbl1.w;
    };

    ldg_slab(0);
    sts_slab(0);
    __syncthreads();

    for (int it = 0; it < NIT; it++) {
        const int bf = it & 1;
        const bool have = (it + 1) < NIT;
        if (have) ldg_slab(it + 1);

        const uint32_t* Ah = smu + bf * CV_BUF_U32 + CV_AH;
        const uint32_t* Al = smu + bf * CV_BUF_U32 + CV_AL;
        const uint32_t* Bh = smu + bf * CV_BUF_U32 + CV_BH;
        const uint32_t* Bl = smu + bf * CV_BUF_U32 + CV_BL;

        #pragma unroll
        for (int s = 0; s < 2; s++) {
            const int fo = tg * 4 + 2 * s;
            uint32_t bhx[4][2], blx[4][2];
            #pragma unroll
            for (int ni = 0; ni < 4; ni++) {
                int cidx = (wn + ni * 8 + g) * CV_ST + fo;
                bhx[ni][0] = Bh[cidx]; bhx[ni][1] = Bh[cidx + 1];
                blx[ni][0] = Bl[cidx]; blx[ni][1] = Bl[cidx + 1];
            }
            #pragma unroll
            for (int mi = 0; mi < 4; mi++) {
                int r = (wm + mi * 16 + g) * CV_ST + fo;
                int r8 = r + 8 * CV_ST;
                uint32_t a0 = Ah[r], a1 = Ah[r8], a2 = Ah[r + 1], a3 = Ah[r8 + 1];
                uint32_t l0 = Al[r], l1 = Al[r8], l2 = Al[r + 1], l3 = Al[r8 + 1];
                #pragma unroll
                for (int ni = 0; ni < 4; ni++) {
                    mma_bf16s(dacc[mi][ni], a0, a1, a2, a3, bhx[ni][0], bhx[ni][1]);
                    mma_bf16s(dacc[mi][ni], a0, a1, a2, a3, blx[ni][0], blx[ni][1]);
                    mma_bf16s(dacc[mi][ni], l0, l1, l2, l3, bhx[ni][0], bhx[ni][1]);
                }
            }
        }

        if (have) sts_slab(bf ^ 1);
        __syncthreads();
    }

    if (tn != 2) {
        float* out = &g_qkv[tn][b][0][0];
        #pragma unroll
        for (int mi = 0; mi < 4; mi++) {
            int lr0 = wm + mi * 16 + g;
            float b0 = s_bias[lr0], b1 = s_bias[lr0 + 8];
            #pragma unroll
            for (int ni = 0; ni < 4; ni++) {
                int col = n0 + wn + ni * 8 + 2 * tg;
                float4 d = dacc[mi][ni];
                *(float2*)&out[(size_t)(m0 + lr0) * SS + col] =
                    make_float2(d.x + b0, d.y + b0);
                *(float2*)&out[(size_t)(m0 + lr0 + 8) * SS + col] =
                    make_float2(d.z + b1, d.w + b1);
            }
        }
    } else {
        // V: emit packed bf16 hi/lo directly (kpair over s = adjacent cols)
        #pragma unroll
        for (int mi = 0; mi < 4; mi++) {
            int lr0 = wm + mi * 16 + g;
            float b0 = s_bias[lr0], b1 = s_bias[lr0 + 8];
            int row0 = m0 + lr0, row1 = row0 + 8;
            int bh0 = b * HH + (row0 >> 6), bh1 = b * HH + (row1 >> 6);
            int dd0 = row0 & 63, dd1 = row1 & 63;
            #pragma unroll
            for (int ni = 0; ni < 4; ni++) {
                int col = n0 + wn + ni * 8 + 2 * tg;
                int kp = col >> 1;
                int idx = (kp & ~15) | pos16(kp & 15);
                float4 d = dacc[mi][ni];
                uint32_t ph, pl;
                bsplit2(d.x + b0, d.y + b0, ph, pl);
                g_vh[bh0][dd0][idx] = ph; g_vl[bh0][dd0][idx] = pl;
                bsplit2(d.z + b1, d.w + b1, ph, pl);
                g_vh[bh1][dd1][idx] = ph; g_vl[bh1][dd1][idx] = pl;
            }
        }
    }
}

// ---------------------------------------------------------------------------
// Kernel 4: qkprep — split Q (x 1/64) and K into kpair-packed bf16 hi/lo.
// ---------------------------------------------------------------------------
__global__ void qkprep_kernel() {
    __shared__ float tile[32][33];
    int zz = blockIdx.z;
    int tn = zz / BB, b = zz % BB;     // tn: 0=Q, 1=K
    const float* src = &g_qkv[tn][b][0][0];
    int s0 = blockIdx.x * 32, d0 = blockIdx.y * 32;
    int tx = threadIdx.x, ty = threadIdx.y;
    #pragma unroll
    for (int i = ty; i < 32; i += 8)
        tile[i][tx] = src[(size_t)(d0 + i) * SS + s0 + tx];
    __syncthreads();

    const float scale = (tn == 0) ? 0.015625f : 1.0f;
    const int h = d0 >> 6;
    const int kp_base = (d0 & 63) >> 1;
    const int bh = b * HH + h;
    uint32_t* dh = (tn == 0) ? &g_sqh[bh][0][0] : &g_skh[bh][0][0];
    uint32_t* dl = (tn == 0) ? &g_sql[bh][0][0] : &g_skl[bh][0][0];

    const int kpl = tx & 15;
    const int half = tx >> 4;
    const int pos = pos32(kp_base + kpl);
    #pragma unroll
    for (int i = ty; i < 32; i += 8) {
        float u = tile[2 * kpl][i] * scale;
        float v = tile[2 * kpl + 1][i] * scale;
        uint32_t ph, pl;
        bsplit2(u, v, ph, pl);
        if (half == 0) dh[(size_t)(s0 + i) * 32 + pos] = ph;
        else           dl[(size_t)(s0 + i) * 32 + pos] = pl;
    }
}

// ---------------------------------------------------------------------------
// Kernel 5: scores GEMM via bf16 mma (3 terms). Raw scores -> g_p.
// ---------------------------------------------------------------------------
#define SG_ST 33
#define SG_A_H 0
#define SG_A_L 4224
#define SG_B_H 8448
#define SG_B_L 12672
#define SG_SMEM (16896 * (int)sizeof(uint32_t))

__global__ __launch_bounds__(256, 2) void scores_gemm() {
    extern __shared__ uint32_t smu[];
    const int b = blockIdx.z, h = blockIdx.y;
    const int s0 = (blockIdx.x >> 3) * 128, t0 = (blockIdx.x & 7) * 128;
    const int bh = b * HH + h;
    const int tid = threadIdx.x, wid = tid >> 5, lane = tid & 31;
    const int g = lane >> 2, tg = lane & 3;
    const int wm = (wid >> 2) * 64, wn = (wid & 3) * 32;

    {
        const int row = tid >> 1, c0 = (tid & 1) * 16;
        const uint32_t* sa_h = &g_sqh[bh][s0 + row][c0];
        const uint32_t* sa_l = &g_sql[bh][s0 + row][c0];
        const uint32_t* sb_h = &g_skh[bh][t0 + row][c0];
        const uint32_t* sb_l = &g_skl[bh][t0 + row][c0];
        uint32_t* Ah = smu + SG_A_H + row * SG_ST + c0;
        uint32_t* Al = smu + SG_A_L + row * SG_ST + c0;
        uint32_t* Bh = smu + SG_B_H + row * SG_ST + c0;
        uint32_t* Bl = smu + SG_B_L + row * SG_ST + c0;
        #pragma unroll
        for (int i = 0; i < 4; i++) {
            uint4 va = *(const uint4*)&sa_h[4 * i];
            uint4 vb = *(const uint4*)&sa_l[4 * i];
            uint4 vc = *(const uint4*)&sb_h[4 * i];
            uint4 vd = *(const uint4*)&sb_l[4 * i];
            Ah[4 * i] = va.x; Ah[4 * i + 1] = va.y; Ah[4 * i + 2] = va.z; Ah[4 * i + 3] = va.w;
            Al[4 * i] = vb.x; Al[4 * i + 1] = vb.y; Al[4 * i + 2] = vb.z; Al[4 * i + 3] = vb.w;
            Bh[4 * i] = vc.x; Bh[4 * i + 1] = vc.y; Bh[4 * i + 2] = vc.z; Bh[4 * i + 3] = vc.w;
            Bl[4 * i] = vd.x; Bl[4 * i + 1] = vd.y; Bl[4 * i + 2] = vd.z; Bl[4 * i + 3] = vd.w;
        }
    }
    __syncthreads();

    const uint32_t* Ah = smu + SG_A_H;
    const uint32_t* Al = smu + SG_A_L;
    const uint32_t* Bh = smu + SG_B_H;
    const uint32_t* Bl = smu + SG_B_L;

    float4 dacc[4][4];
    #pragma unroll
    for (int mi = 0; mi < 4; mi++)
        #pragma unroll
        for (int ni = 0; ni < 4; ni++) dacc[mi][ni] = make_float4(0.f, 0.f, 0.f, 0.f);

    #pragma unroll
    for (int s = 0; s < 4; s++) {
        const int fo = tg * 8 + 2 * s;
        uint32_t bhx[4][2], blx[4][2];
        #pragma unroll
        for (int ni = 0; ni < 4; ni++) {
            int c = (wn + ni * 8 + g) * SG_ST + fo;
            bhx[ni][0] = Bh[c]; bhx[ni][1] = Bh[c + 1];
            blx[ni][0] = Bl[c]; blx[ni][1] = Bl[c + 1];
        }
        #pragma unroll
        for (int mi = 0; mi < 4; mi++) {
            int r = (wm + mi * 16 + g) * SG_ST + fo;
            int r8 = r + 8 * SG_ST;
            uint32_t a0 = Ah[r], a1 = Ah[r8], a2 = Ah[r + 1], a3 = Ah[r8 + 1];
            uint32_t l0 = Al[r], l1 = Al[r8], l2 = Al[r + 1], l3 = Al[r8 + 1];
            #pragma unroll
            for (int ni = 0; ni < 4; ni++) {
                mma_bf16s(dacc[mi][ni], a0, a1, a2, a3, bhx[ni][0], bhx[ni][1]);
                mma_bf16s(dacc[mi][ni], a0, a1, a2, a3, blx[ni][0], blx[ni][1]);
                mma_bf16s(dacc[mi][ni], l0, l1, l2, l3, bhx[ni][0], bhx[ni][1]);
            }
        }
    }

    float* Pg = &g_p[((size_t)bh << 20)];
    #pragma unroll
    for (int mi = 0; mi < 4; mi++) {
        int lr0 = s0 + wm + mi * 16 + g;
        #pragma unroll
        for (int ni = 0; ni < 4; ni++) {
            int col = t0 + wn + ni * 8 + 2 * tg;
            float4 d = dacc[mi][ni];
            *(float2*)&Pg[(size_t)lr0 * SS + col]       = make_float2(d.x, d.y);
            *(float2*)&Pg[(size_t)(lr0 + 8) * SS + col] = make_float2(d.z, d.w);
        }
    }
}

// ---------------------------------------------------------------------------
// Kernel 6: softmax + fused ave + packed bf16 split P emission.
// ---------------------------------------------------------------------------
#define SMA_SMEM (16384 * (int)sizeof(float))

__global__ __launch_bounds__(256) void softmax_ave(float* __restrict__ ave) {
    extern __shared__ float smf[];
    float* buf = smf;            // 8*1024
    float* av  = smf + 8192;     // 8*1024

    const int b = blockIdx.y, s0 = blockIdx.x * 8;
    const int tid = threadIdx.x, w = tid >> 5, lane = tid & 31;

    #pragma unroll
    for (int i = 0; i < 8; i++)
        *(float4*)&av[(i * 256 + tid) * 4] = make_float4(0.f, 0.f, 0.f, 0.f);

    for (int h = 0; h < HH; h++) {
        const int bh = b * HH + h;
        const float* Pg = &g_p[(((size_t)bh) << 20) + (size_t)s0 * SS];
        __syncthreads();
        #pragma unroll
        for (int i = 0; i < 8; i++) {
            int off = (i * 256 + tid) * 4;
            *(float4*)&buf[off] = *(const float4*)&Pg[off];
        }
        __syncthreads();

        {
            float* row = &buf[w * 1024];
            float* arow = &av[w * 1024];
            float m = -1e30f;
            for (int j = lane; j < 1024; j += 32) m = fmaxf(m, row[j]);
            #pragma unroll
            for (int o = 16; o > 0; o >>= 1)
                m = fmaxf(m, __shfl_xor_sync(0xffffffffu, m, o));
            float s = 0.0f;
            for (int j = lane; j < 1024; j += 32) {
                float e = __expf(row[j] - m);
                row[j] = e;
                s += e;
            }
            #pragma unroll
            for (int o = 16; o > 0; o >>= 1) s += __shfl_xor_sync(0xffffffffu, s, o);
            float inv = 1.0f / s;
            for (int j = lane; j < 1024; j += 32) {
                float p = row[j] * inv;
                row[j] = p;
                arow[j] += 0.125f * p;
            }
        }
        __syncthreads();

        #pragma unroll
        for (int i = 0; i < 16; i++) {
            int tt = i * 256 + tid;          // 0..4095
            int r = tt >> 9, kk = tt & 511;
            float2 uv = *(float2*)&buf[r * 1024 + 2 * kk];
            uint32_t ph, pl;
            bsplit2(uv.x, uv.y, ph, pl);
            int idx = (kk & ~15) | pos16(kk & 15);
            g_ph[bh][s0 + r][idx] = ph;
            g_pl[bh][s0 + r][idx] = pl;
        }
    }

    __syncthreads();
    #pragma unroll
    for (int i = 0; i < 8; i++) {
        int off = (i * 256 + tid) * 4;
        int r = off >> 10, c = off & 1023;
        *(float4*)&ave[((size_t)b * SS + s0 + r) * SS + c] = *(float4*)&av[off];
    }
}

// ---------------------------------------------------------------------------
// Kernel 7: PV GEMM via bf16 mma (3 terms), pure-copy staging. Epilogue emits
// packed o1 (kpair over d = adjacent output cols).
// ---------------------------------------------------------------------------
#define PV_ST 17
#define PV_A_H 0
#define PV_A_L 2176
#define PV_B_H 4352
#define PV_B_L 5440
#define PV_BUF_U32 6528
#define PV_SMEM (2 * PV_BUF_U32 * (int)sizeof(uint32_t))

__global__ __launch_bounds__(256, 2) void pv_mma() {
    extern __shared__ uint32_t smu[];
    const int b = blockIdx.z, h = blockIdx.y, s0 = blockIdx.x * 128;
    const int bh = b * HH + h;
    const int tid = threadIdx.x, wid = tid >> 5, lane = tid & 31;
    const int g = lane >> 2, tg = lane & 3;
    const int wm = (wid >> 2) * 64, wn = (wid & 3) * 16;

    float4 dacc[4][2];
    #pragma unroll
    for (int mi = 0; mi < 4; mi++)
        #pragma unroll
        for (int ni = 0; ni < 2; ni++) dacc[mi][ni] = make_float4(0.f, 0.f, 0.f, 0.f);

    const int a_row = tid >> 1, a_c0 = (tid & 1) * 8;
    const int b_d = tid >> 2, b_c0 = (tid & 3) * 4;

    uint4 rah0, rah1, ral0, ral1, rbh, rbl;

    auto ldg_slab = [&](int c) {
        const uint32_t* ph = &g_ph[bh][s0 + a_row][c * 16 + a_c0];
        const uint32_t* pl = &g_pl[bh][s0 + a_row][c * 16 + a_c0];
        rah0 = *(const uint4*)&ph[0]; rah1 = *(const uint4*)&ph[4];
        ral0 = *(const uint4*)&pl[0]; ral1 = *(const uint4*)&pl[4];
        rbh = *(const uint4*)&g_vh[bh][b_d][c * 16 + b_c0];
        rbl = *(const uint4*)&g_vl[bh][b_d][c * 16 + b_c0];
    };
    auto sts_slab = [&](int bf) {
        uint32_t* Ah = smu + bf * PV_BUF_U32 + PV_A_H + a_row * PV_ST + a_c0;
        uint32_t* Al = smu + bf * PV_BUF_U32 + PV_A_L + a_row * PV_ST + a_c0;
        uint32_t* Bh = smu + bf * PV_BUF_U32 + PV_B_H + b_d * PV_ST + b_c0;
        uint32_t* Bl = smu + bf * PV_BUF_U32 + PV_B_L + b_d * PV_ST + b_c0;
        Ah[0] = rah0.x; Ah[1] = rah0.y; Ah[2] = rah0.z; Ah[3] = rah0.w;
        Ah[4] = rah1.x; Ah[5] = rah1.y; Ah[6] = rah1.z; Ah[7] = rah1.w;
        Al[0] = ral0.x; Al[1] = ral0.y; Al[2] = ral0.z; Al[3] = ral0.w;
        Al[4] = ral1.x; Al[5] = ral1.y; Al[6] = ral1.z; Al[7] = ral1.w;
        Bh[0] = rbh.x; Bh[1] = rbh.y; Bh[2] = rbh.z; Bh[3] = rbh.w;
        Bl[0] = rbl.x; Bl[1] = rbl.y; Bl[2] = rbl.z; Bl[3] = rbl.w;
    };

    ldg_slab(0);
    sts_slab(0);
    __syncthreads();

    for (int c = 0; c < 32; c++) {
        const int bf = c & 1;
        const bool have = (c + 1) < 32;
        if (have) ldg_slab(c + 1);

        const uint32_t* Ah = smu + bf * PV_BUF_U32 + PV_A_H;
        const uint32_t* Al = smu + bf * PV_BUF_U32 + PV_A_L;
        const uint32_t* Bh = smu + bf * PV_BUF_U32 + PV_B_H;
        const uint32_t* Bl = smu + bf * PV_BUF_U32 + PV_B_L;

        #pragma unroll
        for (int s = 0; s < 2; s++) {
            const int fo = tg * 4 + 2 * s;
            uint32_t bhx[2][2], blx[2][2];
            #pragma unroll
            for (int ni = 0; ni < 2; ni++) {
                int cidx = (wn + ni * 8 + g) * PV_ST + fo;
                bhx[ni][0] = Bh[cidx]; bhx[ni][1] = Bh[cidx + 1];
                blx[ni][0] = Bl[cidx]; blx[ni][1] = Bl[cidx + 1];
            }
            #pragma unroll
            for (int mi = 0; mi < 4; mi++) {
                int r = (wm + mi * 16 + g) * PV_ST + fo;
                int r8 = r + 8 * PV_ST;
                uint32_t a0 = Ah[r], a1 = Ah[r8], a2 = Ah[r + 1], a3 = Ah[r8 + 1];
                uint32_t l0 = Al[r], l1 = Al[r8], l2 = Al[r + 1], l3 = Al[r8 + 1];
                #pragma unroll
                for (int ni = 0; ni < 2; ni++) {
                    mma_bf16s(dacc[mi][ni], a0, a1, a2, a3, bhx[ni][0], bhx[ni][1]);
                    mma_bf16s(dacc[mi][ni], a0, a1, a2, a3, blx[ni][0], blx[ni][1]);
                    mma_bf16s(dacc[mi][ni], l0, l1, l2, l3, bhx[ni][0], bhx[ni][1]);
                }
            }
        }

        if (have) sts_slab(bf ^ 1);
        __syncthreads();
    }

    // epilogue: pack (col, col+1) pairs = one kpair over d
    #pragma unroll
    for (int mi = 0; mi < 4; mi++) {
        int lr0 = s0 + wm + mi * 16 + g;
        int row0 = b * SS + lr0, row1 = row0 + 8;
        #pragma unroll
        for (int ni = 0; ni < 2; ni++) {
            int col = h * HD + wn + ni * 8 + 2 * tg;
            int kp = col >> 1;
            int idx = (kp & ~15) | pos16(kp & 15);
            float4 d = dacc[mi][ni];
            uint32_t ph, pl;
            bsplit2(d.x, d.y, ph, pl);
            g_oh[row0][idx] = ph; g_ol[row0][idx] = pl;
            bsplit2(d.z, d.w, ph, pl);
            g_oh[row1][idx] = ph; g_ol[row1][idx] = pl;
        }
    }
}

// ---------------------------------------------------------------------------
// Kernel 8: output projection via bf16 mma (3 terms): out = O1 @ Wo^T + bo.
// 2 CTAs/SM; A-fragments loaded inside mi-loop.
// ---------------------------------------------------------------------------
__global__ __launch_bounds__(256, 2) void proj_mma(const float* __restrict__ bo,
                                                   float* __restrict__ out) {
    extern __shared__ uint32_t smu[];
    const int m0 = blockIdx.x * 128, n0 = blockIdx.y * 128;
    const int tid = threadIdx.x, wid = tid >> 5, lane = tid & 31;
    const int g = lane >> 2, tg = lane & 3;
    const int wm = (wid >> 2) * 64, wn = (wid & 3) * 32;

    float4 dacc[4][4];
    #pragma unroll
    for (int mi = 0; mi < 4; mi++)
        #pragma unroll
        for (int ni = 0; ni < 4; ni++) dacc[mi][ni] = make_float4(0.f, 0.f, 0.f, 0.f);

    const int a_row = tid >> 1, a_half = (tid & 1) * 8;

    uint4 rah0, rah1, ral0, ral1, rbh0, rbh1, rbl0, rbl1;

    auto ldg_slab = [&](int c) {
        const uint32_t* oh = &g_oh[m0 + a_row][c * 16 + a_half];
        const uint32_t* ol = &g_ol[m0 + a_row][c * 16 + a_half];
        rah0 = *(const uint4*)&oh[0]; rah1 = *(const uint4*)&oh[4];
        ral0 = *(const uint4*)&ol[0]; ral1 = *(const uint4*)&ol[4];
        const uint32_t* wh = &g_wh[3][0][n0 + a_row][c * 16 + a_half];
        const uint32_t* wl = &g_wl[3][0][n0 + a_row][c * 16 + a_half];
        rbh0 = *(const uint4*)&wh[0]; rbh1 = *(const uint4*)&wh[4];
        rbl0 = *(const uint4*)&wl[0]; rbl1 = *(const uint4*)&wl[4];
    };
    auto sts_slab = [&](int bf) {
        uint32_t* Ah = smu + bf * CV_BUF_U32 + CV_AH + a_row * CV_ST + a_half;
        uint32_t* Al = smu + bf * CV_BUF_U32 + CV_AL + a_row * CV_ST + a_half;
        uint32_t* Bh = smu + bf * CV_BUF_U32 + CV_BH + a_row * CV_ST + a_half;
        uint32_t* Bl = smu + bf * CV_BUF_U32 + CV_BL + a_row * CV_ST + a_half;
        Ah[0] = rah0.x; Ah[1] = rah0.y; Ah[2] = rah0.z; Ah[3] = rah0.w;
        Ah[4] = rah1.x; Ah[5] = rah1.y; Ah[6] = rah1.z; Ah[7] = rah1.w;
        Al[0] = ral0.x; Al[1] = ral0.y; Al[2] = ral0.z; Al[3] = ral0.w;
        Al[4] = ral1.x; Al[5] = ral1.y; Al[6] = ral1.z; Al[7] = ral1.w;
        Bh[0] = rbh0.x; Bh[1] = rbh0.y; Bh[2] = rbh0.z; Bh[3] = rbh0.w;
        Bh[4] = rbh1.x; Bh[5] = rbh1.y; Bh[6] = rbh1.z; Bh[7] = rbh1.w;
        Bl[0] = rbl0.x; Bl[1] = rbl0.y; Bl[2] = rbl0.z; Bl[3] = rbl0.w;
        Bl[4] = rbl1.x; Bl[5] = rbl1.y; Bl[6] = rbl1.z; Bl[7] = rbl1.w;
    };

    ldg_slab(0);
    sts_slab(0);
    __syncthreads();

    for (int c = 0; c < 16; c++) {
        const int bf = c & 1;
        const bool have = (c + 1) < 16;
        if (have) ldg_slab(c + 1);

        const uint32_t* Ah = smu + bf * CV_BUF_U32 + CV_AH;
        const uint32_t* Al = smu + bf * CV_BUF_U32 + CV_AL;
        const uint32_t* Bh = smu + bf * CV_BUF_U32 + CV_BH;
        const uint32_t* Bl = smu + bf * CV_BUF_U32 + CV_BL;

        #pragma unroll
        for (int s = 0; s < 2; s++) {
            const int fo = tg * 4 + 2 * s;
            uint32_t bhx[4][2], blx[4][2];
            #pragma unroll
            for (int ni = 0; ni < 4; ni++) {
                int cidx = (wn + ni * 8 + g) * CV_ST + fo;
                bhx[ni][0] = Bh[cidx]; bhx[ni][1] = Bh[cidx + 1];
                blx[ni][0] = Bl[cidx]; blx[ni][1] = Bl[cidx + 1];
            }
            #pragma unroll
            for (int mi = 0; mi < 4; mi++) {
                int r = (wm + mi * 16 + g) * CV_ST + fo;
                int r8 = r + 8 * CV_ST;
                uint32_t a0 = Ah[r], a1 = Ah[r8], a2 = Ah[r + 1], a3 = Ah[r8 + 1];
                uint32_t l0 = Al[r], l1 = Al[r8], l2 = Al[r + 1], l3 = Al[r8 + 1];
                #pragma unroll
                for (int ni = 0; ni < 4; ni++) {
                    mma_bf16s(dacc[mi][ni], a0, a1, a2, a3, bhx[ni][0], bhx[ni][1]);
                    mma_bf16s(dacc[mi][ni], a0, a1, a2, a3, blx[ni][0], blx[ni][1]);
                    mma_bf16s(dacc[mi][ni], l0, l1, l2, l3, bhx[ni][0], bhx[ni][1]);
                }
            }
        }

        if (have) sts_slab(bf ^ 1);
        __syncthreads();
    }

    #pragma unroll
    for (int mi = 0; mi < 4; mi++) {
        int lr0 = m0 + wm + mi * 16 + g;
        #pragma unroll
        for (int ni = 0; ni < 4; ni++) {
            int col = n0 + wn + ni * 8 + 2 * tg;
            float2 bb = *(const float2*)&bo[col];
            float4 d = dacc[mi][ni];
            *(float2*)&out[(size_t)lr0 * DD + col]       = make_float2(d.x + bb.x, d.y + bb.y);
            *(float2*)&out[(size_t)(lr0 + 8) * DD + col] = make_float2(d.z + bb.x, d.w + bb.y);
        }
    }
}

// ---------------------------------------------------------------------------
extern "C" void kernel_launch(void* const* d_in, const int* in_sizes, int n_in,
                              void* d_out, int out_size) {
    const float* query = (const float*)d_in[0];
    const float* key_t = (const float*)d_in[1];
    const float* value = (const float*)d_in[2];
    const float* Wq    = (const float*)d_in[3];
    const float* bq    = (const float*)d_in[4];
    const float* Wk    = (const float*)d_in[5];
    const float* bk    = (const float*)d_in[6];
    const float* Wv    = (const float*)d_in[7];
    const float* bv    = (const float*)d_in[8];
    const float* Wo    = (const float*)d_in[9];
    const float* bo    = (const float*)d_in[10];

    float* out = (float*)d_out;
    float* ave = out + (size_t)BB * SS * DD;

    cudaFuncSetAttribute(conv_mma, cudaFuncAttributeMaxDynamicSharedMemorySize, CV_SMEM);
    cudaFuncSetAttribute(scores_gemm, cudaFuncAttributeMaxDynamicSharedMemorySize, SG_SMEM);
    cudaFuncSetAttribute(softmax_ave, cudaFuncAttributeMaxDynamicSharedMemorySize, SMA_SMEM);
    cudaFuncSetAttribute(pv_mma, cudaFuncAttributeMaxDynamicSharedMemorySize, PV_SMEM);
    cudaFuncSetAttribute(proj_mma, cudaFuncAttributeMaxDynamicSharedMemorySize, CV_SMEM);

    xprep_kernel<<<dim3(SS / 128, BB, 3), 256>>>(query, key_t, value);
    wprep_kernel<<<dim3(DD / 64, 4), 256>>>(Wq, Wk, Wv, Wo);
    conv_mma<<<dim3(DD / 128, SS / 128, 3 * BB), 256, CV_SMEM>>>(bq, bk, bv);
    qkprep_kernel<<<dim3(SS / 32, DD / 32, 2 * BB), dim3(32, 8)>>>();
    scores_gemm<<<dim3(64, HH, BB), 256, SG_SMEM>>>();
    softmax_ave<<<dim3(SS / 8, BB), 256, SMA_SMEM>>>(ave);
    pv_mma<<<dim3(SS / 128, HH, BB), 256, PV_SMEM>>>();
    proj_mma<<<dim3((BB * SS) / 128, DD / 128), 256, CV_SMEM>>>(bo, out);
}

// round 14
// speedup vs baseline: 2.1443x; 1.2472x over previous
#include <cuda_runtime.h>
#include <cuda_bf16.h>
#include <cstdint>

// ---------------------------------------------------------------------------
// ConvMultiheadAttention: B=8, S=1024, D=512, H=8, hd=64, KERNEL=3
// out  = [8,1024,512]  ; ave = [8,1024,1024]
// ---------------------------------------------------------------------------

#define BB 8
#define SS 1024
#define DD 512
#define HH 8
#define HD 64

typedef unsigned long long ull;

// ----- bf16 split helpers ----------------------------------------------------
__device__ __forceinline__ void bsplit2(float u, float v, uint32_t& ph, uint32_t& pl) {
    __nv_bfloat16 hu = __float2bfloat16_rn(u);
    __nv_bfloat16 hv = __float2bfloat16_rn(v);
    __nv_bfloat16 lu = __float2bfloat16_rn(u - __bfloat162float(hu));
    __nv_bfloat16 lv = __float2bfloat16_rn(v - __bfloat162float(hv));
    ph = (uint32_t)__bfloat16_as_ushort(hu) | ((uint32_t)__bfloat16_as_ushort(hv) << 16);
    pl = (uint32_t)__bfloat16_as_ushort(lu) | ((uint32_t)__bfloat16_as_ushort(lv) << 16);
}
__device__ __forceinline__ void mma_bf16s(float4& d, uint32_t a0, uint32_t a1,
                                          uint32_t a2, uint32_t a3,
                                          uint32_t b0, uint32_t b1) {
    asm("mma.sync.aligned.m16n8k16.row.col.f32.bf16.bf16.f32 "
        "{%0,%1,%2,%3}, {%4,%5,%6,%7}, {%8,%9}, {%0,%1,%2,%3};"
        : "+f"(d.x), "+f"(d.y), "+f"(d.z), "+f"(d.w)
        : "r"(a0), "r"(a1), "r"(a2), "r"(a3), "r"(b0), "r"(b1));
}
__device__ __forceinline__ void ldsm4(uint32_t& r0, uint32_t& r1, uint32_t& r2,
                                      uint32_t& r3, uint32_t addr) {
    asm volatile("ldmatrix.sync.aligned.m8n8.x4.shared.b16 {%0,%1,%2,%3}, [%4];"
        : "=r"(r0), "=r"(r1), "=r"(r2), "=r"(r3) : "r"(addr));
}

// ----- scratch (static device globals) --------------------------------------
// All packed arrays use PLAIN kpair order (ldmatrix supplies the fragment
// permutation in hardware).
__device__ float g_qkv[2][BB][DD][SS];       // conv outputs Q,K [B,D,S]
__device__ uint32_t g_xh[3][BB][SS][256];    // inputs split hi
__device__ uint32_t g_xl[3][BB][SS][256];    // inputs split lo
__device__ uint32_t g_wh[4][3][DD][256];     // weights split hi, per tap (3=Wo)
__device__ uint32_t g_wl[4][3][DD][256];     // weights split lo
__device__ uint32_t g_sqh[BB * HH][SS][32];  // Q/64 split hi
__device__ uint32_t g_sql[BB * HH][SS][32];
__device__ uint32_t g_skh[BB * HH][SS][32];  // K split hi
__device__ uint32_t g_skl[BB * HH][SS][32];
__device__ float g_p[(size_t)BB * HH * SS * SS]; // raw scores
__device__ uint32_t g_ph[BB * HH][SS][512];  // probs split hi
__device__ uint32_t g_pl[BB * HH][SS][512];  // probs split lo
__device__ uint32_t g_vh[BB * HH][HD][512];  // V split hi
__device__ uint32_t g_vl[BB * HH][HD][512];  // V split lo
__device__ uint32_t g_oh[BB * SS][256];      // o1 split hi
__device__ uint32_t g_ol[BB * SS][256];      // o1 split lo

// ---------------------------------------------------------------------------
// Kernel 1: xprep — split inputs [B,S,D] into kpair-packed bf16 hi/lo (plain)
// ---------------------------------------------------------------------------
__global__ void xprep_kernel(const float* __restrict__ q,
                             const float* __restrict__ k,
                             const float* __restrict__ v) {
    const int tn = blockIdx.z, b = blockIdx.y, s0 = blockIdx.x * 128;
    const float* src = (tn == 0) ? q : (tn == 1) ? k : v;
    const int kp = threadIdx.x;             // 0..255
    for (int i = 0; i < 128; i++) {
        int s = s0 + i;
        float2 uv = *(const float2*)&src[((size_t)b * SS + s) * DD + 2 * kp];
        uint32_t ph, pl;
        bsplit2(uv.x, uv.y, ph, pl);
        g_xh[tn][b][s][kp] = ph;
        g_xl[tn][b][s][kp] = pl;
    }
}

// ---------------------------------------------------------------------------
// Kernel 2: wprep — split weights (Wq/Wk/Wv per tap, Wo) into plain hi/lo.
// ---------------------------------------------------------------------------
__global__ void wprep_kernel(const float* __restrict__ Wq,
                             const float* __restrict__ Wk,
                             const float* __restrict__ Wv,
                             const float* __restrict__ Wo) {
    const int tn = blockIdx.y;
    const float* W = (tn == 0) ? Wq : (tn == 1) ? Wk : (tn == 2) ? Wv : Wo;
    const int KER = (tn == 0 || tn == 1) ? 3 : 1;
    const int Kdim = DD * KER;
    const int co0 = blockIdx.x * 64;
    const int kp = threadIdx.x;              // 0..255 (ci pair)
    for (int tap = 0; tap < KER; tap++)
        for (int i = 0; i < 64; i++) {
            int co = co0 + i;
            float u = W[(size_t)co * Kdim + (2 * kp) * KER + tap];
            float vv = W[(size_t)co * Kdim + (2 * kp + 1) * KER + tap];
            uint32_t ph, pl;
            bsplit2(u, vv, ph, pl);
            g_wh[tn][tap][co][kp] = ph;
            g_wl[tn][tap][co][kp] = pl;
        }
}

// ---------------------------------------------------------------------------
// Kernel 3: conv1d as tap-decomposed bf16 MMA GEMM (split, 3 terms), LDSM
// fragment loads. Q/K epilogue -> g_qkv; V epilogue -> packed g_vh/g_vl.
// smem stride 20 u32 (80B, 16B-aligned rows, conflict-free LDSM phases).
// ---------------------------------------------------------------------------
#define CV_ST 20
#define CV_AH 0
#define CV_AL 2560
#define CV_BH 5120
#define CV_BL 7680
#define CV_BUF_U32 10240
#define CV_SMEM (2 * CV_BUF_U32 * (int)sizeof(uint32_t))

__global__ __launch_bounds__(256, 2)
void conv_mma(const float* __restrict__ bq, const float* __restrict__ bk,
              const float* __restrict__ bv) {
    extern __shared__ uint32_t smu[];
    __shared__ float s_bias[128];

    const int zz = blockIdx.z, tn = zz / BB, b = zz % BB;
    const float* bias = (tn == 0) ? bq : (tn == 1) ? bk : bv;
    const int KER = (tn == 2) ? 1 : 3;
    const int pad = KER >> 1;
    const int NIT = KER * 16;
    const int m0 = blockIdx.x * 128, n0 = blockIdx.y * 128;
    const int tid = threadIdx.x, wid = tid >> 5, lane = tid & 31;
    const int g = lane >> 2, tg = lane & 3;
    const int wm = (wid >> 2) * 64, wn = (wid & 3) * 32;
    const int lt = lane >> 3, ro = lane & 7;   // ldsm tile index, row offset

    if (tid < 128) s_bias[tid] = bias[m0 + tid];

    const uint32_t sbase = (uint32_t)__cvta_generic_to_shared(smu);

    float4 dacc[4][4];
    #pragma unroll
    for (int mi = 0; mi < 4; mi++)
        #pragma unroll
        for (int ni = 0; ni < 4; ni++) dacc[mi][ni] = make_float4(0.f, 0.f, 0.f, 0.f);

    const int a_row = tid >> 1, a_half = (tid & 1) * 8;
    const int b_s = tid & 127, b_half = (tid >> 7) * 8;

    uint4 rah0, rah1, ral0, ral1, rbh0, rbh1, rbl0, rbl1;

    auto ldg_slab = [&](int it) {
        int tap = it >> 4, c = it & 15;
        const uint32_t* wh = &g_wh[tn][tap][m0 + a_row][c * 16 + a_half];
        const uint32_t* wl = &g_wl[tn][tap][m0 + a_row][c * 16 + a_half];
        rah0 = *(const uint4*)&wh[0]; rah1 = *(const uint4*)&wh[4];
        ral0 = *(const uint4*)&wl[0]; ral1 = *(const uint4*)&wl[4];
        int s_glob = n0 + b_s + tap - pad;
        if ((unsigned)s_glob < (unsigned)SS) {
            const uint32_t* xh = &g_xh[tn][b][s_glob][c * 16 + b_half];
            const uint32_t* xl = &g_xl[tn][b][s_glob][c * 16 + b_half];
            rbh0 = *(const uint4*)&xh[0]; rbh1 = *(const uint4*)&xh[4];
            rbl0 = *(const uint4*)&xl[0]; rbl1 = *(const uint4*)&xl[4];
        } else {
            rbh0 = make_uint4(0, 0, 0, 0); rbh1 = rbh0;
            rbl0 = rbh0; rbl1 = rbh0;
        }
    };
    auto sts_slab = [&](int bf) {
        uint32_t* Ah = smu + bf * CV_BUF_U32 + CV_AH + a_row * CV_ST + a_half;
        uint32_t* Al = smu + bf * CV_BUF_U32 + CV_AL + a_row * CV_ST + a_half;
        uint32_t* Bh = smu + bf * CV_BUF_U32 + CV_BH + b_s * CV_ST + b_half;
        uint32_t* Bl = smu + bf * CV_BUF_U32 + CV_BL + b_s * CV_ST + b_half;
        *(uint4*)&Ah[0] = rah0; *(uint4*)&Ah[4] = rah1;
        *(uint4*)&Al[0] = ral0; *(uint4*)&Al[4] = ral1;
        *(uint4*)&Bh[0] = rbh0; *(uint4*)&Bh[4] = rbh1;
        *(uint4*)&Bl[0] = rbl0; *(uint4*)&Bl[4] = rbl1;
    };

    ldg_slab(0);
    sts_slab(0);
    __syncthreads();

    for (int it = 0; it < NIT; it++) {
        const int bf = it & 1;
        const bool have = (it + 1) < NIT;
        if (have) ldg_slab(it + 1);

        const uint32_t bufB = sbase + 4 * (bf * CV_BUF_U32);
        #pragma unroll
        for (int s = 0; s < 2; s++) {
            uint32_t bh[4][2], bl[4][2];
            #pragma unroll
            for (int p = 0; p < 2; p++) {
                uint32_t off = (wn + (2 * p + (lt >> 1)) * 8 + ro) * CV_ST
                             + s * 8 + (lt & 1) * 4;
                uint32_t r0, r1, r2, r3;
                ldsm4(r0, r1, r2, r3, bufB + 4 * (CV_BH + off));
                bh[2 * p][0] = r0; bh[2 * p][1] = r1;
                bh[2 * p + 1][0] = r2; bh[2 * p + 1][1] = r3;
                ldsm4(r0, r1, r2, r3, bufB + 4 * (CV_BL + off));
                bl[2 * p][0] = r0; bl[2 * p][1] = r1;
                bl[2 * p + 1][0] = r2; bl[2 * p + 1][1] = r3;
            }
            #pragma unroll
            for (int mi = 0; mi < 4; mi++) {
                uint32_t aoff = (wm + mi * 16 + (lt & 1) * 8 + ro) * CV_ST
                              + s * 8 + (lt >> 1) * 4;
                uint32_t a0, a1, a2, a3, l0, l1, l2, l3;
                ldsm4(a0, a1, a2, a3, bufB + 4 * (CV_AH + aoff));
                ldsm4(l0, l1, l2, l3, bufB + 4 * (CV_AL + aoff));
                #pragma unroll
                for (int ni = 0; ni < 4; ni++) {
                    mma_bf16s(dacc[mi][ni], a0, a1, a2, a3, bh[ni][0], bh[ni][1]);
                    mma_bf16s(dacc[mi][ni], a0, a1, a2, a3, bl[ni][0], bl[ni][1]);
                    mma_bf16s(dacc[mi][ni], l0, l1, l2, l3, bh[ni][0], bh[ni][1]);
                }
            }
        }

        if (have) sts_slab(bf ^ 1);
        __syncthreads();
    }

    if (tn != 2) {
        float* out = &g_qkv[tn][b][0][0];
        #pragma unroll
        for (int mi = 0; mi < 4; mi++) {
            int lr0 = wm + mi * 16 + g;
            float b0 = s_bias[lr0], b1 = s_bias[lr0 + 8];
            #pragma unroll
            for (int ni = 0; ni < 4; ni++) {
                int col = n0 + wn + ni * 8 + 2 * tg;
                float4 d = dacc[mi][ni];
                *(float2*)&out[(size_t)(m0 + lr0) * SS + col] =
                    make_float2(d.x + b0, d.y + b0);
                *(float2*)&out[(size_t)(m0 + lr0 + 8) * SS + col] =
                    make_float2(d.z + b1, d.w + b1);
            }
        }
    } else {
        // V: emit packed bf16 hi/lo directly (kpair over s = adjacent cols)
        #pragma unroll
        for (int mi = 0; mi < 4; mi++) {
            int lr0 = wm + mi * 16 + g;
            float b0 = s_bias[lr0], b1 = s_bias[lr0 + 8];
            int row0 = m0 + lr0, row1 = row0 + 8;
            int bh0 = b * HH + (row0 >> 6), bh1 = b * HH + (row1 >> 6);
            int dd0 = row0 & 63, dd1 = row1 & 63;
            #pragma unroll
            for (int ni = 0; ni < 4; ni++) {
                int kp = (n0 + wn + ni * 8 + 2 * tg) >> 1;
                float4 d = dacc[mi][ni];
                uint32_t ph, pl;
                bsplit2(d.x + b0, d.y + b0, ph, pl);
                g_vh[bh0][dd0][kp] = ph; g_vl[bh0][dd0][kp] = pl;
                bsplit2(d.z + b1, d.w + b1, ph, pl);
                g_vh[bh1][dd1][kp] = ph; g_vl[bh1][dd1][kp] = pl;
            }
        }
    }
}

// ---------------------------------------------------------------------------
// Kernel 4: qkprep — split Q (x 1/64) and K into plain kpair-packed hi/lo.
// ---------------------------------------------------------------------------
__global__ void qkprep_kernel() {
    __shared__ float tile[32][33];
    int zz = blockIdx.z;
    int tn = zz / BB, b = zz % BB;     // tn: 0=Q, 1=K
    const float* src = &g_qkv[tn][b][0][0];
    int s0 = blockIdx.x * 32, d0 = blockIdx.y * 32;
    int tx = threadIdx.x, ty = threadIdx.y;
    #pragma unroll
    for (int i = ty; i < 32; i += 8)
        tile[i][tx] = src[(size_t)(d0 + i) * SS + s0 + tx];
    __syncthreads();

    const float scale = (tn == 0) ? 0.015625f : 1.0f;
    const int h = d0 >> 6;
    const int kp_base = (d0 & 63) >> 1;
    const int bh = b * HH + h;
    uint32_t* dh = (tn == 0) ? &g_sqh[bh][0][0] : &g_skh[bh][0][0];
    uint32_t* dl = (tn == 0) ? &g_sql[bh][0][0] : &g_skl[bh][0][0];

    const int kpl = tx & 15;
    const int half = tx >> 4;
    const int pos = kp_base + kpl;
    #pragma unroll
    for (int i = ty; i < 32; i += 8) {
        float u = tile[2 * kpl][i] * scale;
        float v = tile[2 * kpl + 1][i] * scale;
        uint32_t ph, pl;
        bsplit2(u, v, ph, pl);
        if (half == 0) dh[(size_t)(s0 + i) * 32 + pos] = ph;
        else           dl[(size_t)(s0 + i) * 32 + pos] = pl;
    }
}

// ---------------------------------------------------------------------------
// Kernel 5: scores GEMM via bf16 mma (3 terms), LDSM fragment loads.
// smem stride 36 u32. Raw scores -> g_p.
// ---------------------------------------------------------------------------
#define SG_ST 36
#define SG_A_H 0
#define SG_A_L 4608
#define SG_B_H 9216
#define SG_B_L 13824
#define SG_SMEM (18432 * (int)sizeof(uint32_t))

__global__ __launch_bounds__(256, 2) void scores_gemm() {
    extern __shared__ uint32_t smu[];
    const int b = blockIdx.z, h = blockIdx.y;
    const int s0 = (blockIdx.x >> 3) * 128, t0 = (blockIdx.x & 7) * 128;
    const int bh = b * HH + h;
    const int tid = threadIdx.x, wid = tid >> 5, lane = tid & 31;
    const int g = lane >> 2, tg = lane & 3;
    const int wm = (wid >> 2) * 64, wn = (wid & 3) * 32;
    const int lt = lane >> 3, ro = lane & 7;

    const uint32_t sbase = (uint32_t)__cvta_generic_to_shared(smu);

    {
        const int row = tid >> 1, c0 = (tid & 1) * 16;
        const uint32_t* sa_h = &g_sqh[bh][s0 + row][c0];
        const uint32_t* sa_l = &g_sql[bh][s0 + row][c0];
        const uint32_t* sb_h = &g_skh[bh][t0 + row][c0];
        const uint32_t* sb_l = &g_skl[bh][t0 + row][c0];
        uint32_t* Ah = smu + SG_A_H + row * SG_ST + c0;
        uint32_t* Al = smu + SG_A_L + row * SG_ST + c0;
        uint32_t* Bh = smu + SG_B_H + row * SG_ST + c0;
        uint32_t* Bl = smu + SG_B_L + row * SG_ST + c0;
        #pragma unroll
        for (int i = 0; i < 4; i++) {
            *(uint4*)&Ah[4 * i] = *(const uint4*)&sa_h[4 * i];
            *(uint4*)&Al[4 * i] = *(const uint4*)&sa_l[4 * i];
            *(uint4*)&Bh[4 * i] = *(const uint4*)&sb_h[4 * i];
            *(uint4*)&Bl[4 * i] = *(const uint4*)&sb_l[4 * i];
        }
    }
    __syncthreads();

    float4 dacc[4][4];
    #pragma unroll
    for (int mi = 0; mi < 4; mi++)
        #pragma unroll
        for (int ni = 0; ni < 4; ni++) dacc[mi][ni] = make_float4(0.f, 0.f, 0.f, 0.f);

    #pragma unroll
    for (int s = 0; s < 4; s++) {
        uint32_t bh2[4][2], bl2[4][2];
        #pragma unroll
        for (int p = 0; p < 2; p++) {
            uint32_t off = (wn + (2 * p + (lt >> 1)) * 8 + ro) * SG_ST
                         + s * 8 + (lt & 1) * 4;
            uint32_t r0, r1, r2, r3;
            ldsm4(r0, r1, r2, r3, sbase + 4 * (SG_B_H + off));
            bh2[2 * p][0] = r0; bh2[2 * p][1] = r1;
            bh2[2 * p + 1][0] = r2; bh2[2 * p + 1][1] = r3;
            ldsm4(r0, r1, r2, r3, sbase + 4 * (SG_B_L + off));
            bl2[2 * p][0] = r0; bl2[2 * p][1] = r1;
            bl2[2 * p + 1][0] = r2; bl2[2 * p + 1][1] = r3;
        }
        #pragma unroll
        for (int mi = 0; mi < 4; mi++) {
            uint32_t aoff = (wm + mi * 16 + (lt & 1) * 8 + ro) * SG_ST
                          + s * 8 + (lt >> 1) * 4;
            uint32_t a0, a1, a2, a3, l0, l1, l2, l3;
            ldsm4(a0, a1, a2, a3, sbase + 4 * (SG_A_H + aoff));
            ldsm4(l0, l1, l2, l3, sbase + 4 * (SG_A_L + aoff));
            #pragma unroll
            for (int ni = 0; ni < 4; ni++) {
                mma_bf16s(dacc[mi][ni], a0, a1, a2, a3, bh2[ni][0], bh2[ni][1]);
                mma_bf16s(dacc[mi][ni], a0, a1, a2, a3, bl2[ni][0], bl2[ni][1]);
                mma_bf16s(dacc[mi][ni], l0, l1, l2, l3, bh2[ni][0], bh2[ni][1]);
            }
        }
    }

    float* Pg = &g_p[((size_t)bh << 20)];
    #pragma unroll
    for (int mi = 0; mi < 4; mi++) {
        int lr0 = s0 + wm + mi * 16 + g;
        #pragma unroll
        for (int ni = 0; ni < 4; ni++) {
            int col = t0 + wn + ni * 8 + 2 * tg;
            float4 d = dacc[mi][ni];
            *(float2*)&Pg[(size_t)lr0 * SS + col]       = make_float2(d.x, d.y);
            *(float2*)&Pg[(size_t)(lr0 + 8) * SS + col] = make_float2(d.z, d.w);
        }
    }
}

// ---------------------------------------------------------------------------
// Kernel 6: softmax + fused ave + plain packed bf16 split P emission.
// ---------------------------------------------------------------------------
#define SMA_SMEM (16384 * (int)sizeof(float))

__global__ __launch_bounds__(256) void softmax_ave(float* __restrict__ ave) {
    extern __shared__ float smf[];
    float* buf = smf;            // 8*1024
    float* av  = smf + 8192;     // 8*1024

    const int b = blockIdx.y, s0 = blockIdx.x * 8;
    const int tid = threadIdx.x, w = tid >> 5, lane = tid & 31;

    #pragma unroll
    for (int i = 0; i < 8; i++)
        *(float4*)&av[(i * 256 + tid) * 4] = make_float4(0.f, 0.f, 0.f, 0.f);

    for (int h = 0; h < HH; h++) {
        const int bh = b * HH + h;
        const float* Pg = &g_p[(((size_t)bh) << 20) + (size_t)s0 * SS];
        __syncthreads();
        #pragma unroll
        for (int i = 0; i < 8; i++) {
            int off = (i * 256 + tid) * 4;
            *(float4*)&buf[off] = *(const float4*)&Pg[off];
        }
        __syncthreads();

        {
            float* row = &buf[w * 1024];
            float* arow = &av[w * 1024];
            float m = -1e30f;
            for (int j = lane; j < 1024; j += 32) m = fmaxf(m, row[j]);
            #pragma unroll
            for (int o = 16; o > 0; o >>= 1)
                m = fmaxf(m, __shfl_xor_sync(0xffffffffu, m, o));
            float s = 0.0f;
            for (int j = lane; j < 1024; j += 32) {
                float e = __expf(row[j] - m);
                row[j] = e;
                s += e;
            }
            #pragma unroll
            for (int o = 16; o > 0; o >>= 1) s += __shfl_xor_sync(0xffffffffu, s, o);
            float inv = 1.0f / s;
            for (int j = lane; j < 1024; j += 32) {
                float p = row[j] * inv;
                row[j] = p;
                arow[j] += 0.125f * p;
            }
        }
        __syncthreads();

        #pragma unroll
        for (int i = 0; i < 16; i++) {
            int tt = i * 256 + tid;          // 0..4095
            int r = tt >> 9, kk = tt & 511;
            float2 uv = *(float2*)&buf[r * 1024 + 2 * kk];
            uint32_t ph, pl;
            bsplit2(uv.x, uv.y, ph, pl);
            g_ph[bh][s0 + r][kk] = ph;
            g_pl[bh][s0 + r][kk] = pl;
        }
    }

    __syncthreads();
    #pragma unroll
    for (int i = 0; i < 8; i++) {
        int off = (i * 256 + tid) * 4;
        int r = off >> 10, c = off & 1023;
        *(float4*)&ave[((size_t)b * SS + s0 + r) * SS + c] = *(float4*)&av[off];
    }
}

// ---------------------------------------------------------------------------
// Kernel 7: PV GEMM via bf16 mma (3 terms), LDSM fragment loads.
// smem stride 20 u32. Epilogue emits plain packed o1.
// ---------------------------------------------------------------------------
#define PV_ST 20
#define PV_A_H 0
#define PV_A_L 2560
#define PV_B_H 5120
#define PV_B_L 6400
#define PV_BUF_U32 7680
#define PV_SMEM (2 * PV_BUF_U32 * (int)sizeof(uint32_t))

__global__ __launch_bounds__(256, 2) void pv_mma() {
    extern __shared__ uint32_t smu[];
    const int b = blockIdx.z, h = blockIdx.y, s0 = blockIdx.x * 128;
    const int bh = b * HH + h;
    const int tid = threadIdx.x, wid = tid >> 5, lane = tid & 31;
    const int g = lane >> 2, tg = lane & 3;
    const int wm = (wid >> 2) * 64, wn = (wid & 3) * 16;
    const int lt = lane >> 3, ro = lane & 7;

    const uint32_t sbase = (uint32_t)__cvta_generic_to_shared(smu);

    float4 dacc[4][2];
    #pragma unroll
    for (int mi = 0; mi < 4; mi++)
        #pragma unroll
        for (int ni = 0; ni < 2; ni++) dacc[mi][ni] = make_float4(0.f, 0.f, 0.f, 0.f);

    const int a_row = tid >> 1, a_c0 = (tid & 1) * 8;
    const int b_d = tid >> 2, b_c0 = (tid & 3) * 4;

    uint4 rah0, rah1, ral0, ral1, rbh, rbl;

    auto ldg_slab = [&](int c) {
        const uint32_t* ph = &g_ph[bh][s0 + a_row][c * 16 + a_c0];
        const uint32_t* pl = &g_pl[bh][s0 + a_row][c * 16 + a_c0];
        rah0 = *(const uint4*)&ph[0]; rah1 = *(const uint4*)&ph[4];
        ral0 = *(const uint4*)&pl[0]; ral1 = *(const uint4*)&pl[4];
        rbh = *(const uint4*)&g_vh[bh][b_d][c * 16 + b_c0];
        rbl = *(const uint4*)&g_vl[bh][b_d][c * 16 + b_c0];
    };
    auto sts_slab = [&](int bf) {
        uint32_t* Ah = smu + bf * PV_BUF_U32 + PV_A_H + a_row * PV_ST + a_c0;
        uint32_t* Al = smu + bf * PV_BUF_U32 + PV_A_L + a_row * PV_ST + a_c0;
        uint32_t* Bh = smu + bf * PV_BUF_U32 + PV_B_H + b_d * PV_ST + b_c0;
        uint32_t* Bl = smu + bf * PV_BUF_U32 + PV_B_L + b_d * PV_ST + b_c0;
        *(uint4*)&Ah[0] = rah0; *(uint4*)&Ah[4] = rah1;
        *(uint4*)&Al[0] = ral0; *(uint4*)&Al[4] = ral1;
        *(uint4*)&Bh[0] = rbh;
        *(uint4*)&Bl[0] = rbl;
    };

    ldg_slab(0);
    sts_slab(0);
    __syncthreads();

    for (int c = 0; c < 32; c++) {
        const int bf = c & 1;
        const bool have = (c + 1) < 32;
        if (have) ldg_slab(c + 1);

        const uint32_t bufB = sbase + 4 * (bf * PV_BUF_U32);
        #pragma unroll
        for (int s = 0; s < 2; s++) {
            uint32_t bh2[2][2], bl2[2][2];
            {
                uint32_t off = (wn + (lt >> 1) * 8 + ro) * PV_ST
                             + s * 8 + (lt & 1) * 4;
                uint32_t r0, r1, r2, r3;
                ldsm4(r0, r1, r2, r3, bufB + 4 * (PV_B_H + off));
                bh2[0][0] = r0; bh2[0][1] = r1; bh2[1][0] = r2; bh2[1][1] = r3;
                ldsm4(r0, r1, r2, r3, bufB + 4 * (PV_B_L + off));
                bl2[0][0] = r0; bl2[0][1] = r1; bl2[1][0] = r2; bl2[1][1] = r3;
            }
            #pragma unroll
            for (int mi = 0; mi < 4; mi++) {
                uint32_t aoff = (wm + mi * 16 + (lt & 1) * 8 + ro) * PV_ST
                              + s * 8 + (lt >> 1) * 4;
                uint32_t a0, a1, a2, a3, l0, l1, l2, l3;
                ldsm4(a0, a1, a2, a3, bufB + 4 * (PV_A_H + aoff));
                ldsm4(l0, l1, l2, l3, bufB + 4 * (PV_A_L + aoff));
                #pragma unroll
                for (int ni = 0; ni < 2; ni++) {
                    mma_bf16s(dacc[mi][ni], a0, a1, a2, a3, bh2[ni][0], bh2[ni][1]);
                    mma_bf16s(dacc[mi][ni], a0, a1, a2, a3, bl2[ni][0], bl2[ni][1]);
                    mma_bf16s(dacc[mi][ni], l0, l1, l2, l3, bh2[ni][0], bh2[ni][1]);
                }
            }
        }

        if (have) sts_slab(bf ^ 1);
        __syncthreads();
    }

    // epilogue: pack (col, col+1) pairs = one kpair over d (plain order)
    #pragma unroll
    for (int mi = 0; mi < 4; mi++) {
        int lr0 = s0 + wm + mi * 16 + g;
        int row0 = b * SS + lr0, row1 = row0 + 8;
        #pragma unroll
        for (int ni = 0; ni < 2; ni++) {
            int kp = (h * HD + wn + ni * 8 + 2 * tg) >> 1;
            float4 d = dacc[mi][ni];
            uint32_t ph, pl;
            bsplit2(d.x, d.y, ph, pl);
            g_oh[row0][kp] = ph; g_ol[row0][kp] = pl;
            bsplit2(d.z, d.w, ph, pl);
            g_oh[row1][kp] = ph; g_ol[row1][kp] = pl;
        }
    }
}

// ---------------------------------------------------------------------------
// Kernel 8: output projection via bf16 mma (3 terms), LDSM fragment loads.
// ---------------------------------------------------------------------------
__global__ __launch_bounds__(256, 2) void proj_mma(const float* __restrict__ bo,
                                                   float* __restrict__ out) {
    extern __shared__ uint32_t smu[];
    const int m0 = blockIdx.x * 128, n0 = blockIdx.y * 128;
    const int tid = threadIdx.x, wid = tid >> 5, lane = tid & 31;
    const int g = lane >> 2, tg = lane & 3;
    const int wm = (wid >> 2) * 64, wn = (wid & 3) * 32;
    const int lt = lane >> 3, ro = lane & 7;

    const uint32_t sbase = (uint32_t)__cvta_generic_to_shared(smu);

    float4 dacc[4][4];
    #pragma unroll
    for (int mi = 0; mi < 4; mi++)
        #pragma unroll
        for (int ni = 0; ni < 4; ni++) dacc[mi][ni] = make_float4(0.f, 0.f, 0.f, 0.f);

    const int a_row = tid >> 1, a_half = (tid & 1) * 8;

    uint4 rah0, rah1, ral0, ral1, rbh0, rbh1, rbl0, rbl1;

    auto ldg_slab = [&](int c) {
        const uint32_t* oh = &g_oh[m0 + a_row][c * 16 + a_half];
        const uint32_t* ol = &g_ol[m0 + a_row][c * 16 + a_half];
        rah0 = *(const uint4*)&oh[0]; rah1 = *(const uint4*)&oh[4];
        ral0 = *(const uint4*)&ol[0]; ral1 = *(const uint4*)&ol[4];
        const uint32_t* wh = &g_wh[3][0][n0 + a_row][c * 16 + a_half];
        const uint32_t* wl = &g_wl[3][0][n0 + a_row][c * 16 + a_half];
        rbh0 = *(const uint4*)&wh[0]; rbh1 = *(const uint4*)&wh[4];
        rbl0 = *(const uint4*)&wl[0]; rbl1 = *(const uint4*)&wl[4];
    };
    auto sts_slab = [&](int bf) {
        uint32_t* Ah = smu + bf * CV_BUF_U32 + CV_AH + a_row * CV_ST + a_half;
        uint32_t* Al = smu + bf * CV_BUF_U32 + CV_AL + a_row * CV_ST + a_half;
        uint32_t* Bh = smu + bf * CV_BUF_U32 + CV_BH + a_row * CV_ST + a_half;
        uint32_t* Bl = smu + bf * CV_BUF_U32 + CV_BL + a_row * CV_ST + a_half;
        *(uint4*)&Ah[0] = rah0; *(uint4*)&Ah[4] = rah1;
        *(uint4*)&Al[0] = ral0; *(uint4*)&Al[4] = ral1;
        *(uint4*)&Bh[0] = rbh0; *(uint4*)&Bh[4] = rbh1;
        *(uint4*)&Bl[0] = rbl0; *(uint4*)&Bl[4] = rbl1;
    };

    ldg_slab(0);
    sts_slab(0);
    __syncthreads();

    for (int c = 0; c < 16; c++) {
        const int bf = c & 1;
        const bool have = (c + 1) < 16;
        if (have) ldg_slab(c + 1);

        const uint32_t bufB = sbase + 4 * (bf * CV_BUF_U32);
        #pragma unroll
        for (int s = 0; s < 2; s++) {
            uint32_t bh[4][2], bl[4][2];
            #pragma unroll
            for (int p = 0; p < 2; p++) {
                uint32_t off = (wn + (2 * p + (lt >> 1)) * 8 + ro) * CV_ST
                             + s * 8 + (lt & 1) * 4;
                uint32_t r0, r1, r2, r3;
                ldsm4(r0, r1, r2, r3, bufB + 4 * (CV_BH + off));
                bh[2 * p][0] = r0; bh[2 * p][1] = r1;
                bh[2 * p + 1][0] = r2; bh[2 * p + 1][1] = r3;
                ldsm4(r0, r1, r2, r3, bufB + 4 * (CV_BL + off));
                bl[2 * p][0] = r0; bl[2 * p][1] = r1;
                bl[2 * p + 1][0] = r2; bl[2 * p + 1][1] = r3;
            }
            #pragma unroll
            for (int mi = 0; mi < 4; mi++) {
                uint32_t aoff = (wm + mi * 16 + (lt & 1) * 8 + ro) * CV_ST
                              + s * 8 + (lt >> 1) * 4;
                uint32_t a0, a1, a2, a3, l0, l1, l2, l3;
                ldsm4(a0, a1, a2, a3, bufB + 4 * (CV_AH + aoff));
                ldsm4(l0, l1, l2, l3, bufB + 4 * (CV_AL + aoff));
                #pragma unroll
                for (int ni = 0; ni < 4; ni++) {
                    mma_bf16s(dacc[mi][ni], a0, a1, a2, a3, bh[ni][0], bh[ni][1]);
                    mma_bf16s(dacc[mi][ni], a0, a1, a2, a3, bl[ni][0], bl[ni][1]);
                    mma_bf16s(dacc[mi][ni], l0, l1, l2, l3, bh[ni][0], bh[ni][1]);
                }
            }
        }

        if (have) sts_slab(bf ^ 1);
        __syncthreads();
    }

    #pragma unroll
    for (int mi = 0; mi < 4; mi++) {
        int lr0 = m0 + wm + mi * 16 + g;
        #pragma unroll
        for (int ni = 0; ni < 4; ni++) {
            int col = n0 + wn + ni * 8 + 2 * tg;
            float2 bb = *(const float2*)&bo[col];
            float4 d = dacc[mi][ni];
            *(float2*)&out[(size_t)lr0 * DD + col]       = make_float2(d.x + bb.x, d.y + bb.y);
            *(float2*)&out[(size_t)(lr0 + 8) * DD + col] = make_float2(d.z + bb.x, d.w + bb.y);
        }
    }
}

// ---------------------------------------------------------------------------
extern "C" void kernel_launch(void* const* d_in, const int* in_sizes, int n_in,
                              void* d_out, int out_size) {
    const float* query = (const float*)d_in[0];
    const float* key_t = (const float*)d_in[1];
    const float* value = (const float*)d_in[2];
    const float* Wq    = (const float*)d_in[3];
    const float* bq    = (const float*)d_in[4];
    const float* Wk    = (const float*)d_in[5];
    const float* bk    = (const float*)d_in[6];
    const float* Wv    = (const float*)d_in[7];
    const float* bv    = (const float*)d_in[8];
    const float* Wo    = (const float*)d_in[9];
    const float* bo    = (const float*)d_in[10];

    float* out = (float*)d_out;
    float* ave = out + (size_t)BB * SS * DD;

    cudaFuncSetAttribute(conv_mma, cudaFuncAttributeMaxDynamicSharedMemorySize, CV_SMEM);
    cudaFuncSetAttribute(scores_gemm, cudaFuncAttributeMaxDynamicSharedMemorySize, SG_SMEM);
    cudaFuncSetAttribute(softmax_ave, cudaFuncAttributeMaxDynamicSharedMemorySize, SMA_SMEM);
    cudaFuncSetAttribute(pv_mma, cudaFuncAttributeMaxDynamicSharedMemorySize, PV_SMEM);
    cudaFuncSetAttribute(proj_mma, cudaFuncAttributeMaxDynamicSharedMemorySize, CV_SMEM);

    xprep_kernel<<<dim3(SS / 128, BB, 3), 256>>>(query, key_t, value);
    wprep_kernel<<<dim3(DD / 64, 4), 256>>>(Wq, Wk, Wv, Wo);
    conv_mma<<<dim3(DD / 128, SS / 128, 3 * BB), 256, CV_SMEM>>>(bq, bk, bv);
    qkprep_kernel<<<dim3(SS / 32, DD / 32, 2 * BB), dim3(32, 8)>>>();
    scores_gemm<<<dim3(64, HH, BB), 256, SG_SMEM>>>();
    softmax_ave<<<dim3(SS / 8, BB), 256, SMA_SMEM>>>(ave);
    pv_mma<<<dim3(SS / 128, HH, BB), 256, PV_SMEM>>>();
    proj_mma<<<dim3((BB * SS) / 128, DD / 128), 256, CV_SMEM>>>(bo, out);
}